// round 11
// baseline (speedup 1.0000x reference)
#include <cuda_runtime.h>
#include <cstdint>

#define D_MODEL 1024
#define N_HEADS 16
#define D_HEAD  64
#define D_FF    4096
#define BATCH   4
#define SEQ     1024
#define M_TOK   (BATCH*SEQ)   // 4096

// ---------------- scratch (allocation-free: device globals) ----------------
__device__ float g_h   [M_TOK*D_MODEL];
__device__ float g_q   [M_TOK*D_MODEL];
__device__ float g_k   [M_TOK*D_MODEL];
__device__ float g_v   [M_TOK*D_MODEL];
__device__ float g_vT  [M_TOK*D_MODEL];
__device__ float g_o1  [M_TOK*D_MODEL];
__device__ float g_h2  [M_TOK*D_MODEL];
__device__ float g_ff  [M_TOK*D_FF];
__device__ float g_wqkv[3*D_MODEL*D_MODEL];
__device__ float g_w1r [D_FF*D_MODEL];
__device__ float g_w2r [D_MODEL*D_FF];
__device__ float g_stm [64*8*1024];
__device__ float g_stl [64*8*1024];
__device__ float g_scl [64*8*1024];

// ---------------- helpers ----------------
__device__ __forceinline__ uint32_t f2tf(float f) {
    uint32_t u;
    asm("cvt.rna.tf32.f32 %0, %1;" : "=r"(u) : "f"(f));
    return u;
}
__device__ __forceinline__ float f2tf_f(float f) { return __uint_as_float(f2tf(f)); }

// permuted column position: within each 16-block, k -> 4*(k&3) + ((k>>2)&3)
__device__ __forceinline__ int permc(int c) {
    return (c & ~15) | (((c & 3) << 2) | ((c >> 2) & 3));
}

__device__ __forceinline__ uint32_t smem_u32(const void* p) {
    uint32_t a;
    asm("{ .reg .u64 t; cvta.to.shared.u64 t, %1; cvt.u32.u64 %0, t; }" : "=r"(a) : "l"(p));
    return a;
}

__device__ __forceinline__ void cp_async16(uint32_t saddr, const void* gptr) {
    asm volatile("cp.async.cg.shared.global [%0], [%1], 16;" :: "r"(saddr), "l"(gptr) : "memory");
}
__device__ __forceinline__ void cp_commit() {
    asm volatile("cp.async.commit_group;" ::: "memory");
}
__device__ __forceinline__ void cp_wait1() {
    asm volatile("cp.async.wait_group 1;" ::: "memory");
}
__device__ __forceinline__ void cp_wait2() {
    asm volatile("cp.async.wait_group 2;" ::: "memory");
}

__device__ __forceinline__ void mma_tf32(float* c, uint32_t a0, uint32_t a1, uint32_t a2, uint32_t a3,
                                         uint32_t b0, uint32_t b1) {
    asm volatile(
        "mma.sync.aligned.m16n8k8.row.col.f32.tf32.tf32.f32 "
        "{%0,%1,%2,%3}, {%4,%5,%6,%7}, {%8,%9}, {%0,%1,%2,%3};\n"
        : "+f"(c[0]), "+f"(c[1]), "+f"(c[2]), "+f"(c[3])
        : "r"(a0), "r"(a1), "r"(a2), "r"(a3), "r"(b0), "r"(b1));
}

// ---------------- round-to-tf32 copy, PERMUTED output ----------------
__global__ void round_copy(const float4* __restrict__ src, float* __restrict__ dst, int n4) {
    int i = blockIdx.x * blockDim.x + threadIdx.x;
    if (i < n4) {
        float4 v = src[i];
        float* p = dst + 16 * (i >> 2) + (i & 3);
        p[0]  = f2tf_f(v.x);
        p[4]  = f2tf_f(v.y);
        p[8]  = f2tf_f(v.z);
        p[12] = f2tf_f(v.w);
    }
}

// ---------------- LayerNorm; tf32-rounded + PERMUTED output ----------------
__global__ void ln_kernel(const float* __restrict__ x, const float* __restrict__ g,
                          const float* __restrict__ b, float* __restrict__ out) {
    int row = blockIdx.x;
    int t = threadIdx.x;  // 256 threads, 4 floats each
    const float4* xr = (const float4*)(x + (size_t)row * D_MODEL);
    float4 v = xr[t];
    __shared__ float red[8];

    float s = v.x + v.y + v.z + v.w;
    #pragma unroll
    for (int o = 16; o; o >>= 1) s += __shfl_xor_sync(0xffffffffu, s, o);
    if ((t & 31) == 0) red[t >> 5] = s;
    __syncthreads();
    float tot = red[0]+red[1]+red[2]+red[3]+red[4]+red[5]+red[6]+red[7];
    float mean = tot * (1.0f / D_MODEL);

    float dx = v.x - mean, dy = v.y - mean, dz = v.z - mean, dw = v.w - mean;
    float ss = dx*dx + dy*dy + dz*dz + dw*dw;
    #pragma unroll
    for (int o = 16; o; o >>= 1) ss += __shfl_xor_sync(0xffffffffu, ss, o);
    __syncthreads();
    if ((t & 31) == 0) red[t >> 5] = ss;
    __syncthreads();
    float vtot = red[0]+red[1]+red[2]+red[3]+red[4]+red[5]+red[6]+red[7];
    float inv = 1.0f / (sqrtf(vtot * (1.0f / (D_MODEL - 1))) + 1e-12f);

    float4 g4 = ((const float4*)g)[t];
    float4 b4 = ((const float4*)b)[t];
    float* p = out + (size_t)row * D_MODEL + 16 * (t >> 2) + (t & 3);
    p[0]  = f2tf_f(g4.x * dx * inv + b4.x);
    p[4]  = f2tf_f(g4.y * dy * inv + b4.y);
    p[8]  = f2tf_f(g4.z * dz * inv + b4.z);
    p[12] = f2tf_f(g4.w * dw * inv + b4.w);
}

// ---------------- V transpose: v (permuted) -> vT (permuted) ----------------
__global__ void transpose_v(const float* __restrict__ v, float* __restrict__ vT) {
    __shared__ float tile[32][33];
    int bh = blockIdx.z;             // b*H + h
    int b = bh / N_HEADS, h = bh % N_HEADS;
    int s0 = blockIdx.x * 32;
    int d0 = blockIdx.y * 32;
    int tx = threadIdx.x, ty = threadIdx.y;  // 32 x 8
    const float* src = v + ((size_t)b * SEQ) * D_MODEL + h * D_HEAD;
    int pc = permc(d0 + tx);
    #pragma unroll
    for (int i = 0; i < 32; i += 8)
        tile[ty + i][tx] = src[(size_t)(s0 + ty + i) * D_MODEL + pc];
    __syncthreads();
    float* dst = vT + ((size_t)bh * D_HEAD) * SEQ;
    int ps = permc(s0 + tx);
    #pragma unroll
    for (int i = 0; i < 32; i += 8)
        dst[(size_t)(d0 + ty + i) * SEQ + ps] = tile[tx][ty + i];
}

// ---------------- stat combine: (m_t, l_t) x8 -> per-tile scale exp(m_t-m)/l ------
__global__ void stat_combine(const float* __restrict__ stm, const float* __restrict__ stl,
                             float* __restrict__ scl) {
    int i = blockIdx.x * blockDim.x + threadIdx.x;   // z*1024 + row, 65536 total
    int z = i >> 10, row = i & 1023;
    const float* pm = stm + (size_t)z * 8 * 1024 + row;
    const float* pl = stl + (size_t)z * 8 * 1024 + row;
    float mv[8];
    float m = -1e30f;
    #pragma unroll
    for (int t = 0; t < 8; t++) { mv[t] = pm[t * 1024]; m = fmaxf(m, mv[t]); }
    float ex[8];
    float l = 0.f;
    #pragma unroll
    for (int t = 0; t < 8; t++) { ex[t] = __expf(mv[t] - m); l += pl[t * 1024] * ex[t]; }
    float inv = 1.0f / l;
    float* ps = scl + (size_t)z * 8 * 1024 + row;
    #pragma unroll
    for (int t = 0; t < 8; t++) ps[t * 1024] = ex[t] * inv;
}

// ---------------- BIG-TILE tf32 GEMM: 128x256 CTA, warp tile 64x64, cp.async x4 ----
// A[M,K], B[N,K] both PERMUTED pre-rounded tf32 gmem. C = A@B^T (+bias)(+res)(relu).
// 8 warps in 2x4 grid (wm = (warp&1)*64, wn = (warp>>1)*64), MT=4, NT=8.
// 4-stage pipeline in dynamic smem (4 x 24KB), wait_group 2.
// QKV select when Ck != null (boundaries at 1024/2048; BN=256 never straddles).
template<int ROUND_OUT, int PERM_OUT>
__global__ void __launch_bounds__(256, 1)
gemm_big(const float* __restrict__ A, const float* __restrict__ B,
         float* __restrict__ C, const float* __restrict__ bias, const float* __restrict__ res,
         float* __restrict__ Ck, float* __restrict__ Cv,
         const float* __restrict__ biask, const float* __restrict__ biasv,
         int M, int N, int K, int lda, int ldb, int ldc, int relu)
{
    extern __shared__ __align__(16) uint32_t sm[];   // 4 stages x 6144 words

    const int tid = threadIdx.x, lane = tid & 31, warp = tid >> 5;
    const int wm = (warp & 1) * 64, wn = (warp >> 1) * 64;
    const int m0 = blockIdx.y * 128, n0 = blockIdx.x * 256;

    const int ft = lane & 3, frl = lane >> 2;
    const int fu = ft ^ ((frl >> 1) & 3);
    const uint32_t ldAw = (uint32_t)((wm + frl) * 16 + 4 * fu);
    const uint32_t ldBw = (uint32_t)(2048 + (wn + frl) * 16 + 4 * fu);

    float acc[4][8][4];
    #pragma unroll
    for (int i = 0; i < 4; i++)
        #pragma unroll
        for (int j = 0; j < 8; j++)
            #pragma unroll
            for (int c = 0; c < 4; c++) acc[i][j][c] = 0.f;

    const uint32_t smem_base = smem_u32(sm);
    uint32_t sw6[6];
    const float* gp6[6];
    #pragma unroll
    for (int j = 0; j < 6; j++) {
        int id = tid + 256 * j;
        if (id < 512) {               // A: 128 rows x 4 units
            int r = id >> 2, u = id & 3;
            int up = u ^ ((r >> 1) & 3);
            sw6[j] = (uint32_t)((r * 16 + 4 * up) * 4);
            gp6[j] = A + (size_t)(m0 + r) * lda + 4 * u;
        } else {                      // B: 256 rows x 4 units
            int idb = id - 512;
            int r = idb >> 2, u = idb & 3;
            int up = u ^ ((r >> 1) & 3);
            sw6[j] = (uint32_t)((2048 + r * 16 + 4 * up) * 4);
            gp6[j] = B + (size_t)(n0 + r) * ldb + 4 * u;
        }
    }

    auto issue = [&](int tile, int stg) {
        const int k0 = tile * 16;
        const uint32_t sb = smem_base + (uint32_t)stg * 24576u;
        #pragma unroll
        for (int j = 0; j < 6; j++) cp_async16(sb + sw6[j], gp6[j] + k0);
        cp_commit();
    };
    auto compute_at = [&](const uint32_t* base) {
        uint4 af[4][2];
        #pragma unroll
        for (int mt = 0; mt < 4; mt++)
            #pragma unroll
            for (int h = 0; h < 2; h++)
                af[mt][h] = *(const uint4*)&base[ldAw + mt * 256 + h * 128];
        #pragma unroll
        for (int nt = 0; nt < 8; nt++) {
            uint4 bf = *(const uint4*)&base[ldBw + nt * 128];
            #pragma unroll
            for (int mt = 0; mt < 4; mt++) {
                mma_tf32(acc[mt][nt], af[mt][0].x, af[mt][1].x, af[mt][0].y, af[mt][1].y,
                         bf.x, bf.y);
                mma_tf32(acc[mt][nt], af[mt][0].z, af[mt][1].z, af[mt][0].w, af[mt][1].w,
                         bf.z, bf.w);
            }
        }
    };

    const int nk = K / 16;
    issue(0, 0); issue(1, 1); issue(2, 2);
    int st = 0;
    for (int t = 0; t < nk; ++t) {
        cp_wait2();
        __syncthreads();
        compute_at(sm + st * 6144);
        if (t + 3 < nk) issue(t + 3, (st + 3) & 3);
        else            cp_commit();
        st = (st + 1) & 3;
    }

    // ---- epilogue (QKV 3-way select; optional permuted C) ----
    float* Cp = C; const float* bp = bias; int noff = 0;
    if (Ck) {
        if (n0 >= 2048)      { Cp = Cv; bp = biasv; noff = 2048; }
        else if (n0 >= 1024) { Cp = Ck; bp = biask; noff = 1024; }
    }
    #pragma unroll
    for (int mt = 0; mt < 4; ++mt) {
        #pragma unroll
        for (int nt = 0; nt < 8; ++nt) {
            int rbase = m0 + wm + mt * 16 + (lane >> 2);
            int cbase = n0 + wn + nt * 8 + (lane & 3) * 2;
            #pragma unroll
            for (int h = 0; h < 2; ++h) {
                int rr = rbase + h * 8;
                int cl = cbase - noff;
                float v0 = acc[mt][nt][h * 2 + 0];
                float v1 = acc[mt][nt][h * 2 + 1];
                if (bp)  { float2 bb = *(const float2*)(bp + cl); v0 += bb.x; v1 += bb.y; }
                if (res) { float2 r2 = *(const float2*)(res + (size_t)rr * ldc + cl); v0 += r2.x; v1 += r2.y; }
                if (relu) { v0 = fmaxf(v0, 0.f); v1 = fmaxf(v1, 0.f); }
                if (ROUND_OUT) { v0 = f2tf_f(v0); v1 = f2tf_f(v1); }
                if (PERM_OUT) {
                    int p = permc(cl);
                    float* rp = Cp + (size_t)rr * ldc;
                    rp[p] = v0; rp[p + 4] = v1;
                } else {
                    *(float2*)(Cp + (size_t)rr * ldc + cl) = make_float2(v0, v1);
                }
            }
        }
    }
}

// ---------------- tf32 mma.sync GEMM (scores / ctx) — unchanged from R9 ------------
// MODE 0: cp.async 3-stage pipeline; A,B permuted tf32 gmem.
// MODE 2: attn-ctx; A = E standard; p = E*scl; writeback P; B permuted.
template<int MODE, int ROUND_OUT, int STATS, int NT, int PERM_OUT>
__global__ void __launch_bounds__(256, 2)
gemm_mma(const float* __restrict__ A, const float* __restrict__ B,
         float* __restrict__ C, const float* __restrict__ bias, const float* __restrict__ res,
         float* __restrict__ Ck, float* __restrict__ Cv,
         const float* __restrict__ biask, const float* __restrict__ biasv,
         const float* __restrict__ scl, float* __restrict__ stm, float* __restrict__ stl,
         int M, int N, int K, int lda, int ldb, int ldc,
         float scale, int relu, int zmod,
         long long aLo, long long aHi, long long bLo, long long bHi,
         long long cLo, long long cHi)
{
    constexpr int SMW = (MODE == 0) ? 12288 : 8192;
    __shared__ __align__(16) uint32_t sm[SMW];

    int z = blockIdx.z;
    int zlo = z % zmod, zhi = z / zmod;
    A += (size_t)zlo * aLo + (size_t)zhi * aHi;
    B += (size_t)zlo * bLo + (size_t)zhi * bHi;
    size_t coff = (size_t)zlo * cLo + (size_t)zhi * cHi;
    C += coff;
    if (res) res += coff;

    const int tid = threadIdx.x, lane = tid & 31, warp = tid >> 5;
    const int wm = (warp & 3) * 32, wn = (warp >> 2) * (NT * 8);
    const int m0 = blockIdx.y * 128, n0 = blockIdx.x * (16 * NT);

    const int ft = lane & 3, frl = lane >> 2;
    const int fu = ft ^ ((frl >> 1) & 3);
    const uint32_t ldAw = (uint32_t)((wm + frl) * 16 + 4 * fu);
    const uint32_t ldBw = (uint32_t)(2048 + (wn + frl) * 16 + 4 * fu);

    float acc[2][NT][4];
    #pragma unroll
    for (int i = 0; i < 2; i++)
        #pragma unroll
        for (int j = 0; j < NT; j++)
            #pragma unroll
            for (int c = 0; c < 4; c++) acc[i][j][c] = 0.f;

    const int nk = K / 16;

    auto compute_at = [&](const uint32_t* base) {
        uint4 af[2][2];
        #pragma unroll
        for (int mt = 0; mt < 2; mt++)
            #pragma unroll
            for (int h = 0; h < 2; h++)
                af[mt][h] = *(const uint4*)&base[ldAw + mt * 256 + h * 128];
        #pragma unroll
        for (int nt = 0; nt < NT; nt++) {
            uint4 bf = *(const uint4*)&base[ldBw + nt * 128];
            #pragma unroll
            for (int mt = 0; mt < 2; mt++) {
                mma_tf32(acc[mt][nt], af[mt][0].x, af[mt][1].x, af[mt][0].y, af[mt][1].y,
                         bf.x, bf.y);
                mma_tf32(acc[mt][nt], af[mt][0].z, af[mt][1].z, af[mt][0].w, af[mt][1].w,
                         bf.z, bf.w);
            }
        }
    };

    if (MODE == 0) {
        const uint32_t smem_base = smem_u32(sm);
        uint32_t saw[2], sbw[2];
        const float *ga[2], *gb[2];
        #pragma unroll
        for (int j = 0; j < 2; j++) {
            int id = tid + 256 * j;
            int r = id >> 2, u = id & 3;
            int up = u ^ ((r >> 1) & 3);
            saw[j] = (uint32_t)((r * 16 + 4 * up) * 4);
            sbw[j] = (uint32_t)((2048 + r * 16 + 4 * up) * 4);
            ga[j] = A + (size_t)(m0 + r) * lda + 4 * u;
            gb[j] = B + (size_t)(n0 + r) * ldb + 4 * u;
        }
        auto issue = [&](int tile, int stg) {
            const int k0 = tile * 16;
            const uint32_t sb = smem_base + (uint32_t)stg * 16384u;
            #pragma unroll
            for (int j = 0; j < 2; j++) cp_async16(sb + saw[j], ga[j] + k0);
            #pragma unroll
            for (int j = 0; j < 2; j++) cp_async16(sb + sbw[j], gb[j] + k0);
            cp_commit();
        };
        issue(0, 0);
        issue(1, 1);
        int st = 0;
        for (int t = 0; t < nk; ++t) {
            cp_wait1();
            __syncthreads();
            compute_at(sm + st * 4096);
            if (t + 2 < nk) {
                int st2 = st + 2; if (st2 >= 3) st2 -= 3;
                issue(t + 2, st2);
            } else {
                cp_commit();
            }
            if (++st == 3) st = 0;
        }
        __syncthreads();
    } else {
        const int lr = tid >> 2, c4 = tid & 3, sw = (lr >> 1) & 3;
        uint32_t stA[4];
        #pragma unroll
        for (int j = 0; j < 4; j++) stA[j] = lr * 16 + 4 * (j ^ sw) + c4;
        uint32_t stB = 2048 + lr * 16 + 4 * (c4 ^ sw);
        float* PW = (float*)A;
        float4 aR[2]; uint4 bRr;

        auto loadg = [&](int t) {
            int k0 = t * 16 + c4 * 4;
            const float* sp = scl + ((size_t)z * 8 + (t >> 3)) * 1024 + m0 + lr;
            float s0 = sp[0], s1 = sp[64];
            #pragma unroll
            for (int i = 0; i < 2; i++) {
                int gm = m0 + lr + i * 64;
                aR[i] = *(const float4*)(A + (size_t)gm * lda + k0);
                float s = i ? s1 : s0;
                aR[i].x *= s; aR[i].y *= s; aR[i].z *= s; aR[i].w *= s;
                *(float4*)(PW + (size_t)gm * lda + k0) = aR[i];
            }
            bRr = *(const uint4*)(B + (size_t)(n0 + lr) * ldb + k0);
        };
        auto stores = [&]() {
            #pragma unroll
            for (int i = 0; i < 2; i++) {
                float av[4] = {aR[i].x, aR[i].y, aR[i].z, aR[i].w};
                #pragma unroll
                for (int j = 0; j < 4; j++)
                    sm[stA[j] + i * 1024] = f2tf(av[j]);
            }
            *(uint4*)&sm[stB] = bRr;
            #pragma unroll
            for (int j = 0; j < 4; j++) stA[j] ^= 4096;
            stB ^= 4096;
        };
        loadg(0); stores(); __syncthreads();
        for (int t = 0; t < nk; ++t) {
            if (t + 1 < nk) loadg(t + 1);
            compute_at(sm + ((t & 1) ? 4096 : 0));
            if (t + 1 < nk) stores();
            __syncthreads();
        }
    }

    if (STATS) {
        float* smf = (float*)sm;
        const int g = warp >> 2;
        const int rl = lane >> 2;
        float lmax[2][2];
        #pragma unroll
        for (int mt = 0; mt < 2; mt++)
            #pragma unroll
            for (int h = 0; h < 2; h++) {
                float v = -1e30f;
                #pragma unroll
                for (int nt = 0; nt < NT; nt++) {
                    v = fmaxf(v, acc[mt][nt][2 * h]);
                    v = fmaxf(v, acc[mt][nt][2 * h + 1]);
                }
                lmax[mt][h] = v * scale;
            }
        #pragma unroll
        for (int o = 1; o < 4; o <<= 1)
            #pragma unroll
            for (int mt = 0; mt < 2; mt++)
                #pragma unroll
                for (int h = 0; h < 2; h++)
                    lmax[mt][h] = fmaxf(lmax[mt][h], __shfl_xor_sync(0xffffffffu, lmax[mt][h], o));
        __syncthreads();
        if ((lane & 3) == 0)
            #pragma unroll
            for (int mt = 0; mt < 2; mt++)
                #pragma unroll
                for (int h = 0; h < 2; h++)
                    smf[g * 128 + wm + mt * 16 + h * 8 + rl] = lmax[mt][h];
        __syncthreads();
        float rmax[2][2], lsum[2][2];
        #pragma unroll
        for (int mt = 0; mt < 2; mt++)
            #pragma unroll
            for (int h = 0; h < 2; h++) {
                int row = wm + mt * 16 + h * 8 + rl;
                rmax[mt][h] = fmaxf(smf[row], smf[128 + row]);
                lsum[mt][h] = 0.f;
            }
        #pragma unroll
        for (int mt = 0; mt < 2; ++mt) {
            #pragma unroll
            for (int nt = 0; nt < NT; ++nt) {
                int rbase = m0 + wm + mt * 16 + rl;
                int cbase = n0 + wn + nt * 8 + (lane & 3) * 2;
                #pragma unroll
                for (int h = 0; h < 2; ++h) {
                    float e0 = __expf(acc[mt][nt][2 * h]     * scale - rmax[mt][h]);
                    float e1 = __expf(acc[mt][nt][2 * h + 1] * scale - rmax[mt][h]);
                    *(float2*)(C + (size_t)(rbase + h * 8) * ldc + cbase) = make_float2(e0, e1);
                    lsum[mt][h] += e0 + e1;
                }
            }
        }
        #pragma unroll
        for (int o = 1; o < 4; o <<= 1)
            #pragma unroll
            for (int mt = 0; mt < 2; mt++)
                #pragma unroll
                for (int h = 0; h < 2; h++)
                    lsum[mt][h] += __shfl_xor_sync(0xffffffffu, lsum[mt][h], o);
        if ((lane & 3) == 0)
            #pragma unroll
            for (int mt = 0; mt < 2; mt++)
                #pragma unroll
                for (int h = 0; h < 2; h++)
                    smf[256 + g * 128 + wm + mt * 16 + h * 8 + rl] = lsum[mt][h];
        __syncthreads();
        if (g == 0 && (lane & 3) == 0) {
            #pragma unroll
            for (int mt = 0; mt < 2; mt++)
                #pragma unroll
                for (int h = 0; h < 2; h++) {
                    int row = wm + mt * 16 + h * 8 + rl;
                    size_t idx = ((size_t)z * 8 + blockIdx.x) * 1024 + m0 + row;
                    stm[idx] = rmax[mt][h];
                    stl[idx] = smf[256 + row] + smf[384 + row];
                }
        }
    } else {
        float* Cp = C; const float* bp = bias; int noff = 0;
        if (Ck) {
            if (n0 >= 2048)      { Cp = Cv; bp = biasv; noff = 2048; }
            else if (n0 >= 1024) { Cp = Ck; bp = biask; noff = 1024; }
        }
        #pragma unroll
        for (int mt = 0; mt < 2; ++mt) {
            #pragma unroll
            for (int nt = 0; nt < NT; ++nt) {
                int rbase = m0 + wm + mt * 16 + (lane >> 2);
                int cbase = n0 + wn + nt * 8 + (lane & 3) * 2;
                #pragma unroll
                for (int h = 0; h < 2; ++h) {
                    int rr = rbase + h * 8;
                    int cl = cbase - noff;
                    float v0 = acc[mt][nt][h * 2 + 0] * scale;
                    float v1 = acc[mt][nt][h * 2 + 1] * scale;
                    if (bp)  { float2 bb = *(const float2*)(bp + cl); v0 += bb.x; v1 += bb.y; }
                    if (res) { float2 r2 = *(const float2*)(res + (size_t)rr * ldc + cl); v0 += r2.x; v1 += r2.y; }
                    if (relu) { v0 = fmaxf(v0, 0.f); v1 = fmaxf(v1, 0.f); }
                    if (ROUND_OUT) { v0 = f2tf_f(v0); v1 = f2tf_f(v1); }
                    if (PERM_OUT) {
                        int p = permc(cl);
                        float* rp = Cp + (size_t)rr * ldc;
                        rp[p] = v0; rp[p + 4] = v1;
                    } else {
                        *(float2*)(Cp + (size_t)rr * ldc + cl) = make_float2(v0, v1);
                    }
                }
            }
        }
    }
}

// ---------------- launch ----------------
extern "C" void kernel_launch(void* const* d_in, const int* in_sizes, int n_in,
                              void* d_out, int out_size) {
    const float* x     = (const float*)d_in[0];
    const float* ln1_g = (const float*)d_in[1];
    const float* ln1_b = (const float*)d_in[2];
    const float* wq    = (const float*)d_in[3];
    const float* bq    = (const float*)d_in[4];
    const float* wk    = (const float*)d_in[5];
    const float* bk    = (const float*)d_in[6];
    const float* wv    = (const float*)d_in[7];
    const float* bv    = (const float*)d_in[8];
    const float* ln2_g = (const float*)d_in[9];
    const float* ln2_b = (const float*)d_in[10];
    const float* w1    = (const float*)d_in[11];
    const float* b1    = (const float*)d_in[12];
    const float* w2    = (const float*)d_in[13];
    const float* b2    = (const float*)d_in[14];

    float* out  = (float*)d_out;
    float* attn = out + (size_t)BATCH * SEQ * D_MODEL;

    float *h, *q, *k, *v, *vT, *o1, *h2, *ff, *wqkv, *w1r, *w2r, *stm, *stl, *scl;
    cudaGetSymbolAddress((void**)&h,    g_h);
    cudaGetSymbolAddress((void**)&q,    g_q);
    cudaGetSymbolAddress((void**)&k,    g_k);
    cudaGetSymbolAddress((void**)&v,    g_v);
    cudaGetSymbolAddress((void**)&vT,   g_vT);
    cudaGetSymbolAddress((void**)&o1,   g_o1);
    cudaGetSymbolAddress((void**)&h2,   g_h2);
    cudaGetSymbolAddress((void**)&ff,   g_ff);
    cudaGetSymbolAddress((void**)&wqkv, g_wqkv);
    cudaGetSymbolAddress((void**)&w1r,  g_w1r);
    cudaGetSymbolAddress((void**)&w2r,  g_w2r);
    cudaGetSymbolAddress((void**)&stm,  g_stm);
    cudaGetSymbolAddress((void**)&stl,  g_stl);
    cudaGetSymbolAddress((void**)&scl,  g_scl);

    dim3 blk(256);
    const int N4_1M = D_MODEL * D_MODEL / 4;      // 262144
    const int N4_4M = D_FF * D_MODEL / 4;         // 1048576
    const int BIG_SMEM = 4 * 6144 * 4;            // 98304 bytes

    cudaFuncSetAttribute(gemm_big<1, 1>, cudaFuncAttributeMaxDynamicSharedMemorySize, BIG_SMEM);
    cudaFuncSetAttribute(gemm_big<0, 0>, cudaFuncAttributeMaxDynamicSharedMemorySize, BIG_SMEM);

    // 0) pre-round weights into scratch (permuted tf32 layout)
    round_copy<<<(N4_1M + 255) / 256, 256>>>((const float4*)wq, wqkv, N4_1M);
    round_copy<<<(N4_1M + 255) / 256, 256>>>((const float4*)wk, wqkv + D_MODEL * D_MODEL, N4_1M);
    round_copy<<<(N4_1M + 255) / 256, 256>>>((const float4*)wv, wqkv + 2 * D_MODEL * D_MODEL, N4_1M);
    round_copy<<<(N4_4M + 255) / 256, 256>>>((const float4*)w1, w1r, N4_4M);
    round_copy<<<(N4_4M + 255) / 256, 256>>>((const float4*)w2, w2r, N4_4M);

    // 1) LN1 (rounded, permuted output)
    ln_kernel<<<M_TOK, 256>>>(x, ln1_g, ln1_b, h);

    // 2) fused QKV: [4096,3072] = h @ wqkv^T; q/k/v rounded + permuted
    gemm_big<1, 1><<<dim3(12, 32), blk, BIG_SMEM>>>(h, wqkv, q, bq, nullptr, k, v, bk, bv,
        M_TOK, 3 * D_MODEL, D_MODEL, D_MODEL, D_MODEL, D_MODEL, 0);

    // 3) V transpose (permuted in -> permuted out)
    transpose_v<<<dim3(32, 2, BATCH * N_HEADS), dim3(32, 8)>>>(v, vT);

    // 4) scores -> E = exp(s/8 - m_tile) into attn region (standard layout) + stats
    gemm_mma<0, 0, 1, 8, 0><<<dim3(8, 8, N_HEADS * BATCH), blk>>>(q, k, attn, nullptr, nullptr,
        nullptr, nullptr, nullptr, nullptr,
        nullptr, stm, stl,
        SEQ, SEQ, D_HEAD, D_MODEL, D_MODEL, SEQ, 0.125f, 0, BATCH,
        (long long)SEQ * D_MODEL, 64,
        (long long)SEQ * D_MODEL, 64,
        (long long)SEQ * SEQ, (long long)BATCH * SEQ * SEQ);

    // 5) combine per-tile stats -> per-(tile,row) scale exp(m_t-m)/l
    stat_combine<<<256, 256>>>(stm, stl, scl);

    // 6) ctx = P @ vT^T (+ residual x); rescale E->P, write P back (standard)
    gemm_mma<2, 0, 0, 4, 0><<<dim3(1, 8, N_HEADS * BATCH), blk>>>(attn, vT, o1, nullptr, x,
        nullptr, nullptr, nullptr, nullptr,
        scl, nullptr, nullptr,
        SEQ, D_HEAD, SEQ, SEQ, SEQ, D_MODEL, 1.f, 0, BATCH,
        (long long)SEQ * SEQ, (long long)BATCH * SEQ * SEQ,
        (long long)N_HEADS * D_HEAD * SEQ, (long long)D_HEAD * SEQ,
        (long long)SEQ * D_MODEL, 64);

    // 7) LN2 (rounded, permuted output)
    ln_kernel<<<M_TOK, 256>>>(o1, ln2_g, ln2_b, h2);

    // 8) FFN1: relu(h2 @ w1^T + b1), rounded + permuted output
    gemm_big<1, 1><<<dim3(16, 32), blk, BIG_SMEM>>>(h2, w1r, ff, b1, nullptr,
        nullptr, nullptr, nullptr, nullptr,
        M_TOK, D_FF, D_MODEL, D_MODEL, D_MODEL, D_FF, 1);

    // 9) FFN2: ff @ w2^T + b2 + o1 -> final out (standard layout)
    gemm_big<0, 0><<<dim3(4, 32), blk, BIG_SMEM>>>(ff, w2r, out, b2, o1,
        nullptr, nullptr, nullptr, nullptr,
        M_TOK, D_MODEL, D_FF, D_FF, D_FF, D_MODEL, 0);
}

// round 12
// speedup vs baseline: 1.0472x; 1.0472x over previous
#include <cuda_runtime.h>
#include <cstdint>

#define D_MODEL 1024
#define N_HEADS 16
#define D_HEAD  64
#define D_FF    4096
#define BATCH   4
#define SEQ     1024
#define M_TOK   (BATCH*SEQ)   // 4096

// ---------------- scratch (allocation-free: device globals) ----------------
__device__ float g_h   [M_TOK*D_MODEL];
__device__ float g_q   [M_TOK*D_MODEL];
__device__ float g_k   [M_TOK*D_MODEL];
__device__ float g_v   [M_TOK*D_MODEL];
__device__ float g_vT  [M_TOK*D_MODEL];
__device__ float g_o1  [M_TOK*D_MODEL];
__device__ float g_h2  [M_TOK*D_MODEL];
__device__ float g_ff  [M_TOK*D_FF];
__device__ float g_wqkv[3*D_MODEL*D_MODEL];
__device__ float g_w1r [D_FF*D_MODEL];
__device__ float g_w2r [D_MODEL*D_FF];
__device__ float g_stm [64*8*1024];
__device__ float g_stl [64*8*1024];
__device__ float g_scl [64*8*1024];

// ---------------- helpers ----------------
__device__ __forceinline__ uint32_t f2tf(float f) {
    uint32_t u;
    asm("cvt.rna.tf32.f32 %0, %1;" : "=r"(u) : "f"(f));
    return u;
}
__device__ __forceinline__ float f2tf_f(float f) { return __uint_as_float(f2tf(f)); }

// permuted column position: within each 16-block, k -> 4*(k&3) + ((k>>2)&3)
__device__ __forceinline__ int permc(int c) {
    return (c & ~15) | (((c & 3) << 2) | ((c >> 2) & 3));
}

__device__ __forceinline__ uint32_t smem_u32(const void* p) {
    uint32_t a;
    asm("{ .reg .u64 t; cvta.to.shared.u64 t, %1; cvt.u32.u64 %0, t; }" : "=r"(a) : "l"(p));
    return a;
}

__device__ __forceinline__ void cp_async16(uint32_t saddr, const void* gptr) {
    asm volatile("cp.async.cg.shared.global [%0], [%1], 16;" :: "r"(saddr), "l"(gptr) : "memory");
}
__device__ __forceinline__ void cp_commit() {
    asm volatile("cp.async.commit_group;" ::: "memory");
}
__device__ __forceinline__ void cp_wait2() {
    asm volatile("cp.async.wait_group 2;" ::: "memory");
}

__device__ __forceinline__ void mma_tf32(float* c, uint32_t a0, uint32_t a1, uint32_t a2, uint32_t a3,
                                         uint32_t b0, uint32_t b1) {
    asm volatile(
        "mma.sync.aligned.m16n8k8.row.col.f32.tf32.tf32.f32 "
        "{%0,%1,%2,%3}, {%4,%5,%6,%7}, {%8,%9}, {%0,%1,%2,%3};\n"
        : "+f"(c[0]), "+f"(c[1]), "+f"(c[2]), "+f"(c[3])
        : "r"(a0), "r"(a1), "r"(a2), "r"(a3), "r"(b0), "r"(b1));
}

// ---------------- round-to-tf32 copy, PERMUTED output ----------------
__global__ void round_copy(const float4* __restrict__ src, float* __restrict__ dst, int n4) {
    int i = blockIdx.x * blockDim.x + threadIdx.x;
    if (i < n4) {
        float4 v = src[i];
        float* p = dst + 16 * (i >> 2) + (i & 3);
        p[0]  = f2tf_f(v.x);
        p[4]  = f2tf_f(v.y);
        p[8]  = f2tf_f(v.z);
        p[12] = f2tf_f(v.w);
    }
}

// ---------------- LayerNorm; tf32-rounded + PERMUTED output ----------------
__global__ void ln_kernel(const float* __restrict__ x, const float* __restrict__ g,
                          const float* __restrict__ b, float* __restrict__ out) {
    int row = blockIdx.x;
    int t = threadIdx.x;  // 256 threads, 4 floats each
    const float4* xr = (const float4*)(x + (size_t)row * D_MODEL);
    float4 v = xr[t];
    __shared__ float red[8];

    float s = v.x + v.y + v.z + v.w;
    #pragma unroll
    for (int o = 16; o; o >>= 1) s += __shfl_xor_sync(0xffffffffu, s, o);
    if ((t & 31) == 0) red[t >> 5] = s;
    __syncthreads();
    float tot = red[0]+red[1]+red[2]+red[3]+red[4]+red[5]+red[6]+red[7];
    float mean = tot * (1.0f / D_MODEL);

    float dx = v.x - mean, dy = v.y - mean, dz = v.z - mean, dw = v.w - mean;
    float ss = dx*dx + dy*dy + dz*dz + dw*dw;
    #pragma unroll
    for (int o = 16; o; o >>= 1) ss += __shfl_xor_sync(0xffffffffu, ss, o);
    __syncthreads();
    if ((t & 31) == 0) red[t >> 5] = ss;
    __syncthreads();
    float vtot = red[0]+red[1]+red[2]+red[3]+red[4]+red[5]+red[6]+red[7];
    float inv = 1.0f / (sqrtf(vtot * (1.0f / (D_MODEL - 1))) + 1e-12f);

    float4 g4 = ((const float4*)g)[t];
    float4 b4 = ((const float4*)b)[t];
    float* p = out + (size_t)row * D_MODEL + 16 * (t >> 2) + (t & 3);
    p[0]  = f2tf_f(g4.x * dx * inv + b4.x);
    p[4]  = f2tf_f(g4.y * dy * inv + b4.y);
    p[8]  = f2tf_f(g4.z * dz * inv + b4.z);
    p[12] = f2tf_f(g4.w * dw * inv + b4.w);
}

// ---------------- V transpose: v (permuted) -> vT (permuted) ----------------
__global__ void transpose_v(const float* __restrict__ v, float* __restrict__ vT) {
    __shared__ float tile[32][33];
    int bh = blockIdx.z;             // b*H + h
    int b = bh / N_HEADS, h = bh % N_HEADS;
    int s0 = blockIdx.x * 32;
    int d0 = blockIdx.y * 32;
    int tx = threadIdx.x, ty = threadIdx.y;  // 32 x 8
    const float* src = v + ((size_t)b * SEQ) * D_MODEL + h * D_HEAD;
    int pc = permc(d0 + tx);
    #pragma unroll
    for (int i = 0; i < 32; i += 8)
        tile[ty + i][tx] = src[(size_t)(s0 + ty + i) * D_MODEL + pc];
    __syncthreads();
    float* dst = vT + ((size_t)bh * D_HEAD) * SEQ;
    int ps = permc(s0 + tx);
    #pragma unroll
    for (int i = 0; i < 32; i += 8)
        dst[(size_t)(d0 + ty + i) * SEQ + ps] = tile[tx][ty + i];
}

// ---------------- stat combine: (m_t, l_t) x8 -> per-tile scale exp(m_t-m)/l ------
__global__ void stat_combine(const float* __restrict__ stm, const float* __restrict__ stl,
                             float* __restrict__ scl) {
    int i = blockIdx.x * blockDim.x + threadIdx.x;   // z*1024 + row, 65536 total
    int z = i >> 10, row = i & 1023;
    const float* pm = stm + (size_t)z * 8 * 1024 + row;
    const float* pl = stl + (size_t)z * 8 * 1024 + row;
    float mv[8];
    float m = -1e30f;
    #pragma unroll
    for (int t = 0; t < 8; t++) { mv[t] = pm[t * 1024]; m = fmaxf(m, mv[t]); }
    float ex[8];
    float l = 0.f;
    #pragma unroll
    for (int t = 0; t < 8; t++) { ex[t] = __expf(mv[t] - m); l += pl[t * 1024] * ex[t]; }
    float inv = 1.0f / l;
    float* ps = scl + (size_t)z * 8 * 1024 + row;
    #pragma unroll
    for (int t = 0; t < 8; t++) ps[t * 1024] = ex[t] * inv;
}

// ---------------- tf32 mma.sync GEMM ------------------------------------------------
// MODE 0: cp.async 4-stage pipeline (3 tiles in flight); A,B permuted tf32 gmem.
// MODE 2: attn-ctx; A = E standard; p = E*scl; writeback P; B permuted (2-buf reg staging).
// PERM_OUT: epilogue writes C in permuted layout. STATS: scores softmax-E mode (NT=8).
// Warp grid 4x2, warp tile 32 x (NT*8), CTA tile 128 x (16*NT), BK=16.
// Dynamic smem: MODE0 = 4 stages x 16KB = 64KB, MODE2 = 2 bufs x 16KB = 32KB.
template<int MODE, int ROUND_OUT, int STATS, int NT, int PERM_OUT>
__global__ void __launch_bounds__(256, 2)
gemm_mma(const float* __restrict__ A, const float* __restrict__ B,
         float* __restrict__ C, const float* __restrict__ bias, const float* __restrict__ res,
         float* __restrict__ Ck, float* __restrict__ Cv,
         const float* __restrict__ biask, const float* __restrict__ biasv,
         const float* __restrict__ scl, float* __restrict__ stm, float* __restrict__ stl,
         int M, int N, int K, int lda, int ldb, int ldc,
         float scale, int relu, int zmod,
         long long aLo, long long aHi, long long bLo, long long bHi,
         long long cLo, long long cHi)
{
    extern __shared__ __align__(16) uint32_t sm[];

    int z = blockIdx.z;
    int zlo = z % zmod, zhi = z / zmod;
    A += (size_t)zlo * aLo + (size_t)zhi * aHi;
    B += (size_t)zlo * bLo + (size_t)zhi * bHi;
    size_t coff = (size_t)zlo * cLo + (size_t)zhi * cHi;
    C += coff;
    if (res) res += coff;

    const int tid = threadIdx.x, lane = tid & 31, warp = tid >> 5;
    const int wm = (warp & 3) * 32, wn = (warp >> 2) * (NT * 8);
    const int m0 = blockIdx.y * 128, n0 = blockIdx.x * (16 * NT);

    const int ft = lane & 3, frl = lane >> 2;
    const int fu = ft ^ ((frl >> 1) & 3);
    const uint32_t ldAw = (uint32_t)((wm + frl) * 16 + 4 * fu);
    const uint32_t ldBw = (uint32_t)(2048 + (wn + frl) * 16 + 4 * fu);

    float acc[2][NT][4];
    #pragma unroll
    for (int i = 0; i < 2; i++)
        #pragma unroll
        for (int j = 0; j < NT; j++)
            #pragma unroll
            for (int c = 0; c < 4; c++) acc[i][j][c] = 0.f;

    const int nk = K / 16;

    auto compute_at = [&](const uint32_t* base) {
        uint4 af[2][2];
        #pragma unroll
        for (int mt = 0; mt < 2; mt++)
            #pragma unroll
            for (int h = 0; h < 2; h++)
                af[mt][h] = *(const uint4*)&base[ldAw + mt * 256 + h * 128];
        #pragma unroll
        for (int nt = 0; nt < NT; nt++) {
            uint4 bf = *(const uint4*)&base[ldBw + nt * 128];
            #pragma unroll
            for (int mt = 0; mt < 2; mt++) {
                mma_tf32(acc[mt][nt], af[mt][0].x, af[mt][1].x, af[mt][0].y, af[mt][1].y,
                         bf.x, bf.y);
                mma_tf32(acc[mt][nt], af[mt][0].z, af[mt][1].z, af[mt][0].w, af[mt][1].w,
                         bf.z, bf.w);
            }
        }
    };

    if (MODE == 0) {
        // ---- 4-stage cp.async ring, 3 tiles in flight ----
        const uint32_t smem_base = smem_u32(sm);
        uint32_t saw[2], sbw[2];
        const float *ga[2], *gb[2];
        #pragma unroll
        for (int j = 0; j < 2; j++) {
            int id = tid + 256 * j;
            int r = id >> 2, u = id & 3;
            int up = u ^ ((r >> 1) & 3);
            saw[j] = (uint32_t)((r * 16 + 4 * up) * 4);
            sbw[j] = (uint32_t)((2048 + r * 16 + 4 * up) * 4);
            ga[j] = A + (size_t)(m0 + r) * lda + 4 * u;
            gb[j] = B + (size_t)(n0 + r) * ldb + 4 * u;
        }
        auto issue = [&](int tile, int stg) {
            const int k0 = tile * 16;
            const uint32_t sb = smem_base + (uint32_t)stg * 16384u;
            #pragma unroll
            for (int j = 0; j < 2; j++) cp_async16(sb + saw[j], ga[j] + k0);
            #pragma unroll
            for (int j = 0; j < 2; j++) cp_async16(sb + sbw[j], gb[j] + k0);
            cp_commit();
        };
        issue(0, 0); issue(1, 1); issue(2, 2);
        int st = 0;
        for (int t = 0; t < nk; ++t) {
            cp_wait2();
            __syncthreads();
            compute_at(sm + st * 4096);
            // issue into stage (st+3)&3 = the stage computed LAST iteration;
            // this iteration's __syncthreads guarantees all warps are past it.
            if (t + 3 < nk) issue(t + 3, (st + 3) & 3);
            else            cp_commit();
            st = (st + 1) & 3;
        }
        __syncthreads();
    } else {
        // ---- MODE 2: ctx. A standard E + transform + writeback; B permuted. ----
        const int lr = tid >> 2, c4 = tid & 3, sw = (lr >> 1) & 3;
        uint32_t stA[4];
        #pragma unroll
        for (int j = 0; j < 4; j++) stA[j] = lr * 16 + 4 * (j ^ sw) + c4;
        uint32_t stB = 2048 + lr * 16 + 4 * (c4 ^ sw);
        float* PW = (float*)A;
        float4 aR[2]; uint4 bRr;

        auto loadg = [&](int t) {
            int k0 = t * 16 + c4 * 4;
            const float* sp = scl + ((size_t)z * 8 + (t >> 3)) * 1024 + m0 + lr;
            float s0 = sp[0], s1 = sp[64];
            #pragma unroll
            for (int i = 0; i < 2; i++) {
                int gm = m0 + lr + i * 64;
                aR[i] = *(const float4*)(A + (size_t)gm * lda + k0);
                float s = i ? s1 : s0;
                aR[i].x *= s; aR[i].y *= s; aR[i].z *= s; aR[i].w *= s;
                *(float4*)(PW + (size_t)gm * lda + k0) = aR[i];
            }
            bRr = *(const uint4*)(B + (size_t)(n0 + lr) * ldb + k0);
        };
        auto stores = [&]() {
            #pragma unroll
            for (int i = 0; i < 2; i++) {
                float av[4] = {aR[i].x, aR[i].y, aR[i].z, aR[i].w};
                #pragma unroll
                for (int j = 0; j < 4; j++)
                    sm[stA[j] + i * 1024] = f2tf(av[j]);
            }
            *(uint4*)&sm[stB] = bRr;
            #pragma unroll
            for (int j = 0; j < 4; j++) stA[j] ^= 4096;
            stB ^= 4096;
        };
        loadg(0); stores(); __syncthreads();
        for (int t = 0; t < nk; ++t) {
            if (t + 1 < nk) loadg(t + 1);
            compute_at(sm + ((t & 1) ? 4096 : 0));
            if (t + 1 < nk) stores();
            __syncthreads();
        }
    }

    if (STATS) {
        float* smf = (float*)sm;
        const int g = warp >> 2;
        const int rl = lane >> 2;
        float lmax[2][2];
        #pragma unroll
        for (int mt = 0; mt < 2; mt++)
            #pragma unroll
            for (int h = 0; h < 2; h++) {
                float v = -1e30f;
                #pragma unroll
                for (int nt = 0; nt < NT; nt++) {
                    v = fmaxf(v, acc[mt][nt][2 * h]);
                    v = fmaxf(v, acc[mt][nt][2 * h + 1]);
                }
                lmax[mt][h] = v * scale;
            }
        #pragma unroll
        for (int o = 1; o < 4; o <<= 1)
            #pragma unroll
            for (int mt = 0; mt < 2; mt++)
                #pragma unroll
                for (int h = 0; h < 2; h++)
                    lmax[mt][h] = fmaxf(lmax[mt][h], __shfl_xor_sync(0xffffffffu, lmax[mt][h], o));
        __syncthreads();
        if ((lane & 3) == 0)
            #pragma unroll
            for (int mt = 0; mt < 2; mt++)
                #pragma unroll
                for (int h = 0; h < 2; h++)
                    smf[g * 128 + wm + mt * 16 + h * 8 + rl] = lmax[mt][h];
        __syncthreads();
        float rmax[2][2], lsum[2][2];
        #pragma unroll
        for (int mt = 0; mt < 2; mt++)
            #pragma unroll
            for (int h = 0; h < 2; h++) {
                int row = wm + mt * 16 + h * 8 + rl;
                rmax[mt][h] = fmaxf(smf[row], smf[128 + row]);
                lsum[mt][h] = 0.f;
            }
        #pragma unroll
        for (int mt = 0; mt < 2; ++mt) {
            #pragma unroll
            for (int nt = 0; nt < NT; ++nt) {
                int rbase = m0 + wm + mt * 16 + rl;
                int cbase = n0 + wn + nt * 8 + (lane & 3) * 2;
                #pragma unroll
                for (int h = 0; h < 2; ++h) {
                    float e0 = __expf(acc[mt][nt][2 * h]     * scale - rmax[mt][h]);
                    float e1 = __expf(acc[mt][nt][2 * h + 1] * scale - rmax[mt][h]);
                    *(float2*)(C + (size_t)(rbase + h * 8) * ldc + cbase) = make_float2(e0, e1);
                    lsum[mt][h] += e0 + e1;
                }
            }
        }
        #pragma unroll
        for (int o = 1; o < 4; o <<= 1)
            #pragma unroll
            for (int mt = 0; mt < 2; mt++)
                #pragma unroll
                for (int h = 0; h < 2; h++)
                    lsum[mt][h] += __shfl_xor_sync(0xffffffffu, lsum[mt][h], o);
        if ((lane & 3) == 0)
            #pragma unroll
            for (int mt = 0; mt < 2; mt++)
                #pragma unroll
                for (int h = 0; h < 2; h++)
                    smf[256 + g * 128 + wm + mt * 16 + h * 8 + rl] = lsum[mt][h];
        __syncthreads();
        if (g == 0 && (lane & 3) == 0) {
            #pragma unroll
            for (int mt = 0; mt < 2; mt++)
                #pragma unroll
                for (int h = 0; h < 2; h++) {
                    int row = wm + mt * 16 + h * 8 + rl;
                    size_t idx = ((size_t)z * 8 + blockIdx.x) * 1024 + m0 + row;
                    stm[idx] = rmax[mt][h];
                    stl[idx] = smf[256 + row] + smf[384 + row];
                }
        }
    } else {
        float* Cp = C; const float* bp = bias; int noff = 0;
        if (Ck) {
            if (n0 >= 2048)      { Cp = Cv; bp = biasv; noff = 2048; }
            else if (n0 >= 1024) { Cp = Ck; bp = biask; noff = 1024; }
        }
        #pragma unroll
        for (int mt = 0; mt < 2; ++mt) {
            #pragma unroll
            for (int nt = 0; nt < NT; ++nt) {
                int rbase = m0 + wm + mt * 16 + (lane >> 2);
                int cbase = n0 + wn + nt * 8 + (lane & 3) * 2;
                #pragma unroll
                for (int h = 0; h < 2; ++h) {
                    int rr = rbase + h * 8;
                    int cl = cbase - noff;
                    float v0 = acc[mt][nt][h * 2 + 0] * scale;
                    float v1 = acc[mt][nt][h * 2 + 1] * scale;
                    if (bp)  { float2 bb = *(const float2*)(bp + cl); v0 += bb.x; v1 += bb.y; }
                    if (res) { float2 r2 = *(const float2*)(res + (size_t)rr * ldc + cl); v0 += r2.x; v1 += r2.y; }
                    if (relu) { v0 = fmaxf(v0, 0.f); v1 = fmaxf(v1, 0.f); }
                    if (ROUND_OUT) { v0 = f2tf_f(v0); v1 = f2tf_f(v1); }
                    if (PERM_OUT) {
                        int p = permc(cl);
                        float* rp = Cp + (size_t)rr * ldc;
                        rp[p] = v0; rp[p + 4] = v1;
                    } else {
                        *(float2*)(Cp + (size_t)rr * ldc + cl) = make_float2(v0, v1);
                    }
                }
            }
        }
    }
}

// ---------------- launch ----------------
extern "C" void kernel_launch(void* const* d_in, const int* in_sizes, int n_in,
                              void* d_out, int out_size) {
    const float* x     = (const float*)d_in[0];
    const float* ln1_g = (const float*)d_in[1];
    const float* ln1_b = (const float*)d_in[2];
    const float* wq    = (const float*)d_in[3];
    const float* bq    = (const float*)d_in[4];
    const float* wk    = (const float*)d_in[5];
    const float* bk    = (const float*)d_in[6];
    const float* wv    = (const float*)d_in[7];
    const float* bv    = (const float*)d_in[8];
    const float* ln2_g = (const float*)d_in[9];
    const float* ln2_b = (const float*)d_in[10];
    const float* w1    = (const float*)d_in[11];
    const float* b1    = (const float*)d_in[12];
    const float* w2    = (const float*)d_in[13];
    const float* b2    = (const float*)d_in[14];

    float* out  = (float*)d_out;
    float* attn = out + (size_t)BATCH * SEQ * D_MODEL;

    float *h, *q, *k, *v, *vT, *o1, *h2, *ff, *wqkv, *w1r, *w2r, *stm, *stl, *scl;
    cudaGetSymbolAddress((void**)&h,    g_h);
    cudaGetSymbolAddress((void**)&q,    g_q);
    cudaGetSymbolAddress((void**)&k,    g_k);
    cudaGetSymbolAddress((void**)&v,    g_v);
    cudaGetSymbolAddress((void**)&vT,   g_vT);
    cudaGetSymbolAddress((void**)&o1,   g_o1);
    cudaGetSymbolAddress((void**)&h2,   g_h2);
    cudaGetSymbolAddress((void**)&ff,   g_ff);
    cudaGetSymbolAddress((void**)&wqkv, g_wqkv);
    cudaGetSymbolAddress((void**)&w1r,  g_w1r);
    cudaGetSymbolAddress((void**)&w2r,  g_w2r);
    cudaGetSymbolAddress((void**)&stm,  g_stm);
    cudaGetSymbolAddress((void**)&stl,  g_stl);
    cudaGetSymbolAddress((void**)&scl,  g_scl);

    dim3 blk(256);
    const int N4_1M = D_MODEL * D_MODEL / 4;      // 262144
    const int N4_4M = D_FF * D_MODEL / 4;         // 1048576
    const int SM_P4 = 4 * 4096 * 4;               // 65536 bytes (MODE 0)
    const int SM_P2 = 2 * 4096 * 4;               // 32768 bytes (MODE 2)

    cudaFuncSetAttribute(gemm_mma<0, 1, 0, 8, 1>, cudaFuncAttributeMaxDynamicSharedMemorySize, SM_P4);
    cudaFuncSetAttribute(gemm_mma<0, 0, 1, 8, 0>, cudaFuncAttributeMaxDynamicSharedMemorySize, SM_P4);
    cudaFuncSetAttribute(gemm_mma<0, 0, 0, 8, 0>, cudaFuncAttributeMaxDynamicSharedMemorySize, SM_P4);
    cudaFuncSetAttribute(gemm_mma<2, 0, 0, 4, 0>, cudaFuncAttributeMaxDynamicSharedMemorySize, SM_P2);

    // 0) pre-round weights into scratch (permuted tf32 layout)
    round_copy<<<(N4_1M + 255) / 256, 256>>>((const float4*)wq, wqkv, N4_1M);
    round_copy<<<(N4_1M + 255) / 256, 256>>>((const float4*)wk, wqkv + D_MODEL * D_MODEL, N4_1M);
    round_copy<<<(N4_1M + 255) / 256, 256>>>((const float4*)wv, wqkv + 2 * D_MODEL * D_MODEL, N4_1M);
    round_copy<<<(N4_4M + 255) / 256, 256>>>((const float4*)w1, w1r, N4_4M);
    round_copy<<<(N4_4M + 255) / 256, 256>>>((const float4*)w2, w2r, N4_4M);

    // 1) LN1 (rounded, permuted output)
    ln_kernel<<<M_TOK, 256>>>(x, ln1_g, ln1_b, h);

    // 2) fused QKV: [4096,3072] = h @ wqkv^T; q/k/v rounded + permuted
    gemm_mma<0, 1, 0, 8, 1><<<dim3(24, 32, 1), blk, SM_P4>>>(h, wqkv, q, bq, nullptr, k, v, bk, bv,
        nullptr, nullptr, nullptr,
        M_TOK, 3 * D_MODEL, D_MODEL, D_MODEL, D_MODEL, D_MODEL, 1.f, 0, 1, 0,0,0,0,0,0);

    // 3) V transpose (permuted in -> permuted out)
    transpose_v<<<dim3(32, 2, BATCH * N_HEADS), dim3(32, 8)>>>(v, vT);

    // 4) scores -> E = exp(s/8 - m_tile) into attn region (standard layout) + stats
    gemm_mma<0, 0, 1, 8, 0><<<dim3(8, 8, N_HEADS * BATCH), blk, SM_P4>>>(q, k, attn, nullptr, nullptr,
        nullptr, nullptr, nullptr, nullptr,
        nullptr, stm, stl,
        SEQ, SEQ, D_HEAD, D_MODEL, D_MODEL, SEQ, 0.125f, 0, BATCH,
        (long long)SEQ * D_MODEL, 64,
        (long long)SEQ * D_MODEL, 64,
        (long long)SEQ * SEQ, (long long)BATCH * SEQ * SEQ);

    // 5) combine per-tile stats -> per-(tile,row) scale exp(m_t-m)/l
    stat_combine<<<256, 256>>>(stm, stl, scl);

    // 6) ctx = P @ vT^T (+ residual x); rescale E->P, write P back (standard)
    gemm_mma<2, 0, 0, 4, 0><<<dim3(1, 8, N_HEADS * BATCH), blk, SM_P2>>>(attn, vT, o1, nullptr, x,
        nullptr, nullptr, nullptr, nullptr,
        scl, nullptr, nullptr,
        SEQ, D_HEAD, SEQ, SEQ, SEQ, D_MODEL, 1.f, 0, BATCH,
        (long long)SEQ * SEQ, (long long)BATCH * SEQ * SEQ,
        (long long)N_HEADS * D_HEAD * SEQ, (long long)D_HEAD * SEQ,
        (long long)SEQ * D_MODEL, 64);

    // 7) LN2 (rounded, permuted output)
    ln_kernel<<<M_TOK, 256>>>(o1, ln2_g, ln2_b, h2);

    // 8) FFN1: relu(h2 @ w1^T + b1), rounded + permuted output
    gemm_mma<0, 1, 0, 8, 1><<<dim3(32, 32, 1), blk, SM_P4>>>(h2, w1r, ff, b1, nullptr,
        nullptr, nullptr, nullptr, nullptr,
        nullptr, nullptr, nullptr,
        M_TOK, D_FF, D_MODEL, D_MODEL, D_MODEL, D_FF, 1.f, 1, 1, 0,0,0,0,0,0);

    // 9) FFN2: ff @ w2^T + b2 + o1 -> final out (standard layout)
    gemm_mma<0, 0, 0, 8, 0><<<dim3(8, 32, 1), blk, SM_P4>>>(ff, w2r, out, b2, o1,
        nullptr, nullptr, nullptr, nullptr,
        nullptr, nullptr, nullptr,
        M_TOK, D_MODEL, D_FF, D_FF, D_FF, D_MODEL, 1.f, 0, 1, 0,0,0,0,0,0);
}

// round 13
// speedup vs baseline: 1.0990x; 1.0494x over previous
#include <cuda_runtime.h>
#include <cstdint>

#define D_MODEL 1024
#define N_HEADS 16
#define D_HEAD  64
#define D_FF    4096
#define BATCH   4
#define SEQ     1024
#define M_TOK   (BATCH*SEQ)   // 4096

// ---------------- scratch (allocation-free: device globals) ----------------
__device__ float g_h   [M_TOK*D_MODEL];
__device__ float g_q   [M_TOK*D_MODEL];
__device__ float g_k   [M_TOK*D_MODEL];
__device__ float g_v   [M_TOK*D_MODEL];
__device__ float g_vT  [M_TOK*D_MODEL];
__device__ float g_o1  [M_TOK*D_MODEL];
__device__ float g_h2  [M_TOK*D_MODEL];
__device__ float g_ff  [M_TOK*D_FF];
__device__ float g_wqkv[3*D_MODEL*D_MODEL];
__device__ float g_w1r [D_FF*D_MODEL];
__device__ float g_w2r [D_MODEL*D_FF];
__device__ float g_stm [64*8*1024];
__device__ float g_stl [64*8*1024];
__device__ float g_rst [64*1024*2];      // per-(z,row): (m, 1/l)

// ---------------- helpers ----------------
__device__ __forceinline__ uint32_t f2tf(float f) {
    uint32_t u;
    asm("cvt.rna.tf32.f32 %0, %1;" : "=r"(u) : "f"(f));
    return u;
}
__device__ __forceinline__ float f2tf_f(float f) { return __uint_as_float(f2tf(f)); }

// permuted column position: within each 16-block, k -> 4*(k&3) + ((k>>2)&3)
__device__ __forceinline__ int permc(int c) {
    return (c & ~15) | (((c & 3) << 2) | ((c >> 2) & 3));
}

__device__ __forceinline__ uint32_t smem_u32(const void* p) {
    uint32_t a;
    asm("{ .reg .u64 t; cvta.to.shared.u64 t, %1; cvt.u32.u64 %0, t; }" : "=r"(a) : "l"(p));
    return a;
}

__device__ __forceinline__ void cp_async16(uint32_t saddr, const void* gptr) {
    asm volatile("cp.async.cg.shared.global [%0], [%1], 16;" :: "r"(saddr), "l"(gptr) : "memory");
}
__device__ __forceinline__ void cp_commit() {
    asm volatile("cp.async.commit_group;" ::: "memory");
}
__device__ __forceinline__ void cp_wait0() {
    asm volatile("cp.async.wait_group 0;" ::: "memory");
}
__device__ __forceinline__ void cp_wait1() {
    asm volatile("cp.async.wait_group 1;" ::: "memory");
}
__device__ __forceinline__ void cp_wait2() {
    asm volatile("cp.async.wait_group 2;" ::: "memory");
}

__device__ __forceinline__ void mma_tf32(float* c, uint32_t a0, uint32_t a1, uint32_t a2, uint32_t a3,
                                         uint32_t b0, uint32_t b1) {
    asm volatile(
        "mma.sync.aligned.m16n8k8.row.col.f32.tf32.tf32.f32 "
        "{%0,%1,%2,%3}, {%4,%5,%6,%7}, {%8,%9}, {%0,%1,%2,%3};\n"
        : "+f"(c[0]), "+f"(c[1]), "+f"(c[2]), "+f"(c[3])
        : "r"(a0), "r"(a1), "r"(a2), "r"(a3), "r"(b0), "r"(b1));
}

// ---------------- round-to-tf32 copy, PERMUTED output ----------------
__global__ void round_copy(const float4* __restrict__ src, float* __restrict__ dst, int n4) {
    int i = blockIdx.x * blockDim.x + threadIdx.x;
    if (i < n4) {
        float4 v = src[i];
        float* p = dst + 16 * (i >> 2) + (i & 3);
        p[0]  = f2tf_f(v.x);
        p[4]  = f2tf_f(v.y);
        p[8]  = f2tf_f(v.z);
        p[12] = f2tf_f(v.w);
    }
}

// ---------------- LayerNorm; tf32-rounded + PERMUTED output ----------------
__global__ void ln_kernel(const float* __restrict__ x, const float* __restrict__ g,
                          const float* __restrict__ b, float* __restrict__ out) {
    int row = blockIdx.x;
    int t = threadIdx.x;  // 256 threads, 4 floats each
    const float4* xr = (const float4*)(x + (size_t)row * D_MODEL);
    float4 v = xr[t];
    __shared__ float red[8];

    float s = v.x + v.y + v.z + v.w;
    #pragma unroll
    for (int o = 16; o; o >>= 1) s += __shfl_xor_sync(0xffffffffu, s, o);
    if ((t & 31) == 0) red[t >> 5] = s;
    __syncthreads();
    float tot = red[0]+red[1]+red[2]+red[3]+red[4]+red[5]+red[6]+red[7];
    float mean = tot * (1.0f / D_MODEL);

    float dx = v.x - mean, dy = v.y - mean, dz = v.z - mean, dw = v.w - mean;
    float ss = dx*dx + dy*dy + dz*dz + dw*dw;
    #pragma unroll
    for (int o = 16; o; o >>= 1) ss += __shfl_xor_sync(0xffffffffu, ss, o);
    __syncthreads();
    if ((t & 31) == 0) red[t >> 5] = ss;
    __syncthreads();
    float vtot = red[0]+red[1]+red[2]+red[3]+red[4]+red[5]+red[6]+red[7];
    float inv = 1.0f / (sqrtf(vtot * (1.0f / (D_MODEL - 1))) + 1e-12f);

    float4 g4 = ((const float4*)g)[t];
    float4 b4 = ((const float4*)b)[t];
    float* p = out + (size_t)row * D_MODEL + 16 * (t >> 2) + (t & 3);
    p[0]  = f2tf_f(g4.x * dx * inv + b4.x);
    p[4]  = f2tf_f(g4.y * dy * inv + b4.y);
    p[8]  = f2tf_f(g4.z * dz * inv + b4.z);
    p[12] = f2tf_f(g4.w * dw * inv + b4.w);
}

// ---------------- V transpose: v (permuted) -> vT (permuted) ----------------
__global__ void transpose_v(const float* __restrict__ v, float* __restrict__ vT) {
    __shared__ float tile[32][33];
    int bh = blockIdx.z;             // b*H + h
    int b = bh / N_HEADS, h = bh % N_HEADS;
    int s0 = blockIdx.x * 32;
    int d0 = blockIdx.y * 32;
    int tx = threadIdx.x, ty = threadIdx.y;  // 32 x 8
    const float* src = v + ((size_t)b * SEQ) * D_MODEL + h * D_HEAD;
    int pc = permc(d0 + tx);
    #pragma unroll
    for (int i = 0; i < 32; i += 8)
        tile[ty + i][tx] = src[(size_t)(s0 + ty + i) * D_MODEL + pc];
    __syncthreads();
    float* dst = vT + ((size_t)bh * D_HEAD) * SEQ;
    int ps = permc(s0 + tx);
    #pragma unroll
    for (int i = 0; i < 32; i += 8)
        dst[(size_t)(d0 + ty + i) * SEQ + ps] = tile[tx][ty + i];
}

// ---------------- stat combine: (m_t, l_t) x8 -> per-row (m, 1/l) ------------------
__global__ void stat_combine(const float* __restrict__ stm, const float* __restrict__ stl,
                             float2* __restrict__ rst) {
    int i = blockIdx.x * blockDim.x + threadIdx.x;   // z*1024 + row, 65536 total
    int z = i >> 10, row = i & 1023;
    const float* pm = stm + (size_t)z * 8 * 1024 + row;
    const float* pl = stl + (size_t)z * 8 * 1024 + row;
    float mv[8];
    float m = -1e30f;
    #pragma unroll
    for (int t = 0; t < 8; t++) { mv[t] = pm[t * 1024]; m = fmaxf(m, mv[t]); }
    float l = 0.f;
    #pragma unroll
    for (int t = 0; t < 8; t++) l += pl[t * 1024] * __expf(mv[t] - m);
    rst[i] = make_float2(m, 1.0f / l);
}

// ---------------- tf32 mma.sync GEMM (big GEMMs + scores stats) --------------------
// MODE 0: cp.async 4-stage pipeline (3 tiles in flight); A,B permuted tf32 gmem.
// STATS: 0 = normal epilogue; 2 = stats-only (per-row tile max + sumexp -> stm/stl,
//        NO C write). PERM_OUT: epilogue writes C in permuted layout.
// Warp grid 4x2, warp tile 32 x (NT*8), CTA tile 128 x (16*NT), BK=16.
template<int MODE, int ROUND_OUT, int STATS, int NT, int PERM_OUT>
__global__ void __launch_bounds__(256, 2)
gemm_mma(const float* __restrict__ A, const float* __restrict__ B,
         float* __restrict__ C, const float* __restrict__ bias, const float* __restrict__ res,
         float* __restrict__ Ck, float* __restrict__ Cv,
         const float* __restrict__ biask, const float* __restrict__ biasv,
         const float* __restrict__ scl, float* __restrict__ stm, float* __restrict__ stl,
         int M, int N, int K, int lda, int ldb, int ldc,
         float scale, int relu, int zmod,
         long long aLo, long long aHi, long long bLo, long long bHi,
         long long cLo, long long cHi)
{
    extern __shared__ __align__(16) uint32_t sm[];

    int z = blockIdx.z;
    int zlo = z % zmod, zhi = z / zmod;
    A += (size_t)zlo * aLo + (size_t)zhi * aHi;
    B += (size_t)zlo * bLo + (size_t)zhi * bHi;
    size_t coff = (size_t)zlo * cLo + (size_t)zhi * cHi;
    C += coff;
    if (res) res += coff;

    const int tid = threadIdx.x, lane = tid & 31, warp = tid >> 5;
    const int wm = (warp & 3) * 32, wn = (warp >> 2) * (NT * 8);
    const int m0 = blockIdx.y * 128, n0 = blockIdx.x * (16 * NT);

    const int ft = lane & 3, frl = lane >> 2;
    const int fu = ft ^ ((frl >> 1) & 3);
    const uint32_t ldAw = (uint32_t)((wm + frl) * 16 + 4 * fu);
    const uint32_t ldBw = (uint32_t)(2048 + (wn + frl) * 16 + 4 * fu);

    float acc[2][NT][4];
    #pragma unroll
    for (int i = 0; i < 2; i++)
        #pragma unroll
        for (int j = 0; j < NT; j++)
            #pragma unroll
            for (int c = 0; c < 4; c++) acc[i][j][c] = 0.f;

    const int nk = K / 16;

    auto compute_at = [&](const uint32_t* base) {
        uint4 af[2][2];
        #pragma unroll
        for (int mt = 0; mt < 2; mt++)
            #pragma unroll
            for (int h = 0; h < 2; h++)
                af[mt][h] = *(const uint4*)&base[ldAw + mt * 256 + h * 128];
        #pragma unroll
        for (int nt = 0; nt < NT; nt++) {
            uint4 bf = *(const uint4*)&base[ldBw + nt * 128];
            #pragma unroll
            for (int mt = 0; mt < 2; mt++) {
                mma_tf32(acc[mt][nt], af[mt][0].x, af[mt][1].x, af[mt][0].y, af[mt][1].y,
                         bf.x, bf.y);
                mma_tf32(acc[mt][nt], af[mt][0].z, af[mt][1].z, af[mt][0].w, af[mt][1].w,
                         bf.z, bf.w);
            }
        }
    };

    {
        // ---- 4-stage cp.async ring, 3 tiles in flight ----
        const uint32_t smem_base = smem_u32(sm);
        uint32_t saw[2], sbw[2];
        const float *ga[2], *gb[2];
        #pragma unroll
        for (int j = 0; j < 2; j++) {
            int id = tid + 256 * j;
            int r = id >> 2, u = id & 3;
            int up = u ^ ((r >> 1) & 3);
            saw[j] = (uint32_t)((r * 16 + 4 * up) * 4);
            sbw[j] = (uint32_t)((2048 + r * 16 + 4 * up) * 4);
            ga[j] = A + (size_t)(m0 + r) * lda + 4 * u;
            gb[j] = B + (size_t)(n0 + r) * ldb + 4 * u;
        }
        auto issue = [&](int tile, int stg) {
            const int k0 = tile * 16;
            const uint32_t sb = smem_base + (uint32_t)stg * 16384u;
            #pragma unroll
            for (int j = 0; j < 2; j++) cp_async16(sb + saw[j], ga[j] + k0);
            #pragma unroll
            for (int j = 0; j < 2; j++) cp_async16(sb + sbw[j], gb[j] + k0);
            cp_commit();
        };
        issue(0, 0); issue(1, 1); issue(2, 2);
        int st = 0;
        for (int t = 0; t < nk; ++t) {
            cp_wait2();
            __syncthreads();
            compute_at(sm + st * 4096);
            if (t + 3 < nk) issue(t + 3, (st + 3) & 3);
            else            cp_commit();
            st = (st + 1) & 3;
        }
        __syncthreads();
    }

    if (STATS == 2) {
        // ---- stats-only: per-row tile max + sumexp; NO C store ----
        float* smf = (float*)sm;
        const int g = warp >> 2;
        const int rl = lane >> 2;
        float lmax[2][2];
        #pragma unroll
        for (int mt = 0; mt < 2; mt++)
            #pragma unroll
            for (int h = 0; h < 2; h++) {
                float v = -1e30f;
                #pragma unroll
                for (int nt = 0; nt < NT; nt++) {
                    v = fmaxf(v, acc[mt][nt][2 * h]);
                    v = fmaxf(v, acc[mt][nt][2 * h + 1]);
                }
                lmax[mt][h] = v * scale;
            }
        #pragma unroll
        for (int o = 1; o < 4; o <<= 1)
            #pragma unroll
            for (int mt = 0; mt < 2; mt++)
                #pragma unroll
                for (int h = 0; h < 2; h++)
                    lmax[mt][h] = fmaxf(lmax[mt][h], __shfl_xor_sync(0xffffffffu, lmax[mt][h], o));
        __syncthreads();
        if ((lane & 3) == 0)
            #pragma unroll
            for (int mt = 0; mt < 2; mt++)
                #pragma unroll
                for (int h = 0; h < 2; h++)
                    smf[g * 128 + wm + mt * 16 + h * 8 + rl] = lmax[mt][h];
        __syncthreads();
        float rmax[2][2], lsum[2][2];
        #pragma unroll
        for (int mt = 0; mt < 2; mt++)
            #pragma unroll
            for (int h = 0; h < 2; h++) {
                int row = wm + mt * 16 + h * 8 + rl;
                rmax[mt][h] = fmaxf(smf[row], smf[128 + row]);
                lsum[mt][h] = 0.f;
            }
        #pragma unroll
        for (int mt = 0; mt < 2; ++mt)
            #pragma unroll
            for (int nt = 0; nt < NT; ++nt)
                #pragma unroll
                for (int h = 0; h < 2; ++h) {
                    lsum[mt][h] += __expf(acc[mt][nt][2 * h]     * scale - rmax[mt][h]);
                    lsum[mt][h] += __expf(acc[mt][nt][2 * h + 1] * scale - rmax[mt][h]);
                }
        #pragma unroll
        for (int o = 1; o < 4; o <<= 1)
            #pragma unroll
            for (int mt = 0; mt < 2; mt++)
                #pragma unroll
                for (int h = 0; h < 2; h++)
                    lsum[mt][h] += __shfl_xor_sync(0xffffffffu, lsum[mt][h], o);
        if ((lane & 3) == 0)
            #pragma unroll
            for (int mt = 0; mt < 2; mt++)
                #pragma unroll
                for (int h = 0; h < 2; h++)
                    smf[256 + g * 128 + wm + mt * 16 + h * 8 + rl] = lsum[mt][h];
        __syncthreads();
        if (g == 0 && (lane & 3) == 0) {
            #pragma unroll
            for (int mt = 0; mt < 2; mt++)
                #pragma unroll
                for (int h = 0; h < 2; h++) {
                    int row = wm + mt * 16 + h * 8 + rl;
                    size_t idx = ((size_t)z * 8 + blockIdx.x) * 1024 + m0 + row;
                    stm[idx] = rmax[mt][h];
                    stl[idx] = smf[256 + row] + smf[384 + row];
                }
        }
    } else {
        float* Cp = C; const float* bp = bias; int noff = 0;
        if (Ck) {
            if (n0 >= 2048)      { Cp = Cv; bp = biasv; noff = 2048; }
            else if (n0 >= 1024) { Cp = Ck; bp = biask; noff = 1024; }
        }
        #pragma unroll
        for (int mt = 0; mt < 2; ++mt) {
            #pragma unroll
            for (int nt = 0; nt < NT; ++nt) {
                int rbase = m0 + wm + mt * 16 + (lane >> 2);
                int cbase = n0 + wn + nt * 8 + (lane & 3) * 2;
                #pragma unroll
                for (int h = 0; h < 2; ++h) {
                    int rr = rbase + h * 8;
                    int cl = cbase - noff;
                    float v0 = acc[mt][nt][h * 2 + 0] * scale;
                    float v1 = acc[mt][nt][h * 2 + 1] * scale;
                    if (bp)  { float2 bb = *(const float2*)(bp + cl); v0 += bb.x; v1 += bb.y; }
                    if (res) { float2 r2 = *(const float2*)(res + (size_t)rr * ldc + cl); v0 += r2.x; v1 += r2.y; }
                    if (relu) { v0 = fmaxf(v0, 0.f); v1 = fmaxf(v1, 0.f); }
                    if (ROUND_OUT) { v0 = f2tf_f(v0); v1 = f2tf_f(v1); }
                    if (PERM_OUT) {
                        int p = permc(cl);
                        float* rp = Cp + (size_t)rr * ldc;
                        rp[p] = v0; rp[p + 4] = v1;
                    } else {
                        *(float2*)(Cp + (size_t)rr * ldc + cl) = make_float2(v0, v1);
                    }
                }
            }
        }
    }
}

// ---------------- fused attention ctx: S recompute -> P write -> ctx + residual ----
// Per CTA: z (=h*4+b), 128-row q block. Loops 16 column tiles of 64 k-positions:
//   S = q @ k_j^T (tf32 MMA, bit-identical order to scores kernel),
//   p = __expf(s/8 - m) * invl  (per-row stats from rst),
//   P -> gmem (final attn output) and -> smem (rotation-swizzled) for
//   ctx += P @ vT_j^T.  Epilogue: o1 = ctx + x.
// smem (words): q[0,8192) kt[8192,12288) vt[12288,16384) P[16384,24576) = 96KB.
__global__ void __launch_bounds__(256, 2)
attn_ctx(const float* __restrict__ q, const float* __restrict__ k,
         const float* __restrict__ vT, const float2* __restrict__ rst,
         float* __restrict__ attn, const float* __restrict__ x,
         float* __restrict__ o1)
{
    extern __shared__ __align__(16) uint32_t sm[];
    constexpr int QW = 0, KW = 8192, VW = 12288, PWo = 16384;
    constexpr int NJ = 16;

    const int tid = threadIdx.x, lane = tid & 31, warp = tid >> 5;
    const int wm = (warp & 3) * 32, wn = (warp >> 2) * 32;
    const int ft = lane & 3, frl = lane >> 2;
    const int zz = blockIdx.y;           // h*4 + b
    const int b = zz & 3, hh = zz >> 2;
    const int m0 = blockIdx.x * 128;

    const float* qbase = q + ((size_t)b * SEQ + m0) * D_MODEL + hh * 64;
    const float* kbase = k + (size_t)b * SEQ * D_MODEL + hh * 64;
    const float* vbase = vT + (size_t)(b * N_HEADS + hh) * 64 * SEQ;
    float* pbase = attn + (size_t)zz * SEQ * SEQ + (size_t)m0 * SEQ;
    const float* xbase = x + ((size_t)b * SEQ + m0) * D_MODEL + hh * 64;
    float* obase = o1 + ((size_t)b * SEQ + m0) * D_MODEL + hh * 64;

    const uint32_t smb = smem_u32(sm);

    // 64-float row region, rotation swizzle: unit slot = (4*blk + u + 4*(r&1)) & 15
    auto swaddr = [](int r, int blk, int u) {
        return r * 64 + 4 * ((4 * blk + u + ((r & 1) << 2)) & 15);
    };

    auto load_q = [&]() {
        #pragma unroll
        for (int j = 0; j < 8; j++) {
            int g = tid + 256 * j;
            int r = g >> 4, w = g & 15, bb = w >> 2, u = w & 3;
            cp_async16(smb + 4 * (QW + swaddr(r, bb, u)),
                       qbase + (size_t)r * D_MODEL + bb * 16 + 4 * u);
        }
    };
    auto load_k = [&](int jt) {
        #pragma unroll
        for (int j = 0; j < 4; j++) {
            int g = tid + 256 * j;
            int r = g >> 4, w = g & 15, bb = w >> 2, u = w & 3;
            cp_async16(smb + 4 * (KW + swaddr(r, bb, u)),
                       kbase + (size_t)(jt * 64 + r) * D_MODEL + bb * 16 + 4 * u);
        }
    };
    auto load_v = [&](int jt) {
        #pragma unroll
        for (int j = 0; j < 4; j++) {
            int g = tid + 256 * j;
            int r = g >> 4, w = g & 15, bb = w >> 2, u = w & 3;
            cp_async16(smb + 4 * (VW + swaddr(r, bb, u)),
                       vbase + (size_t)r * SEQ + jt * 64 + bb * 16 + 4 * u);
        }
    };

    // per-thread row stats (rows wm + mt*16 + h*8 + frl)
    float2 st[2][2];
    #pragma unroll
    for (int mt = 0; mt < 2; mt++)
        #pragma unroll
        for (int h = 0; h < 2; h++)
            st[mt][h] = rst[(size_t)zz * 1024 + m0 + wm + mt * 16 + h * 8 + frl];

    float acc_c[2][4][4];
    #pragma unroll
    for (int i = 0; i < 2; i++)
        #pragma unroll
        for (int j = 0; j < 4; j++)
            #pragma unroll
            for (int c = 0; c < 4; c++) acc_c[i][j][c] = 0.f;

    load_q(); load_k(0); cp_commit();     // group: {q, kt0}
    load_v(0); cp_commit();               // group: {vt0}

    for (int jt = 0; jt < NJ; ++jt) {
        float acc_s[2][4][4];
        #pragma unroll
        for (int i = 0; i < 2; i++)
            #pragma unroll
            for (int j = 0; j < 4; j++)
                #pragma unroll
                for (int c = 0; c < 4; c++) acc_s[i][j][c] = 0.f;

        cp_wait1();          // kt (and q) ready; vt may still be in flight
        __syncthreads();

        // S = q @ kt^T  (same block/kk order as scores kernel)
        #pragma unroll
        for (int kb = 0; kb < 4; kb++) {
            uint4 af[2][2];
            #pragma unroll
            for (int mt = 0; mt < 2; mt++)
                #pragma unroll
                for (int h = 0; h < 2; h++)
                    af[mt][h] = *(const uint4*)&sm[QW + swaddr(wm + mt * 16 + h * 8 + frl, kb, ft)];
            #pragma unroll
            for (int nt = 0; nt < 4; nt++) {
                uint4 bf = *(const uint4*)&sm[KW + swaddr(wn + nt * 8 + frl, kb, ft)];
                #pragma unroll
                for (int mt = 0; mt < 2; mt++) {
                    mma_tf32(acc_s[mt][nt], af[mt][0].x, af[mt][1].x, af[mt][0].y, af[mt][1].y,
                             bf.x, bf.y);
                    mma_tf32(acc_s[mt][nt], af[mt][0].z, af[mt][1].z, af[mt][0].w, af[mt][1].w,
                             bf.z, bf.w);
                }
            }
        }

        // transform S -> P (in place) and stage P into smem
        #pragma unroll
        for (int mt = 0; mt < 2; mt++) {
            #pragma unroll
            for (int h = 0; h < 2; h++) {
                int r = wm + mt * 16 + h * 8 + frl;
                int rot = (r & 1) << 2;
                float mrow = st[mt][h].x, invl = st[mt][h].y;
                #pragma unroll
                for (int nt = 0; nt < 4; nt++) {
                    #pragma unroll
                    for (int cc = 0; cc < 2; cc++) {
                        float p = __expf(acc_s[mt][nt][h * 2 + cc] * 0.125f - mrow) * invl;
                        acc_s[mt][nt][h * 2 + cc] = p;
                        int c = wn + nt * 8 + (lane & 3) * 2 + cc;
                        int blk = c >> 4, cb = c & 15, t = cb & 3, ii = cb >> 2;
                        sm[PWo + r * 64 + 4 * ((4 * blk + t + rot) & 15) + ii] = __float_as_uint(p);
                    }
                }
            }
        }

        cp_wait0();          // vt ready
        __syncthreads();     // P visible to all; kt fully consumed
        if (jt + 1 < NJ) load_k(jt + 1);
        cp_commit();

        // ctx += P @ vt^T
        #pragma unroll
        for (int kb = 0; kb < 4; kb++) {
            uint4 af[2][2];
            #pragma unroll
            for (int mt = 0; mt < 2; mt++)
                #pragma unroll
                for (int h = 0; h < 2; h++)
                    af[mt][h] = *(const uint4*)&sm[PWo + swaddr(wm + mt * 16 + h * 8 + frl, kb, ft)];
            #pragma unroll
            for (int nt = 0; nt < 4; nt++) {
                uint4 bf = *(const uint4*)&sm[VW + swaddr(wn + nt * 8 + frl, kb, ft)];
                #pragma unroll
                for (int mt = 0; mt < 2; mt++) {
                    mma_tf32(acc_c[mt][nt], af[mt][0].x, af[mt][1].x, af[mt][0].y, af[mt][1].y,
                             bf.x, bf.y);
                    mma_tf32(acc_c[mt][nt], af[mt][0].z, af[mt][1].z, af[mt][0].w, af[mt][1].w,
                             bf.z, bf.w);
                }
            }
        }

        // write final P to gmem
        #pragma unroll
        for (int mt = 0; mt < 2; mt++)
            #pragma unroll
            for (int h = 0; h < 2; h++) {
                int r = wm + mt * 16 + h * 8 + frl;
                float* prow = pbase + (size_t)r * SEQ + jt * 64;
                #pragma unroll
                for (int nt = 0; nt < 4; nt++)
                    *(float2*)(prow + wn + nt * 8 + (lane & 3) * 2) =
                        make_float2(acc_s[mt][nt][h * 2], acc_s[mt][nt][h * 2 + 1]);
            }

        __syncthreads();     // vt and P consumed
        if (jt + 1 < NJ) load_v(jt + 1);
        cp_commit();
    }

    // epilogue: o1 = ctx + x
    #pragma unroll
    for (int mt = 0; mt < 2; mt++)
        #pragma unroll
        for (int h = 0; h < 2; h++) {
            int r = wm + mt * 16 + h * 8 + frl;
            #pragma unroll
            for (int nt = 0; nt < 4; nt++) {
                int c = wn + nt * 8 + (lane & 3) * 2;
                float2 xr = *(const float2*)(xbase + (size_t)r * D_MODEL + c);
                float2 ov = make_float2(acc_c[mt][nt][h * 2] + xr.x,
                                        acc_c[mt][nt][h * 2 + 1] + xr.y);
                *(float2*)(obase + (size_t)r * D_MODEL + c) = ov;
            }
        }
}

// ---------------- launch ----------------
extern "C" void kernel_launch(void* const* d_in, const int* in_sizes, int n_in,
                              void* d_out, int out_size) {
    const float* x     = (const float*)d_in[0];
    const float* ln1_g = (const float*)d_in[1];
    const float* ln1_b = (const float*)d_in[2];
    const float* wq    = (const float*)d_in[3];
    const float* bq    = (const float*)d_in[4];
    const float* wk    = (const float*)d_in[5];
    const float* bk    = (const float*)d_in[6];
    const float* wv    = (const float*)d_in[7];
    const float* bv    = (const float*)d_in[8];
    const float* ln2_g = (const float*)d_in[9];
    const float* ln2_b = (const float*)d_in[10];
    const float* w1    = (const float*)d_in[11];
    const float* b1    = (const float*)d_in[12];
    const float* w2    = (const float*)d_in[13];
    const float* b2    = (const float*)d_in[14];

    float* out  = (float*)d_out;
    float* attn = out + (size_t)BATCH * SEQ * D_MODEL;

    float *h, *q, *k, *v, *vT, *o1, *h2, *ff, *wqkv, *w1r, *w2r, *stm, *stl, *rst;
    cudaGetSymbolAddress((void**)&h,    g_h);
    cudaGetSymbolAddress((void**)&q,    g_q);
    cudaGetSymbolAddress((void**)&k,    g_k);
    cudaGetSymbolAddress((void**)&v,    g_v);
    cudaGetSymbolAddress((void**)&vT,   g_vT);
    cudaGetSymbolAddress((void**)&o1,   g_o1);
    cudaGetSymbolAddress((void**)&h2,   g_h2);
    cudaGetSymbolAddress((void**)&ff,   g_ff);
    cudaGetSymbolAddress((void**)&wqkv, g_wqkv);
    cudaGetSymbolAddress((void**)&w1r,  g_w1r);
    cudaGetSymbolAddress((void**)&w2r,  g_w2r);
    cudaGetSymbolAddress((void**)&stm,  g_stm);
    cudaGetSymbolAddress((void**)&stl,  g_stl);
    cudaGetSymbolAddress((void**)&rst,  g_rst);

    dim3 blk(256);
    const int N4_1M = D_MODEL * D_MODEL / 4;      // 262144
    const int N4_4M = D_FF * D_MODEL / 4;         // 1048576
    const int SM_P4 = 4 * 4096 * 4;               // 65536 bytes (MODE 0)
    const int SM_CTX = 24576 * 4;                 // 98304 bytes (attn_ctx)

    cudaFuncSetAttribute(gemm_mma<0, 1, 0, 8, 1>, cudaFuncAttributeMaxDynamicSharedMemorySize, SM_P4);
    cudaFuncSetAttribute(gemm_mma<0, 0, 2, 8, 0>, cudaFuncAttributeMaxDynamicSharedMemorySize, SM_P4);
    cudaFuncSetAttribute(gemm_mma<0, 0, 0, 8, 0>, cudaFuncAttributeMaxDynamicSharedMemorySize, SM_P4);
    cudaFuncSetAttribute(attn_ctx, cudaFuncAttributeMaxDynamicSharedMemorySize, SM_CTX);

    // 0) pre-round weights into scratch (permuted tf32 layout)
    round_copy<<<(N4_1M + 255) / 256, 256>>>((const float4*)wq, wqkv, N4_1M);
    round_copy<<<(N4_1M + 255) / 256, 256>>>((const float4*)wk, wqkv + D_MODEL * D_MODEL, N4_1M);
    round_copy<<<(N4_1M + 255) / 256, 256>>>((const float4*)wv, wqkv + 2 * D_MODEL * D_MODEL, N4_1M);
    round_copy<<<(N4_4M + 255) / 256, 256>>>((const float4*)w1, w1r, N4_4M);
    round_copy<<<(N4_4M + 255) / 256, 256>>>((const float4*)w2, w2r, N4_4M);

    // 1) LN1 (rounded, permuted output)
    ln_kernel<<<M_TOK, 256>>>(x, ln1_g, ln1_b, h);

    // 2) fused QKV: [4096,3072] = h @ wqkv^T; q/k/v rounded + permuted
    gemm_mma<0, 1, 0, 8, 1><<<dim3(24, 32, 1), blk, SM_P4>>>(h, wqkv, q, bq, nullptr, k, v, bk, bv,
        nullptr, nullptr, nullptr,
        M_TOK, 3 * D_MODEL, D_MODEL, D_MODEL, D_MODEL, D_MODEL, 1.f, 0, 1, 0,0,0,0,0,0);

    // 3) V transpose (permuted in -> permuted out)
    transpose_v<<<dim3(32, 2, BATCH * N_HEADS), dim3(32, 8)>>>(v, vT);

    // 4) scores stats only: per-(tile,row) max + sumexp of s = qk^T/8 (no big write)
    gemm_mma<0, 0, 2, 8, 0><<<dim3(8, 8, N_HEADS * BATCH), blk, SM_P4>>>(q, k, attn, nullptr, nullptr,
        nullptr, nullptr, nullptr, nullptr,
        nullptr, stm, stl,
        SEQ, SEQ, D_HEAD, D_MODEL, D_MODEL, SEQ, 0.125f, 0, BATCH,
        (long long)SEQ * D_MODEL, 64,
        (long long)SEQ * D_MODEL, 64,
        (long long)SEQ * SEQ, (long long)BATCH * SEQ * SEQ);

    // 5) combine per-tile stats -> per-row (m, 1/l)
    stat_combine<<<256, 256>>>(stm, stl, (float2*)rst);

    // 6) fused ctx: recompute S, write final P, ctx = P @ vT^T + x -> o1
    attn_ctx<<<dim3(8, 64), blk, SM_CTX>>>(q, k, vT, (const float2*)rst, attn, x, o1);

    // 7) LN2 (rounded, permuted output)
    ln_kernel<<<M_TOK, 256>>>(o1, ln2_g, ln2_b, h2);

    // 8) FFN1: relu(h2 @ w1^T + b1), rounded + permuted output
    gemm_mma<0, 1, 0, 8, 1><<<dim3(32, 32, 1), blk, SM_P4>>>(h2, w1r, ff, b1, nullptr,
        nullptr, nullptr, nullptr, nullptr,
        nullptr, nullptr, nullptr,
        M_TOK, D_FF, D_MODEL, D_MODEL, D_MODEL, D_FF, 1.f, 1, 1, 0,0,0,0,0,0);

    // 9) FFN2: ff @ w2^T + b2 + o1 -> final out (standard layout)
    gemm_mma<0, 0, 0, 8, 0><<<dim3(8, 32, 1), blk, SM_P4>>>(ff, w2r, out, b2, o1,
        nullptr, nullptr, nullptr, nullptr,
        nullptr, nullptr, nullptr,
        M_TOK, D_MODEL, D_FF, D_FF, D_FF, D_MODEL, 1.f, 0, 1, 0,0,0,0,0,0);
}

// round 14
// speedup vs baseline: 1.9700x; 1.7926x over previous
#include <cuda_runtime.h>
#include <cuda_fp16.h>
#include <cstdint>

#define D_MODEL 1024
#define N_HEADS 16
#define D_HEAD  64
#define D_FF    4096
#define BATCH   4
#define SEQ     1024
#define M_TOK   (BATCH*SEQ)   // 4096

// ---------------- scratch (allocation-free: device globals) ----------------
__device__ __half g_h   [M_TOK*D_MODEL];
__device__ __half g_q   [M_TOK*D_MODEL];
__device__ __half g_k   [M_TOK*D_MODEL];
__device__ __half g_v   [M_TOK*D_MODEL];
__device__ __half g_vT  [M_TOK*D_MODEL];
__device__ __half g_h2  [M_TOK*D_MODEL];
__device__ __half g_ff  [M_TOK*D_FF];
__device__ __half g_wqkv[3*D_MODEL*D_MODEL];
__device__ __half g_w1r [D_FF*D_MODEL];
__device__ __half g_w2r [D_MODEL*D_FF];
__device__ float  g_o1  [M_TOK*D_MODEL];
__device__ float  g_stm [64*8*1024];
__device__ float  g_stl [64*8*1024];
__device__ float  g_rst [64*1024*2];     // per-(z,row): (m, 1/l)

// ---------------- helpers ----------------
__device__ __forceinline__ uint32_t pack_h2(float a, float b) {
    __half2 h = __floats2half2_rn(a, b);
    return reinterpret_cast<uint32_t&>(h);
}

__device__ __forceinline__ uint32_t smem_u32(const void* p) {
    uint32_t a;
    asm("{ .reg .u64 t; cvta.to.shared.u64 t, %1; cvt.u32.u64 %0, t; }" : "=r"(a) : "l"(p));
    return a;
}

__device__ __forceinline__ void cp_async16(uint32_t saddr, const void* gptr) {
    asm volatile("cp.async.cg.shared.global [%0], [%1], 16;" :: "r"(saddr), "l"(gptr) : "memory");
}
__device__ __forceinline__ void cp_commit() {
    asm volatile("cp.async.commit_group;" ::: "memory");
}
__device__ __forceinline__ void cp_wait0() {
    asm volatile("cp.async.wait_group 0;" ::: "memory");
}
__device__ __forceinline__ void cp_wait1() {
    asm volatile("cp.async.wait_group 1;" ::: "memory");
}
__device__ __forceinline__ void cp_wait2() {
    asm volatile("cp.async.wait_group 2;" ::: "memory");
}

__device__ __forceinline__ void mma_f16(float* c, uint32_t a0, uint32_t a1, uint32_t a2, uint32_t a3,
                                        uint32_t b0, uint32_t b1) {
    asm volatile(
        "mma.sync.aligned.m16n8k16.row.col.f32.f16.f16.f32 "
        "{%0,%1,%2,%3}, {%4,%5,%6,%7}, {%8,%9}, {%0,%1,%2,%3};\n"
        : "+f"(c[0]), "+f"(c[1]), "+f"(c[2]), "+f"(c[3])
        : "r"(a0), "r"(a1), "r"(a2), "r"(a3), "r"(b0), "r"(b1));
}

// physical half position of logical half k inside its 32-half block:
// hu = (k&31)>>1; pos_h2 = 4*(hu&3) + (hu>>2); pos = 2*pos_h2 + (k&1)
__device__ __forceinline__ int permh(int k) {
    int k5 = k & 31, hu = k5 >> 1;
    return (k & ~31) + 2 * (4 * (hu & 3) + (hu >> 2)) + (k5 & 1);
}

// ---------------- round-to-fp16 copy, PERMUTED output --------------------------
// thread i handles 8 consecutive floats (k = 8i..8i+7); blk = i>>2, jj = i&3;
// half2 pair m (m=0..3) -> physical h2 index 16*blk + 4*m + jj.
__global__ void round_copy_h(const float4* __restrict__ src, uint32_t* __restrict__ dsth2, int n8) {
    int i = blockIdx.x * blockDim.x + threadIdx.x;
    if (i < n8) {
        float4 va = src[2 * i], vb = src[2 * i + 1];
        uint32_t* p = dsth2 + (size_t)(i >> 2) * 16 + (i & 3);
        p[0]  = pack_h2(va.x, va.y);
        p[4]  = pack_h2(va.z, va.w);
        p[8]  = pack_h2(vb.x, vb.y);
        p[12] = pack_h2(vb.z, vb.w);
    }
}

// ---------------- LayerNorm; fp16 + PERMUTED output ----------------------------
__global__ void ln_kernel(const float* __restrict__ x, const float* __restrict__ g,
                          const float* __restrict__ b, uint32_t* __restrict__ outh2) {
    int row = blockIdx.x;
    int t = threadIdx.x;  // 256 threads, 4 floats each
    const float4* xr = (const float4*)(x + (size_t)row * D_MODEL);
    float4 v = xr[t];
    __shared__ float red[8];

    float s = v.x + v.y + v.z + v.w;
    #pragma unroll
    for (int o = 16; o; o >>= 1) s += __shfl_xor_sync(0xffffffffu, s, o);
    if ((t & 31) == 0) red[t >> 5] = s;
    __syncthreads();
    float tot = red[0]+red[1]+red[2]+red[3]+red[4]+red[5]+red[6]+red[7];
    float mean = tot * (1.0f / D_MODEL);

    float dx = v.x - mean, dy = v.y - mean, dz = v.z - mean, dw = v.w - mean;
    float ss = dx*dx + dy*dy + dz*dz + dw*dw;
    #pragma unroll
    for (int o = 16; o; o >>= 1) ss += __shfl_xor_sync(0xffffffffu, ss, o);
    __syncthreads();
    if ((t & 31) == 0) red[t >> 5] = ss;
    __syncthreads();
    float vtot = red[0]+red[1]+red[2]+red[3]+red[4]+red[5]+red[6]+red[7];
    float inv = 1.0f / (sqrtf(vtot * (1.0f / (D_MODEL - 1))) + 1e-12f);

    float4 g4 = ((const float4*)g)[t];
    float4 b4 = ((const float4*)b)[t];
    float o0 = g4.x * dx * inv + b4.x;
    float o1v = g4.y * dy * inv + b4.y;
    float o2 = g4.z * dz * inv + b4.z;
    float o3 = g4.w * dw * inv + b4.w;

    // floats 4t..4t+3: group s = t>>1 (8 floats), jj = s&3, blk = s>>2, odd = t&1
    int s5 = (t >> 1) & 3, blk = t >> 3, odd = t & 1;
    uint32_t* p = outh2 + (size_t)row * 512 + blk * 16 + 8 * odd + s5;
    p[0] = pack_h2(o0, o1v);
    p[4] = pack_h2(o2, o3);
}

// ---------------- V transpose: v (half, permuted) -> vT (half, permuted) -------
__global__ void transpose_v(const __half* __restrict__ v, __half* __restrict__ vT) {
    __shared__ __half tile[32][33];
    int bh = blockIdx.z;             // b*H + h
    int b = bh / N_HEADS, h = bh % N_HEADS;
    int s0 = blockIdx.x * 32;
    int d0 = blockIdx.y * 32;
    int tx = threadIdx.x, ty = threadIdx.y;  // 32 x 8
    const __half* src = v + ((size_t)b * SEQ) * D_MODEL;
    int pc = permh(h * D_HEAD + d0 + tx);
    #pragma unroll
    for (int i = 0; i < 32; i += 8)
        tile[ty + i][tx] = src[(size_t)(s0 + ty + i) * D_MODEL + pc];
    __syncthreads();
    __half* dst = vT + ((size_t)bh * D_HEAD) * SEQ;
    int ps = permh(s0 + tx);
    #pragma unroll
    for (int i = 0; i < 32; i += 8)
        dst[(size_t)(d0 + ty + i) * SEQ + ps] = tile[tx][ty + i];
}

// ---------------- stat combine: (m_t, l_t) x8 -> per-row (m, 1/l) --------------
__global__ void stat_combine(const float* __restrict__ stm, const float* __restrict__ stl,
                             float2* __restrict__ rst) {
    int i = blockIdx.x * blockDim.x + threadIdx.x;   // z*1024 + row, 65536 total
    int z = i >> 10, row = i & 1023;
    const float* pm = stm + (size_t)z * 8 * 1024 + row;
    const float* pl = stl + (size_t)z * 8 * 1024 + row;
    float mv[8];
    float m = -1e30f;
    #pragma unroll
    for (int t = 0; t < 8; t++) { mv[t] = pm[t * 1024]; m = fmaxf(m, mv[t]); }
    float l = 0.f;
    #pragma unroll
    for (int t = 0; t < 8; t++) l += pl[t * 1024] * __expf(mv[t] - m);
    rst[i] = make_float2(m, 1.0f / l);
}

// ---------------- fp16 mma.sync GEMM (cp.async 4-stage, permuted fp16 gmem) ----
// C = scale*(A[M,K] @ B[N,K]^T) (+bias)(+res)(relu).  BK = 32 halves.
// STATS: 0 = normal; 2 = stats-only (row-tile max + sumexp -> stm/stl, no C write).
// PERM_OUT: C is __half (permuted layout). QKV select when Ck != null.
// Warp grid 4x2, warp tile 32x64, CTA tile 128x128. Smem stage = 4096 words.
template<int STATS, int PERM_OUT>
__global__ void __launch_bounds__(256, 2)
gemm_f16(const __half* __restrict__ A, const __half* __restrict__ B,
         float* __restrict__ C, const float* __restrict__ bias, const float* __restrict__ res,
         __half* __restrict__ Ck, __half* __restrict__ Cv,
         const float* __restrict__ biask, const float* __restrict__ biasv,
         float* __restrict__ stm, float* __restrict__ stl,
         int M, int N, int K, int lda, int ldb, int ldc,
         float scale, int relu, int zmod,
         long long aLo, long long aHi, long long bLo, long long bHi,
         long long cLo, long long cHi)
{
    extern __shared__ __align__(16) uint32_t sm[];

    int z = blockIdx.z;
    int zlo = z % zmod, zhi = z / zmod;
    A += (size_t)zlo * aLo + (size_t)zhi * aHi;
    B += (size_t)zlo * bLo + (size_t)zhi * bHi;
    size_t coff = (size_t)zlo * cLo + (size_t)zhi * cHi;
    C += coff;
    if (res) res += coff;

    const int tid = threadIdx.x, lane = tid & 31, warp = tid >> 5;
    const int wm = (warp & 3) * 32, wn = (warp >> 2) * 64;
    const int m0 = blockIdx.y * 128, n0 = blockIdx.x * 128;

    const int ft = lane & 3, frl = lane >> 2;
    const int fu = ft ^ ((frl >> 1) & 3);
    const uint32_t ldAw = (uint32_t)((wm + frl) * 16 + 4 * fu);
    const uint32_t ldBw = (uint32_t)(2048 + (wn + frl) * 16 + 4 * fu);

    float acc[2][8][4];
    #pragma unroll
    for (int i = 0; i < 2; i++)
        #pragma unroll
        for (int j = 0; j < 8; j++)
            #pragma unroll
            for (int c = 0; c < 4; c++) acc[i][j][c] = 0.f;

    const int nk = K / 32;

    auto compute_at = [&](const uint32_t* base) {
        uint4 af[2][2];
        #pragma unroll
        for (int mt = 0; mt < 2; mt++)
            #pragma unroll
            for (int h = 0; h < 2; h++)
                af[mt][h] = *(const uint4*)&base[ldAw + mt * 256 + h * 128];
        #pragma unroll
        for (int nt = 0; nt < 8; nt++) {
            uint4 bf = *(const uint4*)&base[ldBw + nt * 128];
            #pragma unroll
            for (int mt = 0; mt < 2; mt++) {
                mma_f16(acc[mt][nt], af[mt][0].x, af[mt][1].x, af[mt][0].y, af[mt][1].y,
                        bf.x, bf.y);
                mma_f16(acc[mt][nt], af[mt][0].z, af[mt][1].z, af[mt][0].w, af[mt][1].w,
                        bf.z, bf.w);
            }
        }
    };

    {
        const uint32_t smem_base = smem_u32(sm);
        uint32_t saw[2], sbw[2];
        const __half *ga[2], *gb[2];
        #pragma unroll
        for (int j = 0; j < 2; j++) {
            int id = tid + 256 * j;
            int r = id >> 2, u = id & 3;
            int up = u ^ ((r >> 1) & 3);
            saw[j] = (uint32_t)((r * 16 + 4 * up) * 4);
            sbw[j] = (uint32_t)((2048 + r * 16 + 4 * up) * 4);
            ga[j] = A + (size_t)(m0 + r) * lda + 8 * u;
            gb[j] = B + (size_t)(n0 + r) * ldb + 8 * u;
        }
        auto issue = [&](int tile, int stg) {
            const int k0 = tile * 32;
            const uint32_t sb = smem_base + (uint32_t)stg * 16384u;
            #pragma unroll
            for (int j = 0; j < 2; j++) cp_async16(sb + saw[j], ga[j] + k0);
            #pragma unroll
            for (int j = 0; j < 2; j++) cp_async16(sb + sbw[j], gb[j] + k0);
            cp_commit();
        };
        issue(0, 0); issue(1, 1); issue(2, 2);
        int st = 0;
        for (int t = 0; t < nk; ++t) {
            cp_wait2();
            __syncthreads();
            compute_at(sm + st * 4096);
            if (t + 3 < nk) issue(t + 3, (st + 3) & 3);
            else            cp_commit();
            st = (st + 1) & 3;
        }
        __syncthreads();
    }

    if (STATS == 2) {
        // ---- stats-only: per-row tile max + sumexp; NO C store ----
        float* smf = (float*)sm;
        const int g = warp >> 2;
        const int rl = lane >> 2;
        float lmax[2][2];
        #pragma unroll
        for (int mt = 0; mt < 2; mt++)
            #pragma unroll
            for (int h = 0; h < 2; h++) {
                float v = -1e30f;
                #pragma unroll
                for (int nt = 0; nt < 8; nt++) {
                    v = fmaxf(v, acc[mt][nt][2 * h]);
                    v = fmaxf(v, acc[mt][nt][2 * h + 1]);
                }
                lmax[mt][h] = v * scale;
            }
        #pragma unroll
        for (int o = 1; o < 4; o <<= 1)
            #pragma unroll
            for (int mt = 0; mt < 2; mt++)
                #pragma unroll
                for (int h = 0; h < 2; h++)
                    lmax[mt][h] = fmaxf(lmax[mt][h], __shfl_xor_sync(0xffffffffu, lmax[mt][h], o));
        __syncthreads();
        if ((lane & 3) == 0)
            #pragma unroll
            for (int mt = 0; mt < 2; mt++)
                #pragma unroll
                for (int h = 0; h < 2; h++)
                    smf[g * 128 + wm + mt * 16 + h * 8 + rl] = lmax[mt][h];
        __syncthreads();
        float rmax[2][2], lsum[2][2];
        #pragma unroll
        for (int mt = 0; mt < 2; mt++)
            #pragma unroll
            for (int h = 0; h < 2; h++) {
                int row = wm + mt * 16 + h * 8 + rl;
                rmax[mt][h] = fmaxf(smf[row], smf[128 + row]);
                lsum[mt][h] = 0.f;
            }
        #pragma unroll
        for (int mt = 0; mt < 2; ++mt)
            #pragma unroll
            for (int nt = 0; nt < 8; ++nt)
                #pragma unroll
                for (int h = 0; h < 2; ++h) {
                    lsum[mt][h] += __expf(acc[mt][nt][2 * h]     * scale - rmax[mt][h]);
                    lsum[mt][h] += __expf(acc[mt][nt][2 * h + 1] * scale - rmax[mt][h]);
                }
        #pragma unroll
        for (int o = 1; o < 4; o <<= 1)
            #pragma unroll
            for (int mt = 0; mt < 2; mt++)
                #pragma unroll
                for (int h = 0; h < 2; h++)
                    lsum[mt][h] += __shfl_xor_sync(0xffffffffu, lsum[mt][h], o);
        if ((lane & 3) == 0)
            #pragma unroll
            for (int mt = 0; mt < 2; mt++)
                #pragma unroll
                for (int h = 0; h < 2; h++)
                    smf[256 + g * 128 + wm + mt * 16 + h * 8 + rl] = lsum[mt][h];
        __syncthreads();
        if (g == 0 && (lane & 3) == 0) {
            #pragma unroll
            for (int mt = 0; mt < 2; mt++)
                #pragma unroll
                for (int h = 0; h < 2; h++) {
                    int row = wm + mt * 16 + h * 8 + rl;
                    size_t idx = ((size_t)z * 8 + blockIdx.x) * 1024 + m0 + row;
                    stm[idx] = rmax[mt][h];
                    stl[idx] = smf[256 + row] + smf[384 + row];
                }
        }
    } else {
        // ---- normal epilogue (QKV 3-way select; fp16-permuted or fp32 C) ----
        void* Cp = (void*)C; const float* bp = bias; int noff = 0;
        if (Ck) {
            if (n0 >= 2048)      { Cp = (void*)Cv; bp = biasv; noff = 2048; }
            else if (n0 >= 1024) { Cp = (void*)Ck; bp = biask; noff = 1024; }
        }
        #pragma unroll
        for (int mt = 0; mt < 2; ++mt) {
            #pragma unroll
            for (int nt = 0; nt < 8; ++nt) {
                int rbase = m0 + wm + mt * 16 + (lane >> 2);
                int cbase = n0 + wn + nt * 8 + (lane & 3) * 2;
                #pragma unroll
                for (int h = 0; h < 2; ++h) {
                    int rr = rbase + h * 8;
                    int cl = cbase - noff;
                    float v0 = acc[mt][nt][h * 2 + 0] * scale;
                    float v1 = acc[mt][nt][h * 2 + 1] * scale;
                    if (bp)  { float2 bb = *(const float2*)(bp + cl); v0 += bb.x; v1 += bb.y; }
                    if (res) { float2 r2 = *(const float2*)(res + (size_t)rr * ldc + cl); v0 += r2.x; v1 += r2.y; }
                    if (relu) { v0 = fmaxf(v0, 0.f); v1 = fmaxf(v1, 0.f); }
                    if (PERM_OUT) {
                        int blk = cl >> 5, hu5 = (cl & 31) >> 1;
                        int p = 16 * blk + 4 * (hu5 & 3) + (hu5 >> 2);
                        ((uint32_t*)Cp)[(size_t)rr * (ldc >> 1) + p] = pack_h2(v0, v1);
                    } else {
                        *(float2*)((float*)Cp + (size_t)rr * ldc + cl) = make_float2(v0, v1);
                    }
                }
            }
        }
    }
}

// ---------------- fused attention ctx (fp16 MMAs) ----------------------------------
// Per CTA: z, 128-row q block; 16 column tiles of 64 k-positions.
// S = q @ kt^T; p = __expf(s/8 - m)*invl; P -> gmem fp32 (final attn) and smem fp16;
// ctx += P @ vt^T; epilogue o1 = ctx + x.
// smem words: q[0,4096) kt[4096,6144) vt[6144,8192) P[8192,12288) = 48KB.
__global__ void __launch_bounds__(256, 2)
attn_ctx(const __half* __restrict__ q, const __half* __restrict__ k,
         const __half* __restrict__ vT, const float2* __restrict__ rst,
         float* __restrict__ attn, const float* __restrict__ x,
         float* __restrict__ o1)
{
    extern __shared__ __align__(16) uint32_t sm[];
    constexpr int QW = 0, KW = 4096, VW = 6144, PWo = 8192;
    constexpr int NJ = 16;

    const int tid = threadIdx.x, lane = tid & 31, warp = tid >> 5;
    const int wm = (warp & 3) * 32, wn = (warp >> 2) * 32;
    const int ft = lane & 3, frl = lane >> 2;
    const int zz = blockIdx.y;           // h*4 + b
    const int b = zz & 3, hh = zz >> 2;
    const int m0 = blockIdx.x * 128;

    const __half* qbase = q + ((size_t)b * SEQ + m0) * D_MODEL + hh * 64;
    const __half* kbase = k + (size_t)b * SEQ * D_MODEL + hh * 64;
    const __half* vbase = vT + (size_t)(b * N_HEADS + hh) * 64 * SEQ;
    float* pbase = attn + (size_t)zz * SEQ * SEQ + (size_t)m0 * SEQ;
    const float* xbase = x + ((size_t)b * SEQ + m0) * D_MODEL + hh * 64;
    float* obase = o1 + ((size_t)b * SEQ + m0) * D_MODEL + hh * 64;

    const uint32_t smb = smem_u32(sm);

    // row = 64 halves = 8 units of 16B (32 words); slot = (u + 4*(r&1)) & 7
    auto swaddr = [](int r, int u) {
        return r * 32 + 4 * ((u + ((r & 1) << 2)) & 7);
    };

    auto load_q = [&]() {
        #pragma unroll
        for (int j = 0; j < 4; j++) {
            int g = tid + 256 * j;
            int r = g >> 3, u = g & 7;
            cp_async16(smb + 4 * (QW + swaddr(r, u)), qbase + (size_t)r * D_MODEL + 8 * u);
        }
    };
    auto load_k = [&](int jt) {
        #pragma unroll
        for (int j = 0; j < 2; j++) {
            int g = tid + 256 * j;
            int r = g >> 3, u = g & 7;
            cp_async16(smb + 4 * (KW + swaddr(r, u)),
                       kbase + (size_t)(jt * 64 + r) * D_MODEL + 8 * u);
        }
    };
    auto load_v = [&](int jt) {
        #pragma unroll
        for (int j = 0; j < 2; j++) {
            int g = tid + 256 * j;
            int r = g >> 3, u = g & 7;
            cp_async16(smb + 4 * (VW + swaddr(r, u)),
                       vbase + (size_t)r * SEQ + jt * 64 + 8 * u);
        }
    };

    float2 st[2][2];
    #pragma unroll
    for (int mt = 0; mt < 2; mt++)
        #pragma unroll
        for (int h = 0; h < 2; h++)
            st[mt][h] = rst[(size_t)zz * 1024 + m0 + wm + mt * 16 + h * 8 + frl];

    float acc_c[2][4][4];
    #pragma unroll
    for (int i = 0; i < 2; i++)
        #pragma unroll
        for (int j = 0; j < 4; j++)
            #pragma unroll
            for (int c = 0; c < 4; c++) acc_c[i][j][c] = 0.f;

    load_q(); load_k(0); cp_commit();     // group: {q, kt0}
    load_v(0); cp_commit();               // group: {vt0}

    for (int jt = 0; jt < NJ; ++jt) {
        float acc_s[2][4][4];
        #pragma unroll
        for (int i = 0; i < 2; i++)
            #pragma unroll
            for (int j = 0; j < 4; j++)
                #pragma unroll
                for (int c = 0; c < 4; c++) acc_s[i][j][c] = 0.f;

        cp_wait1();          // q + kt ready
        __syncthreads();

        // S = q @ kt^T  (2 blocks of k32 each -> 2 mma k16-steps per block)
        #pragma unroll
        for (int kb = 0; kb < 2; kb++) {
            uint4 af[2][2];
            #pragma unroll
            for (int mt = 0; mt < 2; mt++)
                #pragma unroll
                for (int h = 0; h < 2; h++)
                    af[mt][h] = *(const uint4*)&sm[QW + swaddr(wm + mt * 16 + h * 8 + frl, 4 * kb + ft)];
            #pragma unroll
            for (int nt = 0; nt < 4; nt++) {
                uint4 bf = *(const uint4*)&sm[KW + swaddr(wn + nt * 8 + frl, 4 * kb + ft)];
                #pragma unroll
                for (int mt = 0; mt < 2; mt++) {
                    mma_f16(acc_s[mt][nt], af[mt][0].x, af[mt][1].x, af[mt][0].y, af[mt][1].y,
                            bf.x, bf.y);
                    mma_f16(acc_s[mt][nt], af[mt][0].z, af[mt][1].z, af[mt][0].w, af[mt][1].w,
                            bf.z, bf.w);
                }
            }
        }

        // transform S -> P (in place) and stage P (fp16) into smem
        #pragma unroll
        for (int mt = 0; mt < 2; mt++) {
            #pragma unroll
            for (int h = 0; h < 2; h++) {
                int r = wm + mt * 16 + h * 8 + frl;
                int rot = (r & 1) << 2;
                float mrow = st[mt][h].x, invl = st[mt][h].y;
                #pragma unroll
                for (int nt = 0; nt < 4; nt++) {
                    float p0 = __expf(acc_s[mt][nt][h * 2 + 0] * 0.125f - mrow) * invl;
                    float p1 = __expf(acc_s[mt][nt][h * 2 + 1] * 0.125f - mrow) * invl;
                    acc_s[mt][nt][h * 2 + 0] = p0;
                    acc_s[mt][nt][h * 2 + 1] = p1;
                    int c = wn + nt * 8 + (lane & 3) * 2;
                    int blk = c >> 5, hu5 = (c & 31) >> 1;
                    int ul = 4 * blk + (hu5 & 3), sub = hu5 >> 2;
                    sm[PWo + r * 32 + 4 * ((ul + rot) & 7) + sub] = pack_h2(p0, p1);
                }
            }
        }

        cp_wait0();          // vt ready
        __syncthreads();     // P visible; kt consumed
        if (jt + 1 < NJ) load_k(jt + 1);
        cp_commit();

        // ctx += P @ vt^T
        #pragma unroll
        for (int kb = 0; kb < 2; kb++) {
            uint4 af[2][2];
            #pragma unroll
            for (int mt = 0; mt < 2; mt++)
                #pragma unroll
                for (int h = 0; h < 2; h++)
                    af[mt][h] = *(const uint4*)&sm[PWo + swaddr(wm + mt * 16 + h * 8 + frl, 4 * kb + ft)];
            #pragma unroll
            for (int nt = 0; nt < 4; nt++) {
                uint4 bf = *(const uint4*)&sm[VW + swaddr(wn + nt * 8 + frl, 4 * kb + ft)];
                #pragma unroll
                for (int mt = 0; mt < 2; mt++) {
                    mma_f16(acc_c[mt][nt], af[mt][0].x, af[mt][1].x, af[mt][0].y, af[mt][1].y,
                            bf.x, bf.y);
                    mma_f16(acc_c[mt][nt], af[mt][0].z, af[mt][1].z, af[mt][0].w, af[mt][1].w,
                            bf.z, bf.w);
                }
            }
        }

        // write final P (fp32) to gmem
        #pragma unroll
        for (int mt = 0; mt < 2; mt++)
            #pragma unroll
            for (int h = 0; h < 2; h++) {
                int r = wm + mt * 16 + h * 8 + frl;
                float* prow = pbase + (size_t)r * SEQ + jt * 64;
                #pragma unroll
                for (int nt = 0; nt < 4; nt++)
                    *(float2*)(prow + wn + nt * 8 + (lane & 3) * 2) =
                        make_float2(acc_s[mt][nt][h * 2], acc_s[mt][nt][h * 2 + 1]);
            }

        __syncthreads();     // vt and P consumed
        if (jt + 1 < NJ) load_v(jt + 1);
        cp_commit();
    }

    // epilogue: o1 = ctx + x
    #pragma unroll
    for (int mt = 0; mt < 2; mt++)
        #pragma unroll
        for (int h = 0; h < 2; h++) {
            int r = wm + mt * 16 + h * 8 + frl;
            #pragma unroll
            for (int nt = 0; nt < 4; nt++) {
                int c = wn + nt * 8 + (lane & 3) * 2;
                float2 xr = *(const float2*)(xbase + (size_t)r * D_MODEL + c);
                *(float2*)(obase + (size_t)r * D_MODEL + c) =
                    make_float2(acc_c[mt][nt][h * 2] + xr.x, acc_c[mt][nt][h * 2 + 1] + xr.y);
            }
        }
}

// ---------------- launch ----------------
extern "C" void kernel_launch(void* const* d_in, const int* in_sizes, int n_in,
                              void* d_out, int out_size) {
    const float* x     = (const float*)d_in[0];
    const float* ln1_g = (const float*)d_in[1];
    const float* ln1_b = (const float*)d_in[2];
    const float* wq    = (const float*)d_in[3];
    const float* bq    = (const float*)d_in[4];
    const float* wk    = (const float*)d_in[5];
    const float* bk    = (const float*)d_in[6];
    const float* wv    = (const float*)d_in[7];
    const float* bv    = (const float*)d_in[8];
    const float* ln2_g = (const float*)d_in[9];
    const float* ln2_b = (const float*)d_in[10];
    const float* w1    = (const float*)d_in[11];
    const float* b1    = (const float*)d_in[12];
    const float* w2    = (const float*)d_in[13];
    const float* b2    = (const float*)d_in[14];

    float* out  = (float*)d_out;
    float* attn = out + (size_t)BATCH * SEQ * D_MODEL;

    __half *h, *q, *k, *v, *vT, *h2, *ff, *wqkv, *w1r, *w2r;
    float *o1, *stm, *stl, *rst;
    cudaGetSymbolAddress((void**)&h,    g_h);
    cudaGetSymbolAddress((void**)&q,    g_q);
    cudaGetSymbolAddress((void**)&k,    g_k);
    cudaGetSymbolAddress((void**)&v,    g_v);
    cudaGetSymbolAddress((void**)&vT,   g_vT);
    cudaGetSymbolAddress((void**)&h2,   g_h2);
    cudaGetSymbolAddress((void**)&ff,   g_ff);
    cudaGetSymbolAddress((void**)&wqkv, g_wqkv);
    cudaGetSymbolAddress((void**)&w1r,  g_w1r);
    cudaGetSymbolAddress((void**)&w2r,  g_w2r);
    cudaGetSymbolAddress((void**)&o1,   g_o1);
    cudaGetSymbolAddress((void**)&stm,  g_stm);
    cudaGetSymbolAddress((void**)&stl,  g_stl);
    cudaGetSymbolAddress((void**)&rst,  g_rst);

    dim3 blk(256);
    const int N8_1M = D_MODEL * D_MODEL / 8;      // 131072
    const int N8_4M = D_FF * D_MODEL / 8;         // 524288
    const int SM_P4 = 4 * 4096 * 4;               // 65536 bytes
    const int SM_CTX = 12288 * 4;                 // 49152 bytes

    cudaFuncSetAttribute(gemm_f16<0, 1>, cudaFuncAttributeMaxDynamicSharedMemorySize, SM_P4);
    cudaFuncSetAttribute(gemm_f16<2, 0>, cudaFuncAttributeMaxDynamicSharedMemorySize, SM_P4);
    cudaFuncSetAttribute(gemm_f16<0, 0>, cudaFuncAttributeMaxDynamicSharedMemorySize, SM_P4);
    cudaFuncSetAttribute(attn_ctx, cudaFuncAttributeMaxDynamicSharedMemorySize, SM_CTX);

    // 0) weights -> fp16 permuted scratch
    round_copy_h<<<(N8_1M + 255) / 256, 256>>>((const float4*)wq, (uint32_t*)wqkv, N8_1M);
    round_copy_h<<<(N8_1M + 255) / 256, 256>>>((const float4*)wk, (uint32_t*)(wqkv + D_MODEL * D_MODEL), N8_1M);
    round_copy_h<<<(N8_1M + 255) / 256, 256>>>((const float4*)wv, (uint32_t*)(wqkv + 2 * D_MODEL * D_MODEL), N8_1M);
    round_copy_h<<<(N8_4M + 255) / 256, 256>>>((const float4*)w1, (uint32_t*)w1r, N8_4M);
    round_copy_h<<<(N8_4M + 255) / 256, 256>>>((const float4*)w2, (uint32_t*)w2r, N8_4M);

    // 1) LN1 (fp16 permuted output)
    ln_kernel<<<M_TOK, 256>>>(x, ln1_g, ln1_b, (uint32_t*)h);

    // 2) fused QKV: q/k/v fp16 permuted
    gemm_f16<0, 1><<<dim3(24, 32, 1), blk, SM_P4>>>(h, wqkv, (float*)q, bq, nullptr, k, v, bk, bv,
        nullptr, nullptr,
        M_TOK, 3 * D_MODEL, D_MODEL, D_MODEL, D_MODEL, D_MODEL, 1.f, 0, 1, 0,0,0,0,0,0);

    // 3) V transpose (fp16 permuted in/out)
    transpose_v<<<dim3(32, 2, BATCH * N_HEADS), dim3(32, 8)>>>(v, vT);

    // 4) scores stats only (no big write)
    gemm_f16<2, 0><<<dim3(8, 8, N_HEADS * BATCH), blk, SM_P4>>>(q, k, attn, nullptr, nullptr,
        nullptr, nullptr, nullptr, nullptr,
        stm, stl,
        SEQ, SEQ, D_HEAD, D_MODEL, D_MODEL, SEQ, 0.125f, 0, BATCH,
        (long long)SEQ * D_MODEL, 64,
        (long long)SEQ * D_MODEL, 64,
        (long long)SEQ * SEQ, (long long)BATCH * SEQ * SEQ);

    // 5) combine per-tile stats -> per-row (m, 1/l)
    stat_combine<<<256, 256>>>(stm, stl, (float2*)rst);

    // 6) fused ctx: recompute S, write final P (fp32), ctx = P @ vT^T + x -> o1
    attn_ctx<<<dim3(8, 64), blk, SM_CTX>>>(q, k, vT, (const float2*)rst, attn, x, o1);

    // 7) LN2 (fp16 permuted output)
    ln_kernel<<<M_TOK, 256>>>(o1, ln2_g, ln2_b, (uint32_t*)h2);

    // 8) FFN1: relu(h2 @ w1^T + b1) -> fp16 permuted
    gemm_f16<0, 1><<<dim3(32, 32, 1), blk, SM_P4>>>(h2, w1r, (float*)ff, b1, nullptr,
        nullptr, nullptr, nullptr, nullptr,
        nullptr, nullptr,
        M_TOK, D_FF, D_MODEL, D_MODEL, D_MODEL, D_FF, 1.f, 1, 1, 0,0,0,0,0,0);

    // 9) FFN2: ff @ w2^T + b2 + o1 -> final out (fp32)
    gemm_f16<0, 0><<<dim3(8, 32, 1), blk, SM_P4>>>(ff, w2r, out, b2, o1,
        nullptr, nullptr, nullptr, nullptr,
        nullptr, nullptr,
        M_TOK, D_MODEL, D_FF, D_FF, D_FF, D_MODEL, 1.f, 0, 1, 0,0,0,0,0,0);
}

// round 15
// speedup vs baseline: 2.0280x; 1.0295x over previous
#include <cuda_runtime.h>
#include <cuda_fp16.h>
#include <cstdint>

#define D_MODEL 1024
#define N_HEADS 16
#define D_HEAD  64
#define D_FF    4096
#define BATCH   4
#define SEQ     1024
#define M_TOK   (BATCH*SEQ)   // 4096

// ---------------- scratch (allocation-free: device globals) ----------------
__device__ __half g_h   [M_TOK*D_MODEL];
__device__ __half g_q   [M_TOK*D_MODEL];
__device__ __half g_k   [M_TOK*D_MODEL];
__device__ __half g_v   [M_TOK*D_MODEL];
__device__ __half g_vT  [M_TOK*D_MODEL];
__device__ __half g_h2  [M_TOK*D_MODEL];
__device__ __half g_ff  [M_TOK*D_FF];
__device__ __half g_wqkv[3*D_MODEL*D_MODEL];
__device__ __half g_w1r [D_FF*D_MODEL];
__device__ __half g_w2r [D_MODEL*D_FF];
__device__ float  g_o1  [M_TOK*D_MODEL];
__device__ float  g_stm [64*8*1024];
__device__ float  g_stl [64*8*1024];

// ---------------- helpers ----------------
__device__ __forceinline__ uint32_t pack_h2(float a, float b) {
    __half2 h = __floats2half2_rn(a, b);
    return reinterpret_cast<uint32_t&>(h);
}

__device__ __forceinline__ uint32_t smem_u32(const void* p) {
    uint32_t a;
    asm("{ .reg .u64 t; cvta.to.shared.u64 t, %1; cvt.u32.u64 %0, t; }" : "=r"(a) : "l"(p));
    return a;
}

__device__ __forceinline__ void cp_async16(uint32_t saddr, const void* gptr) {
    asm volatile("cp.async.cg.shared.global [%0], [%1], 16;" :: "r"(saddr), "l"(gptr) : "memory");
}
__device__ __forceinline__ void cp_commit() {
    asm volatile("cp.async.commit_group;" ::: "memory");
}
__device__ __forceinline__ void cp_wait0() {
    asm volatile("cp.async.wait_group 0;" ::: "memory");
}
__device__ __forceinline__ void cp_wait1() {
    asm volatile("cp.async.wait_group 1;" ::: "memory");
}
__device__ __forceinline__ void cp_wait2() {
    asm volatile("cp.async.wait_group 2;" ::: "memory");
}

__device__ __forceinline__ void mma_f16(float* c, uint32_t a0, uint32_t a1, uint32_t a2, uint32_t a3,
                                        uint32_t b0, uint32_t b1) {
    asm volatile(
        "mma.sync.aligned.m16n8k16.row.col.f32.f16.f16.f32 "
        "{%0,%1,%2,%3}, {%4,%5,%6,%7}, {%8,%9}, {%0,%1,%2,%3};\n"
        : "+f"(c[0]), "+f"(c[1]), "+f"(c[2]), "+f"(c[3])
        : "r"(a0), "r"(a1), "r"(a2), "r"(a3), "r"(b0), "r"(b1));
}

// physical half position of logical half k inside its 32-half block:
// hu = (k&31)>>1; pos_h2 = 4*(hu&3) + (hu>>2); pos = 2*pos_h2 + (k&1)
__device__ __forceinline__ int permh(int k) {
    int k5 = k & 31, hu = k5 >> 1;
    return (k & ~31) + 2 * (4 * (hu & 3) + (hu >> 2)) + (k5 & 1);
}

// ---------------- merged weight round+permute: 5 tensors in one launch ----------
// flat i over 1441792 groups of 8 floats. Ranges:
//  [0,131072) wq -> wqkv     [131072,262144) wk -> wqkv+524288(h2)
//  [262144,393216) wv -> wqkv+1048576    [393216,917504) w1 -> w1r
//  [917504,1441792) w2 -> w2r
__global__ void round_all(const float4* __restrict__ wq, const float4* __restrict__ wk,
                          const float4* __restrict__ wv, const float4* __restrict__ w1,
                          const float4* __restrict__ w2,
                          uint32_t* __restrict__ dqkv, uint32_t* __restrict__ dw1,
                          uint32_t* __restrict__ dw2) {
    int i = blockIdx.x * blockDim.x + threadIdx.x;
    const float4* src; uint32_t* dst; int idx;
    if (i < 131072)       { src = wq; dst = dqkv;           idx = i; }
    else if (i < 262144)  { src = wk; dst = dqkv + 524288;  idx = i - 131072; }
    else if (i < 393216)  { src = wv; dst = dqkv + 1048576; idx = i - 262144; }
    else if (i < 917504)  { src = w1; dst = dw1;            idx = i - 393216; }
    else                  { src = w2; dst = dw2;            idx = i - 917504; }
    float4 va = src[2 * idx], vb = src[2 * idx + 1];
    uint32_t* p = dst + (size_t)(idx >> 2) * 16 + (idx & 3);
    p[0]  = pack_h2(va.x, va.y);
    p[4]  = pack_h2(va.z, va.w);
    p[8]  = pack_h2(vb.x, vb.y);
    p[12] = pack_h2(vb.z, vb.w);
}

// ---------------- LayerNorm; fp16 + PERMUTED output ----------------------------
__global__ void ln_kernel(const float* __restrict__ x, const float* __restrict__ g,
                          const float* __restrict__ b, uint32_t* __restrict__ outh2) {
    int row = blockIdx.x;
    int t = threadIdx.x;  // 256 threads, 4 floats each
    const float4* xr = (const float4*)(x + (size_t)row * D_MODEL);
    float4 v = xr[t];
    __shared__ float red[8];

    float s = v.x + v.y + v.z + v.w;
    #pragma unroll
    for (int o = 16; o; o >>= 1) s += __shfl_xor_sync(0xffffffffu, s, o);
    if ((t & 31) == 0) red[t >> 5] = s;
    __syncthreads();
    float tot = red[0]+red[1]+red[2]+red[3]+red[4]+red[5]+red[6]+red[7];
    float mean = tot * (1.0f / D_MODEL);

    float dx = v.x - mean, dy = v.y - mean, dz = v.z - mean, dw = v.w - mean;
    float ss = dx*dx + dy*dy + dz*dz + dw*dw;
    #pragma unroll
    for (int o = 16; o; o >>= 1) ss += __shfl_xor_sync(0xffffffffu, ss, o);
    __syncthreads();
    if ((t & 31) == 0) red[t >> 5] = ss;
    __syncthreads();
    float vtot = red[0]+red[1]+red[2]+red[3]+red[4]+red[5]+red[6]+red[7];
    float inv = 1.0f / (sqrtf(vtot * (1.0f / (D_MODEL - 1))) + 1e-12f);

    float4 g4 = ((const float4*)g)[t];
    float4 b4 = ((const float4*)b)[t];
    float o0 = g4.x * dx * inv + b4.x;
    float o1v = g4.y * dy * inv + b4.y;
    float o2 = g4.z * dz * inv + b4.z;
    float o3 = g4.w * dw * inv + b4.w;

    int s5 = (t >> 1) & 3, blk = t >> 3, odd = t & 1;
    uint32_t* p = outh2 + (size_t)row * 512 + blk * 16 + 8 * odd + s5;
    p[0] = pack_h2(o0, o1v);
    p[4] = pack_h2(o2, o3);
}

// ---------------- V transpose: v (half, permuted) -> vT (half, permuted) -------
__global__ void transpose_v(const __half* __restrict__ v, __half* __restrict__ vT) {
    __shared__ __half tile[32][33];
    int bh = blockIdx.z;             // b*H + h
    int b = bh / N_HEADS, h = bh % N_HEADS;
    int s0 = blockIdx.x * 32;
    int d0 = blockIdx.y * 32;
    int tx = threadIdx.x, ty = threadIdx.y;  // 32 x 8
    const __half* src = v + ((size_t)b * SEQ) * D_MODEL;
    int pc = permh(h * D_HEAD + d0 + tx);
    #pragma unroll
    for (int i = 0; i < 32; i += 8)
        tile[ty + i][tx] = src[(size_t)(s0 + ty + i) * D_MODEL + pc];
    __syncthreads();
    __half* dst = vT + ((size_t)bh * D_HEAD) * SEQ;
    int ps = permh(s0 + tx);
    #pragma unroll
    for (int i = 0; i < 32; i += 8)
        dst[(size_t)(d0 + ty + i) * SEQ + ps] = tile[tx][ty + i];
}

// ---------------- fp16 mma.sync GEMM (cp.async 4-stage, permuted fp16 gmem) ----
// C = scale*(A[M,K] @ B[N,K]^T) (+bias)(+res)(relu).  BK = 32 halves.
// STATS: 0 = normal; 2 = stats-only (row-tile max + sumexp -> stm/stl, no C write).
// PERM_OUT: C is __half (permuted layout), written as coalesced uint4 per nt-group.
// QKV select when Ck != null. Warp grid 4x2, warp tile 32x64, CTA tile 128x128.
template<int STATS, int PERM_OUT>
__global__ void __launch_bounds__(256, 2)
gemm_f16(const __half* __restrict__ A, const __half* __restrict__ B,
         float* __restrict__ C, const float* __restrict__ bias, const float* __restrict__ res,
         __half* __restrict__ Ck, __half* __restrict__ Cv,
         const float* __restrict__ biask, const float* __restrict__ biasv,
         float* __restrict__ stm, float* __restrict__ stl,
         int M, int N, int K, int lda, int ldb, int ldc,
         float scale, int relu, int zmod,
         long long aLo, long long aHi, long long bLo, long long bHi,
         long long cLo, long long cHi)
{
    extern __shared__ __align__(16) uint32_t sm[];

    int z = blockIdx.z;
    int zlo = z % zmod, zhi = z / zmod;
    A += (size_t)zlo * aLo + (size_t)zhi * aHi;
    B += (size_t)zlo * bLo + (size_t)zhi * bHi;
    size_t coff = (size_t)zlo * cLo + (size_t)zhi * cHi;
    C += coff;
    if (res) res += coff;

    const int tid = threadIdx.x, lane = tid & 31, warp = tid >> 5;
    const int wm = (warp & 3) * 32, wn = (warp >> 2) * 64;
    const int m0 = blockIdx.y * 128, n0 = blockIdx.x * 128;

    const int ft = lane & 3, frl = lane >> 2;
    const int fu = ft ^ ((frl >> 1) & 3);
    const uint32_t ldAw = (uint32_t)((wm + frl) * 16 + 4 * fu);
    const uint32_t ldBw = (uint32_t)(2048 + (wn + frl) * 16 + 4 * fu);

    float acc[2][8][4];
    #pragma unroll
    for (int i = 0; i < 2; i++)
        #pragma unroll
        for (int j = 0; j < 8; j++)
            #pragma unroll
            for (int c = 0; c < 4; c++) acc[i][j][c] = 0.f;

    const int nk = K / 32;

    auto compute_at = [&](const uint32_t* base) {
        uint4 af[2][2];
        #pragma unroll
        for (int mt = 0; mt < 2; mt++)
            #pragma unroll
            for (int h = 0; h < 2; h++)
                af[mt][h] = *(const uint4*)&base[ldAw + mt * 256 + h * 128];
        #pragma unroll
        for (int nt = 0; nt < 8; nt++) {
            uint4 bf = *(const uint4*)&base[ldBw + nt * 128];
            #pragma unroll
            for (int mt = 0; mt < 2; mt++) {
                mma_f16(acc[mt][nt], af[mt][0].x, af[mt][1].x, af[mt][0].y, af[mt][1].y,
                        bf.x, bf.y);
                mma_f16(acc[mt][nt], af[mt][0].z, af[mt][1].z, af[mt][0].w, af[mt][1].w,
                        bf.z, bf.w);
            }
        }
    };

    {
        const uint32_t smem_base = smem_u32(sm);
        uint32_t saw[2], sbw[2];
        const __half *ga[2], *gb[2];
        #pragma unroll
        for (int j = 0; j < 2; j++) {
            int id = tid + 256 * j;
            int r = id >> 2, u = id & 3;
            int up = u ^ ((r >> 1) & 3);
            saw[j] = (uint32_t)((r * 16 + 4 * up) * 4);
            sbw[j] = (uint32_t)((2048 + r * 16 + 4 * up) * 4);
            ga[j] = A + (size_t)(m0 + r) * lda + 8 * u;
            gb[j] = B + (size_t)(n0 + r) * ldb + 8 * u;
        }
        auto issue = [&](int tile, int stg) {
            const int k0 = tile * 32;
            const uint32_t sb = smem_base + (uint32_t)stg * 16384u;
            #pragma unroll
            for (int j = 0; j < 2; j++) cp_async16(sb + saw[j], ga[j] + k0);
            #pragma unroll
            for (int j = 0; j < 2; j++) cp_async16(sb + sbw[j], gb[j] + k0);
            cp_commit();
        };
        issue(0, 0); issue(1, 1); issue(2, 2);
        int st = 0;
        for (int t = 0; t < nk; ++t) {
            cp_wait2();
            __syncthreads();
            compute_at(sm + st * 4096);
            if (t + 3 < nk) issue(t + 3, (st + 3) & 3);
            else            cp_commit();
            st = (st + 1) & 3;
        }
        __syncthreads();
    }

    if (STATS == 2) {
        // ---- stats-only: per-row tile max + sumexp; NO C store ----
        float* smf = (float*)sm;
        const int g = warp >> 2;
        const int rl = lane >> 2;
        float lmax[2][2];
        #pragma unroll
        for (int mt = 0; mt < 2; mt++)
            #pragma unroll
            for (int h = 0; h < 2; h++) {
                float v = -1e30f;
                #pragma unroll
                for (int nt = 0; nt < 8; nt++) {
                    v = fmaxf(v, acc[mt][nt][2 * h]);
                    v = fmaxf(v, acc[mt][nt][2 * h + 1]);
                }
                lmax[mt][h] = v * scale;
            }
        #pragma unroll
        for (int o = 1; o < 4; o <<= 1)
            #pragma unroll
            for (int mt = 0; mt < 2; mt++)
                #pragma unroll
                for (int h = 0; h < 2; h++)
                    lmax[mt][h] = fmaxf(lmax[mt][h], __shfl_xor_sync(0xffffffffu, lmax[mt][h], o));
        __syncthreads();
        if ((lane & 3) == 0)
            #pragma unroll
            for (int mt = 0; mt < 2; mt++)
                #pragma unroll
                for (int h = 0; h < 2; h++)
                    smf[g * 128 + wm + mt * 16 + h * 8 + rl] = lmax[mt][h];
        __syncthreads();
        float rmax[2][2], lsum[2][2];
        #pragma unroll
        for (int mt = 0; mt < 2; mt++)
            #pragma unroll
            for (int h = 0; h < 2; h++) {
                int row = wm + mt * 16 + h * 8 + rl;
                rmax[mt][h] = fmaxf(smf[row], smf[128 + row]);
                lsum[mt][h] = 0.f;
            }
        #pragma unroll
        for (int mt = 0; mt < 2; ++mt)
            #pragma unroll
            for (int nt = 0; nt < 8; ++nt)
                #pragma unroll
                for (int h = 0; h < 2; ++h) {
                    lsum[mt][h] += __expf(acc[mt][nt][2 * h]     * scale - rmax[mt][h]);
                    lsum[mt][h] += __expf(acc[mt][nt][2 * h + 1] * scale - rmax[mt][h]);
                }
        #pragma unroll
        for (int o = 1; o < 4; o <<= 1)
            #pragma unroll
            for (int mt = 0; mt < 2; mt++)
                #pragma unroll
                for (int h = 0; h < 2; h++)
                    lsum[mt][h] += __shfl_xor_sync(0xffffffffu, lsum[mt][h], o);
        if ((lane & 3) == 0)
            #pragma unroll
            for (int mt = 0; mt < 2; mt++)
                #pragma unroll
                for (int h = 0; h < 2; h++)
                    smf[256 + g * 128 + wm + mt * 16 + h * 8 + rl] = lsum[mt][h];
        __syncthreads();
        if (g == 0 && (lane & 3) == 0) {
            #pragma unroll
            for (int mt = 0; mt < 2; mt++)
                #pragma unroll
                for (int h = 0; h < 2; h++) {
                    int row = wm + mt * 16 + h * 8 + rl;
                    size_t idx = ((size_t)z * 8 + blockIdx.x) * 1024 + m0 + row;
                    stm[idx] = rmax[mt][h];
                    stl[idx] = smf[256 + row] + smf[384 + row];
                }
        }
    } else {
        // ---- normal epilogue (QKV 3-way select) ----
        void* Cp = (void*)C; const float* bp = bias; int noff = 0;
        if (Ck) {
            if (n0 >= 2048)      { Cp = (void*)Cv; bp = biasv; noff = 2048; }
            else if (n0 >= 1024) { Cp = (void*)Ck; bp = biask; noff = 1024; }
        }
        if (PERM_OUT) {
            // coalesced fp16 store: nt-group of 4 packed h2 = one aligned uint4.
            // p = 16*blk + 4*a + (nt&3), a = lane&3, blk = (cl_base>>5) + g.
            uint32_t* Ch2 = (uint32_t*)Cp;
            const int a = lane & 3;
            const int clb = n0 + wn - noff;            // multiple of 32
            #pragma unroll
            for (int mt = 0; mt < 2; ++mt) {
                #pragma unroll
                for (int h = 0; h < 2; ++h) {
                    int rr = m0 + wm + mt * 16 + h * 8 + (lane >> 2);
                    #pragma unroll
                    for (int g = 0; g < 2; ++g) {
                        uint32_t w[4];
                        #pragma unroll
                        for (int j = 0; j < 4; ++j) {
                            int nt = 4 * g + j;
                            int cl = clb + nt * 8 + a * 2;
                            float v0 = acc[mt][nt][h * 2 + 0] * scale;
                            float v1 = acc[mt][nt][h * 2 + 1] * scale;
                            if (bp) { float2 bb = *(const float2*)(bp + cl); v0 += bb.x; v1 += bb.y; }
                            if (relu) { v0 = fmaxf(v0, 0.f); v1 = fmaxf(v1, 0.f); }
                            w[j] = pack_h2(v0, v1);
                        }
                        int p0 = ((clb >> 5) + g) * 16 + 4 * a;
                        uint4 u4 = make_uint4(w[0], w[1], w[2], w[3]);
                        *(uint4*)&Ch2[(size_t)rr * (ldc >> 1) + p0] = u4;
                    }
                }
            }
        } else {
            #pragma unroll
            for (int mt = 0; mt < 2; ++mt) {
                #pragma unroll
                for (int nt = 0; nt < 8; ++nt) {
                    int rbase = m0 + wm + mt * 16 + (lane >> 2);
                    int cbase = n0 + wn + nt * 8 + (lane & 3) * 2;
                    #pragma unroll
                    for (int h = 0; h < 2; ++h) {
                        int rr = rbase + h * 8;
                        int cl = cbase - noff;
                        float v0 = acc[mt][nt][h * 2 + 0] * scale;
                        float v1 = acc[mt][nt][h * 2 + 1] * scale;
                        if (bp)  { float2 bb = *(const float2*)(bp + cl); v0 += bb.x; v1 += bb.y; }
                        if (res) { float2 r2 = *(const float2*)(res + (size_t)rr * ldc + cl); v0 += r2.x; v1 += r2.y; }
                        if (relu) { v0 = fmaxf(v0, 0.f); v1 = fmaxf(v1, 0.f); }
                        *(float2*)((float*)Cp + (size_t)rr * ldc + cl) = make_float2(v0, v1);
                    }
                }
            }
        }
    }
}

// ---------------- fused attention ctx (fp16 MMAs, in-kernel stat combine) ----------
// Per CTA: z, 128-row q block; 16 column tiles of 64 k-positions.
// Prologue: combine per-tile (m_t, l_t) stats for this CTA's 128 rows -> smem (m,1/l).
// Loop: S = q @ kt^T; p = __expf(s/8 - m)*invl; P -> gmem fp32 and smem fp16;
// ctx += P @ vt^T; epilogue o1 = ctx + x.
// smem words: q[0,4096) kt[4096,6144) vt[6144,8192) P[8192,12288) rst[12288,12544)
__global__ void __launch_bounds__(256, 2)
attn_ctx(const __half* __restrict__ q, const __half* __restrict__ k,
         const __half* __restrict__ vT, const float* __restrict__ stm,
         const float* __restrict__ stl,
         float* __restrict__ attn, const float* __restrict__ x,
         float* __restrict__ o1)
{
    extern __shared__ __align__(16) uint32_t sm[];
    constexpr int QW = 0, KW = 4096, VW = 6144, PWo = 8192;
    constexpr int NJ = 16;
    float2* rstS = (float2*)(sm + 12288);

    const int tid = threadIdx.x, lane = tid & 31, warp = tid >> 5;
    const int wm = (warp & 3) * 32, wn = (warp >> 2) * 32;
    const int ft = lane & 3, frl = lane >> 2;
    const int zz = blockIdx.y;           // h*4 + b
    const int b = zz & 3, hh = zz >> 2;
    const int m0 = blockIdx.x * 128;

    const __half* qbase = q + ((size_t)b * SEQ + m0) * D_MODEL + hh * 64;
    const __half* kbase = k + (size_t)b * SEQ * D_MODEL + hh * 64;
    const __half* vbase = vT + (size_t)(b * N_HEADS + hh) * 64 * SEQ;
    float* pbase = attn + (size_t)zz * SEQ * SEQ + (size_t)m0 * SEQ;
    const float* xbase = x + ((size_t)b * SEQ + m0) * D_MODEL + hh * 64;
    float* obase = o1 + ((size_t)b * SEQ + m0) * D_MODEL + hh * 64;

    const uint32_t smb = smem_u32(sm);

    auto swaddr = [](int r, int u) {
        return r * 32 + 4 * ((u + ((r & 1) << 2)) & 7);
    };

    auto load_q = [&]() {
        #pragma unroll
        for (int j = 0; j < 4; j++) {
            int g = tid + 256 * j;
            int r = g >> 3, u = g & 7;
            cp_async16(smb + 4 * (QW + swaddr(r, u)), qbase + (size_t)r * D_MODEL + 8 * u);
        }
    };
    auto load_k = [&](int jt) {
        #pragma unroll
        for (int j = 0; j < 2; j++) {
            int g = tid + 256 * j;
            int r = g >> 3, u = g & 7;
            cp_async16(smb + 4 * (KW + swaddr(r, u)),
                       kbase + (size_t)(jt * 64 + r) * D_MODEL + 8 * u);
        }
    };
    auto load_v = [&](int jt) {
        #pragma unroll
        for (int j = 0; j < 2; j++) {
            int g = tid + 256 * j;
            int r = g >> 3, u = g & 7;
            cp_async16(smb + 4 * (VW + swaddr(r, u)),
                       vbase + (size_t)r * SEQ + jt * 64 + 8 * u);
        }
    };

    load_q(); load_k(0); cp_commit();     // group: {q, kt0}
    load_v(0); cp_commit();               // group: {vt0}

    // in-kernel stat combine while loads are in flight
    if (tid < 128) {
        int row = m0 + tid;
        const float* pm = stm + (size_t)zz * 8 * 1024 + row;
        const float* pl = stl + (size_t)zz * 8 * 1024 + row;
        float mv[8];
        float m = -1e30f;
        #pragma unroll
        for (int t = 0; t < 8; t++) { mv[t] = pm[t * 1024]; m = fmaxf(m, mv[t]); }
        float l = 0.f;
        #pragma unroll
        for (int t = 0; t < 8; t++) l += pl[t * 1024] * __expf(mv[t] - m);
        rstS[tid] = make_float2(m, 1.0f / l);
    }
    __syncthreads();

    float2 st[2][2];
    #pragma unroll
    for (int mt = 0; mt < 2; mt++)
        #pragma unroll
        for (int h = 0; h < 2; h++)
            st[mt][h] = rstS[wm + mt * 16 + h * 8 + frl];

    float acc_c[2][4][4];
    #pragma unroll
    for (int i = 0; i < 2; i++)
        #pragma unroll
        for (int j = 0; j < 4; j++)
            #pragma unroll
            for (int c = 0; c < 4; c++) acc_c[i][j][c] = 0.f;

    for (int jt = 0; jt < NJ; ++jt) {
        float acc_s[2][4][4];
        #pragma unroll
        for (int i = 0; i < 2; i++)
            #pragma unroll
            for (int j = 0; j < 4; j++)
                #pragma unroll
                for (int c = 0; c < 4; c++) acc_s[i][j][c] = 0.f;

        cp_wait1();          // q + kt ready
        __syncthreads();

        // S = q @ kt^T
        #pragma unroll
        for (int kb = 0; kb < 2; kb++) {
            uint4 af[2][2];
            #pragma unroll
            for (int mt = 0; mt < 2; mt++)
                #pragma unroll
                for (int h = 0; h < 2; h++)
                    af[mt][h] = *(const uint4*)&sm[QW + swaddr(wm + mt * 16 + h * 8 + frl, 4 * kb + ft)];
            #pragma unroll
            for (int nt = 0; nt < 4; nt++) {
                uint4 bf = *(const uint4*)&sm[KW + swaddr(wn + nt * 8 + frl, 4 * kb + ft)];
                #pragma unroll
                for (int mt = 0; mt < 2; mt++) {
                    mma_f16(acc_s[mt][nt], af[mt][0].x, af[mt][1].x, af[mt][0].y, af[mt][1].y,
                            bf.x, bf.y);
                    mma_f16(acc_s[mt][nt], af[mt][0].z, af[mt][1].z, af[mt][0].w, af[mt][1].w,
                            bf.z, bf.w);
                }
            }
        }

        // transform S -> P and stage P (fp16) into smem
        #pragma unroll
        for (int mt = 0; mt < 2; mt++) {
            #pragma unroll
            for (int h = 0; h < 2; h++) {
                int r = wm + mt * 16 + h * 8 + frl;
                int rot = (r & 1) << 2;
                float mrow = st[mt][h].x, invl = st[mt][h].y;
                #pragma unroll
                for (int nt = 0; nt < 4; nt++) {
                    float p0 = __expf(acc_s[mt][nt][h * 2 + 0] * 0.125f - mrow) * invl;
                    float p1 = __expf(acc_s[mt][nt][h * 2 + 1] * 0.125f - mrow) * invl;
                    acc_s[mt][nt][h * 2 + 0] = p0;
                    acc_s[mt][nt][h * 2 + 1] = p1;
                    int c = wn + nt * 8 + (lane & 3) * 2;
                    int blk = c >> 5, hu5 = (c & 31) >> 1;
                    int ul = 4 * blk + (hu5 & 3), sub = hu5 >> 2;
                    sm[PWo + r * 32 + 4 * ((ul + rot) & 7) + sub] = pack_h2(p0, p1);
                }
            }
        }

        cp_wait0();          // vt ready
        __syncthreads();     // P visible; kt consumed
        if (jt + 1 < NJ) load_k(jt + 1);
        cp_commit();

        // ctx += P @ vt^T
        #pragma unroll
        for (int kb = 0; kb < 2; kb++) {
            uint4 af[2][2];
            #pragma unroll
            for (int mt = 0; mt < 2; mt++)
                #pragma unroll
                for (int h = 0; h < 2; h++)
                    af[mt][h] = *(const uint4*)&sm[PWo + swaddr(wm + mt * 16 + h * 8 + frl, 4 * kb + ft)];
            #pragma unroll
            for (int nt = 0; nt < 4; nt++) {
                uint4 bf = *(const uint4*)&sm[VW + swaddr(wn + nt * 8 + frl, 4 * kb + ft)];
                #pragma unroll
                for (int mt = 0; mt < 2; mt++) {
                    mma_f16(acc_c[mt][nt], af[mt][0].x, af[mt][1].x, af[mt][0].y, af[mt][1].y,
                            bf.x, bf.y);
                    mma_f16(acc_c[mt][nt], af[mt][0].z, af[mt][1].z, af[mt][0].w, af[mt][1].w,
                            bf.z, bf.w);
                }
            }
        }

        // write final P (fp32) to gmem
        #pragma unroll
        for (int mt = 0; mt < 2; mt++)
            #pragma unroll
            for (int h = 0; h < 2; h++) {
                int r = wm + mt * 16 + h * 8 + frl;
                float* prow = pbase + (size_t)r * SEQ + jt * 64;
                #pragma unroll
                for (int nt = 0; nt < 4; nt++)
                    *(float2*)(prow + wn + nt * 8 + (lane & 3) * 2) =
                        make_float2(acc_s[mt][nt][h * 2], acc_s[mt][nt][h * 2 + 1]);
            }

        __syncthreads();     // vt and P consumed
        if (jt + 1 < NJ) load_v(jt + 1);
        cp_commit();
    }

    // epilogue: o1 = ctx + x
    #pragma unroll
    for (int mt = 0; mt < 2; mt++)
        #pragma unroll
        for (int h = 0; h < 2; h++) {
            int r = wm + mt * 16 + h * 8 + frl;
            #pragma unroll
            for (int nt = 0; nt < 4; nt++) {
                int c = wn + nt * 8 + (lane & 3) * 2;
                float2 xr = *(const float2*)(xbase + (size_t)r * D_MODEL + c);
                *(float2*)(obase + (size_t)r * D_MODEL + c) =
                    make_float2(acc_c[mt][nt][h * 2] + xr.x, acc_c[mt][nt][h * 2 + 1] + xr.y);
            }
        }
}

// ---------------- launch ----------------
extern "C" void kernel_launch(void* const* d_in, const int* in_sizes, int n_in,
                              void* d_out, int out_size) {
    const float* x     = (const float*)d_in[0];
    const float* ln1_g = (const float*)d_in[1];
    const float* ln1_b = (const float*)d_in[2];
    const float* wq    = (const float*)d_in[3];
    const float* bq    = (const float*)d_in[4];
    const float* wk    = (const float*)d_in[5];
    const float* bk    = (const float*)d_in[6];
    const float* wv    = (const float*)d_in[7];
    const float* bv    = (const float*)d_in[8];
    const float* ln2_g = (const float*)d_in[9];
    const float* ln2_b = (const float*)d_in[10];
    const float* w1    = (const float*)d_in[11];
    const float* b1    = (const float*)d_in[12];
    const float* w2    = (const float*)d_in[13];
    const float* b2    = (const float*)d_in[14];

    float* out  = (float*)d_out;
    float* attn = out + (size_t)BATCH * SEQ * D_MODEL;

    __half *h, *q, *k, *v, *vT, *h2, *ff, *wqkv, *w1r, *w2r;
    float *o1, *stm, *stl;
    cudaGetSymbolAddress((void**)&h,    g_h);
    cudaGetSymbolAddress((void**)&q,    g_q);
    cudaGetSymbolAddress((void**)&k,    g_k);
    cudaGetSymbolAddress((void**)&v,    g_v);
    cudaGetSymbolAddress((void**)&vT,   g_vT);
    cudaGetSymbolAddress((void**)&h2,   g_h2);
    cudaGetSymbolAddress((void**)&ff,   g_ff);
    cudaGetSymbolAddress((void**)&wqkv, g_wqkv);
    cudaGetSymbolAddress((void**)&w1r,  g_w1r);
    cudaGetSymbolAddress((void**)&w2r,  g_w2r);
    cudaGetSymbolAddress((void**)&o1,   g_o1);
    cudaGetSymbolAddress((void**)&stm,  g_stm);
    cudaGetSymbolAddress((void**)&stl,  g_stl);

    dim3 blk(256);
    const int SM_P4 = 4 * 4096 * 4;               // 65536 bytes
    const int SM_CTX = 12544 * 4;                 // 50176 bytes

    cudaFuncSetAttribute(gemm_f16<0, 1>, cudaFuncAttributeMaxDynamicSharedMemorySize, SM_P4);
    cudaFuncSetAttribute(gemm_f16<2, 0>, cudaFuncAttributeMaxDynamicSharedMemorySize, SM_P4);
    cudaFuncSetAttribute(gemm_f16<0, 0>, cudaFuncAttributeMaxDynamicSharedMemorySize, SM_P4);
    cudaFuncSetAttribute(attn_ctx, cudaFuncAttributeMaxDynamicSharedMemorySize, SM_CTX);

    // 0) all weights -> fp16 permuted scratch (one launch)
    round_all<<<5632, 256>>>((const float4*)wq, (const float4*)wk, (const float4*)wv,
                             (const float4*)w1, (const float4*)w2,
                             (uint32_t*)wqkv, (uint32_t*)w1r, (uint32_t*)w2r);

    // 1) LN1 (fp16 permuted output)
    ln_kernel<<<M_TOK, 256>>>(x, ln1_g, ln1_b, (uint32_t*)h);

    // 2) fused QKV: q/k/v fp16 permuted (coalesced uint4 epilogue)
    gemm_f16<0, 1><<<dim3(24, 32, 1), blk, SM_P4>>>(h, wqkv, (float*)q, bq, nullptr, k, v, bk, bv,
        nullptr, nullptr,
        M_TOK, 3 * D_MODEL, D_MODEL, D_MODEL, D_MODEL, D_MODEL, 1.f, 0, 1, 0,0,0,0,0,0);

    // 3) V transpose (fp16 permuted in/out)
    transpose_v<<<dim3(32, 2, BATCH * N_HEADS), dim3(32, 8)>>>(v, vT);

    // 4) scores stats only (no big write)
    gemm_f16<2, 0><<<dim3(8, 8, N_HEADS * BATCH), blk, SM_P4>>>(q, k, attn, nullptr, nullptr,
        nullptr, nullptr, nullptr, nullptr,
        stm, stl,
        SEQ, SEQ, D_HEAD, D_MODEL, D_MODEL, SEQ, 0.125f, 0, BATCH,
        (long long)SEQ * D_MODEL, 64,
        (long long)SEQ * D_MODEL, 64,
        (long long)SEQ * SEQ, (long long)BATCH * SEQ * SEQ);

    // 5) fused ctx (stat combine inside): recompute S, write P (fp32), ctx + x -> o1
    attn_ctx<<<dim3(8, 64), blk, SM_CTX>>>(q, k, vT, stm, stl, attn, x, o1);

    // 6) LN2 (fp16 permuted output)
    ln_kernel<<<M_TOK, 256>>>(o1, ln2_g, ln2_b, (uint32_t*)h2);

    // 7) FFN1: relu(h2 @ w1^T + b1) -> fp16 permuted (coalesced epilogue)
    gemm_f16<0, 1><<<dim3(32, 32, 1), blk, SM_P4>>>(h2, w1r, (float*)ff, b1, nullptr,
        nullptr, nullptr, nullptr, nullptr,
        nullptr, nullptr,
        M_TOK, D_FF, D_MODEL, D_MODEL, D_MODEL, D_FF, 1.f, 1, 1, 0,0,0,0,0,0);

    // 8) FFN2: ff @ w2^T + b2 + o1 -> final out (fp32)
    gemm_f16<0, 0><<<dim3(8, 32, 1), blk, SM_P4>>>(ff, w2r, out, b2, o1,
        nullptr, nullptr, nullptr, nullptr,
        nullptr, nullptr,
        M_TOK, D_MODEL, D_FF, D_FF, D_FF, D_MODEL, 1.f, 0, 1, 0,0,0,0,0,0);
}

// round 16
// speedup vs baseline: 2.1446x; 1.0575x over previous
#include <cuda_runtime.h>
#include <cuda_fp16.h>
#include <cstdint>

#define D_MODEL 1024
#define N_HEADS 16
#define D_HEAD  64
#define D_FF    4096
#define BATCH   4
#define SEQ     1024
#define M_TOK   (BATCH*SEQ)   // 4096

// ---------------- scratch (allocation-free: device globals) ----------------
__device__ __half g_h   [M_TOK*D_MODEL];
__device__ __half g_q   [M_TOK*D_MODEL];
__device__ __half g_k   [M_TOK*D_MODEL];
__device__ __half g_v   [M_TOK*D_MODEL];
__device__ __half g_vT  [M_TOK*D_MODEL];
__device__ __half g_h2  [M_TOK*D_MODEL];
__device__ __half g_ff  [M_TOK*D_FF];
__device__ __half g_wqkv[3*D_MODEL*D_MODEL];
__device__ __half g_w1r [D_FF*D_MODEL];
__device__ __half g_w2r [D_MODEL*D_FF];
__device__ float  g_o1  [M_TOK*D_MODEL];
__device__ float  g_rst [64*1024*2];     // per-(z,row): (m, 1/l)

// ---------------- helpers ----------------
__device__ __forceinline__ uint32_t pack_h2(float a, float b) {
    __half2 h = __floats2half2_rn(a, b);
    return reinterpret_cast<uint32_t&>(h);
}

__device__ __forceinline__ uint32_t smem_u32(const void* p) {
    uint32_t a;
    asm("{ .reg .u64 t; cvta.to.shared.u64 t, %1; cvt.u32.u64 %0, t; }" : "=r"(a) : "l"(p));
    return a;
}

__device__ __forceinline__ void cp_async16(uint32_t saddr, const void* gptr) {
    asm volatile("cp.async.cg.shared.global [%0], [%1], 16;" :: "r"(saddr), "l"(gptr) : "memory");
}
__device__ __forceinline__ void cp_commit() {
    asm volatile("cp.async.commit_group;" ::: "memory");
}
__device__ __forceinline__ void cp_wait0() {
    asm volatile("cp.async.wait_group 0;" ::: "memory");
}
__device__ __forceinline__ void cp_wait1() {
    asm volatile("cp.async.wait_group 1;" ::: "memory");
}
__device__ __forceinline__ void cp_wait2() {
    asm volatile("cp.async.wait_group 2;" ::: "memory");
}

__device__ __forceinline__ void mma_f16(float* c, uint32_t a0, uint32_t a1, uint32_t a2, uint32_t a3,
                                        uint32_t b0, uint32_t b1) {
    asm volatile(
        "mma.sync.aligned.m16n8k16.row.col.f32.f16.f16.f32 "
        "{%0,%1,%2,%3}, {%4,%5,%6,%7}, {%8,%9}, {%0,%1,%2,%3};\n"
        : "+f"(c[0]), "+f"(c[1]), "+f"(c[2]), "+f"(c[3])
        : "r"(a0), "r"(a1), "r"(a2), "r"(a3), "r"(b0), "r"(b1));
}

// physical half position of logical half k inside its 32-half block:
// hu = (k&31)>>1; pos_h2 = 4*(hu&3) + (hu>>2); pos = 2*pos_h2 + (k&1)
__device__ __forceinline__ int permh(int k) {
    int k5 = k & 31, hu = k5 >> 1;
    return (k & ~31) + 2 * (4 * (hu & 3) + (hu >> 2)) + (k5 & 1);
}

// ---------------- merged weight round+permute: 5 tensors in one launch ----------
__global__ void round_all(const float4* __restrict__ wq, const float4* __restrict__ wk,
                          const float4* __restrict__ wv, const float4* __restrict__ w1,
                          const float4* __restrict__ w2,
                          uint32_t* __restrict__ dqkv, uint32_t* __restrict__ dw1,
                          uint32_t* __restrict__ dw2) {
    int i = blockIdx.x * blockDim.x + threadIdx.x;
    const float4* src; uint32_t* dst; int idx;
    if (i < 131072)       { src = wq; dst = dqkv;           idx = i; }
    else if (i < 262144)  { src = wk; dst = dqkv + 524288;  idx = i - 131072; }
    else if (i < 393216)  { src = wv; dst = dqkv + 1048576; idx = i - 262144; }
    else if (i < 917504)  { src = w1; dst = dw1;            idx = i - 393216; }
    else                  { src = w2; dst = dw2;            idx = i - 917504; }
    float4 va = src[2 * idx], vb = src[2 * idx + 1];
    uint32_t* p = dst + (size_t)(idx >> 2) * 16 + (idx & 3);
    p[0]  = pack_h2(va.x, va.y);
    p[4]  = pack_h2(va.z, va.w);
    p[8]  = pack_h2(vb.x, vb.y);
    p[12] = pack_h2(vb.z, vb.w);
}

// ---------------- LayerNorm; fp16 + PERMUTED output ----------------------------
__global__ void ln_kernel(const float* __restrict__ x, const float* __restrict__ g,
                          const float* __restrict__ b, uint32_t* __restrict__ outh2) {
    int row = blockIdx.x;
    int t = threadIdx.x;  // 256 threads, 4 floats each
    const float4* xr = (const float4*)(x + (size_t)row * D_MODEL);
    float4 v = xr[t];
    __shared__ float red[8];

    float s = v.x + v.y + v.z + v.w;
    #pragma unroll
    for (int o = 16; o; o >>= 1) s += __shfl_xor_sync(0xffffffffu, s, o);
    if ((t & 31) == 0) red[t >> 5] = s;
    __syncthreads();
    float tot = red[0]+red[1]+red[2]+red[3]+red[4]+red[5]+red[6]+red[7];
    float mean = tot * (1.0f / D_MODEL);

    float dx = v.x - mean, dy = v.y - mean, dz = v.z - mean, dw = v.w - mean;
    float ss = dx*dx + dy*dy + dz*dz + dw*dw;
    #pragma unroll
    for (int o = 16; o; o >>= 1) ss += __shfl_xor_sync(0xffffffffu, ss, o);
    __syncthreads();
    if ((t & 31) == 0) red[t >> 5] = ss;
    __syncthreads();
    float vtot = red[0]+red[1]+red[2]+red[3]+red[4]+red[5]+red[6]+red[7];
    float inv = 1.0f / (sqrtf(vtot * (1.0f / (D_MODEL - 1))) + 1e-12f);

    float4 g4 = ((const float4*)g)[t];
    float4 b4 = ((const float4*)b)[t];
    float o0 = g4.x * dx * inv + b4.x;
    float o1v = g4.y * dy * inv + b4.y;
    float o2 = g4.z * dz * inv + b4.z;
    float o3 = g4.w * dw * inv + b4.w;

    int s5 = (t >> 1) & 3, blk = t >> 3, odd = t & 1;
    uint32_t* p = outh2 + (size_t)row * 512 + blk * 16 + 8 * odd + s5;
    p[0] = pack_h2(o0, o1v);
    p[4] = pack_h2(o2, o3);
}

// ---------------- V transpose: v (half, permuted) -> vT (half, permuted) -------
__global__ void transpose_v(const __half* __restrict__ v, __half* __restrict__ vT) {
    __shared__ __half tile[32][33];
    int bh = blockIdx.z;             // b*H + h
    int b = bh / N_HEADS, h = bh % N_HEADS;
    int s0 = blockIdx.x * 32;
    int d0 = blockIdx.y * 32;
    int tx = threadIdx.x, ty = threadIdx.y;  // 32 x 8
    const __half* src = v + ((size_t)b * SEQ) * D_MODEL;
    int pc = permh(h * D_HEAD + d0 + tx);
    #pragma unroll
    for (int i = 0; i < 32; i += 8)
        tile[ty + i][tx] = src[(size_t)(s0 + ty + i) * D_MODEL + pc];
    __syncthreads();
    __half* dst = vT + ((size_t)bh * D_HEAD) * SEQ;
    int ps = permh(s0 + tx);
    #pragma unroll
    for (int i = 0; i < 32; i += 8)
        dst[(size_t)(d0 + ty + i) * SEQ + ps] = tile[tx][ty + i];
}

// ---------------- fp16 mma.sync GEMM (cp.async 4-stage, permuted fp16 gmem) ----
// C = scale*(A[M,K] @ B[N,K]^T) (+bias)(+res)(relu).  BK = 32 halves.
// PERM_OUT: C is __half (permuted layout), coalesced uint4 stores.
// QKV select when Ck != null. Warp grid 4x2, warp tile 32x64, CTA tile 128x128.
template<int PERM_OUT>
__global__ void __launch_bounds__(256, 2)
gemm_f16(const __half* __restrict__ A, const __half* __restrict__ B,
         float* __restrict__ C, const float* __restrict__ bias, const float* __restrict__ res,
         __half* __restrict__ Ck, __half* __restrict__ Cv,
         const float* __restrict__ biask, const float* __restrict__ biasv,
         int M, int N, int K, int lda, int ldb, int ldc,
         float scale, int relu)
{
    extern __shared__ __align__(16) uint32_t sm[];

    const int tid = threadIdx.x, lane = tid & 31, warp = tid >> 5;
    const int wm = (warp & 3) * 32, wn = (warp >> 2) * 64;
    const int m0 = blockIdx.y * 128, n0 = blockIdx.x * 128;

    const int ft = lane & 3, frl = lane >> 2;
    const int fu = ft ^ ((frl >> 1) & 3);
    const uint32_t ldAw = (uint32_t)((wm + frl) * 16 + 4 * fu);
    const uint32_t ldBw = (uint32_t)(2048 + (wn + frl) * 16 + 4 * fu);

    float acc[2][8][4];
    #pragma unroll
    for (int i = 0; i < 2; i++)
        #pragma unroll
        for (int j = 0; j < 8; j++)
            #pragma unroll
            for (int c = 0; c < 4; c++) acc[i][j][c] = 0.f;

    const int nk = K / 32;

    auto compute_at = [&](const uint32_t* base) {
        uint4 af[2][2];
        #pragma unroll
        for (int mt = 0; mt < 2; mt++)
            #pragma unroll
            for (int h = 0; h < 2; h++)
                af[mt][h] = *(const uint4*)&base[ldAw + mt * 256 + h * 128];
        #pragma unroll
        for (int nt = 0; nt < 8; nt++) {
            uint4 bf = *(const uint4*)&base[ldBw + nt * 128];
            #pragma unroll
            for (int mt = 0; mt < 2; mt++) {
                mma_f16(acc[mt][nt], af[mt][0].x, af[mt][1].x, af[mt][0].y, af[mt][1].y,
                        bf.x, bf.y);
                mma_f16(acc[mt][nt], af[mt][0].z, af[mt][1].z, af[mt][0].w, af[mt][1].w,
                        bf.z, bf.w);
            }
        }
    };

    {
        const uint32_t smem_base = smem_u32(sm);
        uint32_t saw[2], sbw[2];
        const __half *ga[2], *gb[2];
        #pragma unroll
        for (int j = 0; j < 2; j++) {
            int id = tid + 256 * j;
            int r = id >> 2, u = id & 3;
            int up = u ^ ((r >> 1) & 3);
            saw[j] = (uint32_t)((r * 16 + 4 * up) * 4);
            sbw[j] = (uint32_t)((2048 + r * 16 + 4 * up) * 4);
            ga[j] = A + (size_t)(m0 + r) * lda + 8 * u;
            gb[j] = B + (size_t)(n0 + r) * ldb + 8 * u;
        }
        auto issue = [&](int tile, int stg) {
            const int k0 = tile * 32;
            const uint32_t sb = smem_base + (uint32_t)stg * 16384u;
            #pragma unroll
            for (int j = 0; j < 2; j++) cp_async16(sb + saw[j], ga[j] + k0);
            #pragma unroll
            for (int j = 0; j < 2; j++) cp_async16(sb + sbw[j], gb[j] + k0);
            cp_commit();
        };
        issue(0, 0); issue(1, 1); issue(2, 2);
        int st = 0;
        for (int t = 0; t < nk; ++t) {
            cp_wait2();
            __syncthreads();
            compute_at(sm + st * 4096);
            if (t + 3 < nk) issue(t + 3, (st + 3) & 3);
            else            cp_commit();
            st = (st + 1) & 3;
        }
        __syncthreads();
    }

    // ---- epilogue (QKV 3-way select) ----
    void* Cp = (void*)C; const float* bp = bias; int noff = 0;
    if (Ck) {
        if (n0 >= 2048)      { Cp = (void*)Cv; bp = biasv; noff = 2048; }
        else if (n0 >= 1024) { Cp = (void*)Ck; bp = biask; noff = 1024; }
    }
    if (PERM_OUT) {
        uint32_t* Ch2 = (uint32_t*)Cp;
        const int a = lane & 3;
        const int clb = n0 + wn - noff;            // multiple of 32
        #pragma unroll
        for (int mt = 0; mt < 2; ++mt) {
            #pragma unroll
            for (int h = 0; h < 2; ++h) {
                int rr = m0 + wm + mt * 16 + h * 8 + (lane >> 2);
                #pragma unroll
                for (int g = 0; g < 2; ++g) {
                    uint32_t w[4];
                    #pragma unroll
                    for (int j = 0; j < 4; ++j) {
                        int nt = 4 * g + j;
                        int cl = clb + nt * 8 + a * 2;
                        float v0 = acc[mt][nt][h * 2 + 0] * scale;
                        float v1 = acc[mt][nt][h * 2 + 1] * scale;
                        if (bp) { float2 bb = *(const float2*)(bp + cl); v0 += bb.x; v1 += bb.y; }
                        if (relu) { v0 = fmaxf(v0, 0.f); v1 = fmaxf(v1, 0.f); }
                        w[j] = pack_h2(v0, v1);
                    }
                    int p0 = ((clb >> 5) + g) * 16 + 4 * a;
                    uint4 u4 = make_uint4(w[0], w[1], w[2], w[3]);
                    *(uint4*)&Ch2[(size_t)rr * (ldc >> 1) + p0] = u4;
                }
            }
        }
    } else {
        #pragma unroll
        for (int mt = 0; mt < 2; ++mt) {
            #pragma unroll
            for (int nt = 0; nt < 8; ++nt) {
                int rbase = m0 + wm + mt * 16 + (lane >> 2);
                int cbase = n0 + wn + nt * 8 + (lane & 3) * 2;
                #pragma unroll
                for (int h = 0; h < 2; ++h) {
                    int rr = rbase + h * 8;
                    int cl = cbase - noff;
                    float v0 = acc[mt][nt][h * 2 + 0] * scale;
                    float v1 = acc[mt][nt][h * 2 + 1] * scale;
                    if (bp)  { float2 bb = *(const float2*)(bp + cl); v0 += bb.x; v1 += bb.y; }
                    if (res) { float2 r2 = *(const float2*)(res + (size_t)rr * ldc + cl); v0 += r2.x; v1 += r2.y; }
                    if (relu) { v0 = fmaxf(v0, 0.f); v1 = fmaxf(v1, 0.f); }
                    *(float2*)((float*)Cp + (size_t)rr * ldc + cl) = make_float2(v0, v1);
                }
            }
        }
    }
}

// ---------------- persistent-q online softmax stats ------------------------------
// Per CTA: (q-block m0, z). q tile resident in smem; loops 8 column tiles of k
// (double-buffered). Per tile: S = q@kt^T (same MMA order as attn_ctx), per-row
// tile max + sumexp (same reductions as before), combined ONLINE into (m, l).
// Emits rst[z*1024 + row] = (m, 1/l).
// smem words: q[0,4096) k[4096,12288) smf[12288,12800) mS[12800,12928) lS[12928,13056)
__global__ void __launch_bounds__(256, 2)
scores_stats(const __half* __restrict__ q, const __half* __restrict__ k,
             float2* __restrict__ rst)
{
    extern __shared__ __align__(16) uint32_t sm[];
    constexpr int QW = 0, KW = 4096;
    float* smf = (float*)(sm + 12288);
    float* mS  = (float*)(sm + 12800);
    float* lS  = (float*)(sm + 12928);

    const int tid = threadIdx.x, lane = tid & 31, warp = tid >> 5;
    const int wm = (warp & 3) * 32, wn = (warp >> 2) * 64;
    const int ft = lane & 3, frl = lane >> 2;
    const int g = warp >> 2, rl = lane >> 2;
    const int zz = blockIdx.y;           // h*4 + b
    const int b = zz & 3, hh = zz >> 2;
    const int m0 = blockIdx.x * 128;

    const __half* qbase = q + ((size_t)b * SEQ + m0) * D_MODEL + hh * 64;
    const __half* kbase = k + (size_t)b * SEQ * D_MODEL + hh * 64;

    const uint32_t smb = smem_u32(sm);
    auto swaddr = [](int r, int u) {
        return r * 32 + 4 * ((u + ((r & 1) << 2)) & 7);
    };

    auto load_q = [&]() {
        #pragma unroll
        for (int j = 0; j < 4; j++) {
            int gg = tid + 256 * j;
            int r = gg >> 3, u = gg & 7;
            cp_async16(smb + 4 * (QW + swaddr(r, u)), qbase + (size_t)r * D_MODEL + 8 * u);
        }
    };
    auto load_k = [&](int jt, int buf) {
        #pragma unroll
        for (int j = 0; j < 4; j++) {
            int gg = tid + 256 * j;
            int r = gg >> 3, u = gg & 7;
            cp_async16(smb + 4 * (KW + buf * 4096 + swaddr(r, u)),
                       kbase + (size_t)(jt * 128 + r) * D_MODEL + 8 * u);
        }
    };

    load_q(); load_k(0, 0); cp_commit();

    if (tid < 128) { mS[tid] = -1e30f; lS[tid] = 0.f; }

    for (int jt = 0; jt < 8; ++jt) {
        if (jt + 1 < 8) { load_k(jt + 1, (jt + 1) & 1); cp_commit(); cp_wait1(); }
        else            cp_wait0();
        __syncthreads();

        const int kwo = KW + (jt & 1) * 4096;
        float acc_s[2][8][4];
        #pragma unroll
        for (int i = 0; i < 2; i++)
            #pragma unroll
            for (int j = 0; j < 8; j++)
                #pragma unroll
                for (int c = 0; c < 4; c++) acc_s[i][j][c] = 0.f;

        #pragma unroll
        for (int kb = 0; kb < 2; kb++) {
            uint4 af[2][2];
            #pragma unroll
            for (int mt = 0; mt < 2; mt++)
                #pragma unroll
                for (int h = 0; h < 2; h++)
                    af[mt][h] = *(const uint4*)&sm[QW + swaddr(wm + mt * 16 + h * 8 + frl, 4 * kb + ft)];
            #pragma unroll
            for (int nt = 0; nt < 8; nt++) {
                uint4 bf = *(const uint4*)&sm[kwo + swaddr(wn + nt * 8 + frl, 4 * kb + ft)];
                #pragma unroll
                for (int mt = 0; mt < 2; mt++) {
                    mma_f16(acc_s[mt][nt], af[mt][0].x, af[mt][1].x, af[mt][0].y, af[mt][1].y,
                            bf.x, bf.y);
                    mma_f16(acc_s[mt][nt], af[mt][0].z, af[mt][1].z, af[mt][0].w, af[mt][1].w,
                            bf.z, bf.w);
                }
            }
        }

        // per-row tile max
        float lmax[2][2];
        #pragma unroll
        for (int mt = 0; mt < 2; mt++)
            #pragma unroll
            for (int h = 0; h < 2; h++) {
                float v = -1e30f;
                #pragma unroll
                for (int nt = 0; nt < 8; nt++) {
                    v = fmaxf(v, acc_s[mt][nt][2 * h]);
                    v = fmaxf(v, acc_s[mt][nt][2 * h + 1]);
                }
                lmax[mt][h] = v * 0.125f;
            }
        #pragma unroll
        for (int o = 1; o < 4; o <<= 1)
            #pragma unroll
            for (int mt = 0; mt < 2; mt++)
                #pragma unroll
                for (int h = 0; h < 2; h++)
                    lmax[mt][h] = fmaxf(lmax[mt][h], __shfl_xor_sync(0xffffffffu, lmax[mt][h], o));
        if ((lane & 3) == 0)
            #pragma unroll
            for (int mt = 0; mt < 2; mt++)
                #pragma unroll
                for (int h = 0; h < 2; h++)
                    smf[g * 128 + wm + mt * 16 + h * 8 + rl] = lmax[mt][h];
        __syncthreads();

        // per-row sumexp against tile max
        float rmax[2][2], lsum[2][2];
        #pragma unroll
        for (int mt = 0; mt < 2; mt++)
            #pragma unroll
            for (int h = 0; h < 2; h++) {
                int row = wm + mt * 16 + h * 8 + rl;
                rmax[mt][h] = fmaxf(smf[row], smf[128 + row]);
                lsum[mt][h] = 0.f;
            }
        #pragma unroll
        for (int mt = 0; mt < 2; ++mt)
            #pragma unroll
            for (int nt = 0; nt < 8; ++nt)
                #pragma unroll
                for (int h = 0; h < 2; ++h) {
                    lsum[mt][h] += __expf(acc_s[mt][nt][2 * h]     * 0.125f - rmax[mt][h]);
                    lsum[mt][h] += __expf(acc_s[mt][nt][2 * h + 1] * 0.125f - rmax[mt][h]);
                }
        #pragma unroll
        for (int o = 1; o < 4; o <<= 1)
            #pragma unroll
            for (int mt = 0; mt < 2; mt++)
                #pragma unroll
                for (int h = 0; h < 2; h++)
                    lsum[mt][h] += __shfl_xor_sync(0xffffffffu, lsum[mt][h], o);
        if ((lane & 3) == 0)
            #pragma unroll
            for (int mt = 0; mt < 2; mt++)
                #pragma unroll
                for (int h = 0; h < 2; h++)
                    smf[256 + g * 128 + wm + mt * 16 + h * 8 + rl] = lsum[mt][h];
        __syncthreads();

        // online combine into running (m, l)
        if (tid < 128) {
            float m_t = fmaxf(smf[tid], smf[128 + tid]);
            float l_t = smf[256 + tid] + smf[384 + tid];
            float m_old = mS[tid];
            float m_new = fmaxf(m_old, m_t);
            lS[tid] = lS[tid] * __expf(m_old - m_new) + l_t * __expf(m_t - m_new);
            mS[tid] = m_new;
        }
        __syncthreads();
    }

    if (tid < 128)
        rst[(size_t)zz * 1024 + m0 + tid] = make_float2(mS[tid], 1.0f / lS[tid]);
}

// ---------------- fused attention ctx (fp16 MMAs) ----------------------------------
// Per CTA: z, 128-row q block; 16 column tiles of 64 k-positions.
// S = q @ kt^T; p = __expf(s/8 - m)*invl (rst read directly); P -> gmem fp32 and
// smem fp16; ctx += P @ vt^T; epilogue o1 = ctx + x.
// smem words: q[0,4096) kt[4096,6144) vt[6144,8192) P[8192,12288) = 48KB
__global__ void __launch_bounds__(256, 2)
attn_ctx(const __half* __restrict__ q, const __half* __restrict__ k,
         const __half* __restrict__ vT, const float2* __restrict__ rst,
         float* __restrict__ attn, const float* __restrict__ x,
         float* __restrict__ o1)
{
    extern __shared__ __align__(16) uint32_t sm[];
    constexpr int QW = 0, KW = 4096, VW = 6144, PWo = 8192;
    constexpr int NJ = 16;

    const int tid = threadIdx.x, lane = tid & 31, warp = tid >> 5;
    const int wm = (warp & 3) * 32, wn = (warp >> 2) * 32;
    const int ft = lane & 3, frl = lane >> 2;
    const int zz = blockIdx.y;           // h*4 + b
    const int b = zz & 3, hh = zz >> 2;
    const int m0 = blockIdx.x * 128;

    const __half* qbase = q + ((size_t)b * SEQ + m0) * D_MODEL + hh * 64;
    const __half* kbase = k + (size_t)b * SEQ * D_MODEL + hh * 64;
    const __half* vbase = vT + (size_t)(b * N_HEADS + hh) * 64 * SEQ;
    float* pbase = attn + (size_t)zz * SEQ * SEQ + (size_t)m0 * SEQ;
    const float* xbase = x + ((size_t)b * SEQ + m0) * D_MODEL + hh * 64;
    float* obase = o1 + ((size_t)b * SEQ + m0) * D_MODEL + hh * 64;

    const uint32_t smb = smem_u32(sm);

    auto swaddr = [](int r, int u) {
        return r * 32 + 4 * ((u + ((r & 1) << 2)) & 7);
    };

    auto load_q = [&]() {
        #pragma unroll
        for (int j = 0; j < 4; j++) {
            int g = tid + 256 * j;
            int r = g >> 3, u = g & 7;
            cp_async16(smb + 4 * (QW + swaddr(r, u)), qbase + (size_t)r * D_MODEL + 8 * u);
        }
    };
    auto load_k = [&](int jt) {
        #pragma unroll
        for (int j = 0; j < 2; j++) {
            int g = tid + 256 * j;
            int r = g >> 3, u = g & 7;
            cp_async16(smb + 4 * (KW + swaddr(r, u)),
                       kbase + (size_t)(jt * 64 + r) * D_MODEL + 8 * u);
        }
    };
    auto load_v = [&](int jt) {
        #pragma unroll
        for (int j = 0; j < 2; j++) {
            int g = tid + 256 * j;
            int r = g >> 3, u = g & 7;
            cp_async16(smb + 4 * (VW + swaddr(r, u)),
                       vbase + (size_t)r * SEQ + jt * 64 + 8 * u);
        }
    };

    load_q(); load_k(0); cp_commit();     // group: {q, kt0}
    load_v(0); cp_commit();               // group: {vt0}

    float2 st[2][2];
    #pragma unroll
    for (int mt = 0; mt < 2; mt++)
        #pragma unroll
        for (int h = 0; h < 2; h++)
            st[mt][h] = rst[(size_t)zz * 1024 + m0 + wm + mt * 16 + h * 8 + frl];

    float acc_c[2][4][4];
    #pragma unroll
    for (int i = 0; i < 2; i++)
        #pragma unroll
        for (int j = 0; j < 4; j++)
            #pragma unroll
            for (int c = 0; c < 4; c++) acc_c[i][j][c] = 0.f;

    for (int jt = 0; jt < NJ; ++jt) {
        float acc_s[2][4][4];
        #pragma unroll
        for (int i = 0; i < 2; i++)
            #pragma unroll
            for (int j = 0; j < 4; j++)
                #pragma unroll
                for (int c = 0; c < 4; c++) acc_s[i][j][c] = 0.f;

        cp_wait1();          // q + kt ready
        __syncthreads();

        // S = q @ kt^T
        #pragma unroll
        for (int kb = 0; kb < 2; kb++) {
            uint4 af[2][2];
            #pragma unroll
            for (int mt = 0; mt < 2; mt++)
                #pragma unroll
                for (int h = 0; h < 2; h++)
                    af[mt][h] = *(const uint4*)&sm[QW + swaddr(wm + mt * 16 + h * 8 + frl, 4 * kb + ft)];
            #pragma unroll
            for (int nt = 0; nt < 4; nt++) {
                uint4 bf = *(const uint4*)&sm[KW + swaddr(wn + nt * 8 + frl, 4 * kb + ft)];
                #pragma unroll
                for (int mt = 0; mt < 2; mt++) {
                    mma_f16(acc_s[mt][nt], af[mt][0].x, af[mt][1].x, af[mt][0].y, af[mt][1].y,
                            bf.x, bf.y);
                    mma_f16(acc_s[mt][nt], af[mt][0].z, af[mt][1].z, af[mt][0].w, af[mt][1].w,
                            bf.z, bf.w);
                }
            }
        }

        // transform S -> P and stage P (fp16) into smem
        #pragma unroll
        for (int mt = 0; mt < 2; mt++) {
            #pragma unroll
            for (int h = 0; h < 2; h++) {
                int r = wm + mt * 16 + h * 8 + frl;
                int rot = (r & 1) << 2;
                float mrow = st[mt][h].x, invl = st[mt][h].y;
                #pragma unroll
                for (int nt = 0; nt < 4; nt++) {
                    float p0 = __expf(acc_s[mt][nt][h * 2 + 0] * 0.125f - mrow) * invl;
                    float p1 = __expf(acc_s[mt][nt][h * 2 + 1] * 0.125f - mrow) * invl;
                    acc_s[mt][nt][h * 2 + 0] = p0;
                    acc_s[mt][nt][h * 2 + 1] = p1;
                    int c = wn + nt * 8 + (lane & 3) * 2;
                    int blk = c >> 5, hu5 = (c & 31) >> 1;
                    int ul = 4 * blk + (hu5 & 3), sub = hu5 >> 2;
                    sm[PWo + r * 32 + 4 * ((ul + rot) & 7) + sub] = pack_h2(p0, p1);
                }
            }
        }

        cp_wait0();          // vt ready
        __syncthreads();     // P visible; kt consumed
        if (jt + 1 < NJ) load_k(jt + 1);
        cp_commit();

        // ctx += P @ vt^T
        #pragma unroll
        for (int kb = 0; kb < 2; kb++) {
            uint4 af[2][2];
            #pragma unroll
            for (int mt = 0; mt < 2; mt++)
                #pragma unroll
                for (int h = 0; h < 2; h++)
                    af[mt][h] = *(const uint4*)&sm[PWo + swaddr(wm + mt * 16 + h * 8 + frl, 4 * kb + ft)];
            #pragma unroll
            for (int nt = 0; nt < 4; nt++) {
                uint4 bf = *(const uint4*)&sm[VW + swaddr(wn + nt * 8 + frl, 4 * kb + ft)];
                #pragma unroll
                for (int mt = 0; mt < 2; mt++) {
                    mma_f16(acc_c[mt][nt], af[mt][0].x, af[mt][1].x, af[mt][0].y, af[mt][1].y,
                            bf.x, bf.y);
                    mma_f16(acc_c[mt][nt], af[mt][0].z, af[mt][1].z, af[mt][0].w, af[mt][1].w,
                            bf.z, bf.w);
                }
            }
        }

        // write final P (fp32) to gmem
        #pragma unroll
        for (int mt = 0; mt < 2; mt++)
            #pragma unroll
            for (int h = 0; h < 2; h++) {
                int r = wm + mt * 16 + h * 8 + frl;
                float* prow = pbase + (size_t)r * SEQ + jt * 64;
                #pragma unroll
                for (int nt = 0; nt < 4; nt++)
                    *(float2*)(prow + wn + nt * 8 + (lane & 3) * 2) =
                        make_float2(acc_s[mt][nt][h * 2], acc_s[mt][nt][h * 2 + 1]);
            }

        __syncthreads();     // vt and P consumed
        if (jt + 1 < NJ) load_v(jt + 1);
        cp_commit();
    }

    // epilogue: o1 = ctx + x
    #pragma unroll
    for (int mt = 0; mt < 2; mt++)
        #pragma unroll
        for (int h = 0; h < 2; h++) {
            int r = wm + mt * 16 + h * 8 + frl;
            #pragma unroll
            for (int nt = 0; nt < 4; nt++) {
                int c = wn + nt * 8 + (lane & 3) * 2;
                float2 xr = *(const float2*)(xbase + (size_t)r * D_MODEL + c);
                *(float2*)(obase + (size_t)r * D_MODEL + c) =
                    make_float2(acc_c[mt][nt][h * 2] + xr.x, acc_c[mt][nt][h * 2 + 1] + xr.y);
            }
        }
}

// ---------------- launch ----------------
extern "C" void kernel_launch(void* const* d_in, const int* in_sizes, int n_in,
                              void* d_out, int out_size) {
    const float* x     = (const float*)d_in[0];
    const float* ln1_g = (const float*)d_in[1];
    const float* ln1_b = (const float*)d_in[2];
    const float* wq    = (const float*)d_in[3];
    const float* bq    = (const float*)d_in[4];
    const float* wk    = (const float*)d_in[5];
    const float* bk    = (const float*)d_in[6];
    const float* wv    = (const float*)d_in[7];
    const float* bv    = (const float*)d_in[8];
    const float* ln2_g = (const float*)d_in[9];
    const float* ln2_b = (const float*)d_in[10];
    const float* w1    = (const float*)d_in[11];
    const float* b1    = (const float*)d_in[12];
    const float* w2    = (const float*)d_in[13];
    const float* b2    = (const float*)d_in[14];

    float* out  = (float*)d_out;
    float* attn = out + (size_t)BATCH * SEQ * D_MODEL;

    __half *h, *q, *k, *v, *vT, *h2, *ff, *wqkv, *w1r, *w2r;
    float *o1, *rst;
    cudaGetSymbolAddress((void**)&h,    g_h);
    cudaGetSymbolAddress((void**)&q,    g_q);
    cudaGetSymbolAddress((void**)&k,    g_k);
    cudaGetSymbolAddress((void**)&v,    g_v);
    cudaGetSymbolAddress((void**)&vT,   g_vT);
    cudaGetSymbolAddress((void**)&h2,   g_h2);
    cudaGetSymbolAddress((void**)&ff,   g_ff);
    cudaGetSymbolAddress((void**)&wqkv, g_wqkv);
    cudaGetSymbolAddress((void**)&w1r,  g_w1r);
    cudaGetSymbolAddress((void**)&w2r,  g_w2r);
    cudaGetSymbolAddress((void**)&o1,   g_o1);
    cudaGetSymbolAddress((void**)&rst,  g_rst);

    dim3 blk(256);
    const int SM_P4 = 4 * 4096 * 4;               // 65536 bytes
    const int SM_SS = 13056 * 4;                  // 52224 bytes
    const int SM_CTX = 12288 * 4;                 // 49152 bytes

    cudaFuncSetAttribute(gemm_f16<1>, cudaFuncAttributeMaxDynamicSharedMemorySize, SM_P4);
    cudaFuncSetAttribute(gemm_f16<0>, cudaFuncAttributeMaxDynamicSharedMemorySize, SM_P4);
    cudaFuncSetAttribute(scores_stats, cudaFuncAttributeMaxDynamicSharedMemorySize, SM_SS);
    cudaFuncSetAttribute(attn_ctx, cudaFuncAttributeMaxDynamicSharedMemorySize, SM_CTX);

    // 0) all weights -> fp16 permuted scratch (one launch)
    round_all<<<5632, 256>>>((const float4*)wq, (const float4*)wk, (const float4*)wv,
                             (const float4*)w1, (const float4*)w2,
                             (uint32_t*)wqkv, (uint32_t*)w1r, (uint32_t*)w2r);

    // 1) LN1 (fp16 permuted output)
    ln_kernel<<<M_TOK, 256>>>(x, ln1_g, ln1_b, (uint32_t*)h);

    // 2) fused QKV: q/k/v fp16 permuted (coalesced uint4 epilogue)
    gemm_f16<1><<<dim3(24, 32, 1), blk, SM_P4>>>(h, wqkv, (float*)q, bq, nullptr, k, v, bk, bv,
        M_TOK, 3 * D_MODEL, D_MODEL, D_MODEL, D_MODEL, D_MODEL, 1.f, 0);

    // 3) V transpose (fp16 permuted in/out)
    transpose_v<<<dim3(32, 2, BATCH * N_HEADS), dim3(32, 8)>>>(v, vT);

    // 4) persistent-q online softmax stats -> rst (m, 1/l)
    scores_stats<<<dim3(8, 64), blk, SM_SS>>>(q, k, (float2*)rst);

    // 5) fused ctx: recompute S, write P (fp32), ctx + x -> o1
    attn_ctx<<<dim3(8, 64), blk, SM_CTX>>>(q, k, vT, (const float2*)rst, attn, x, o1);

    // 6) LN2 (fp16 permuted output)
    ln_kernel<<<M_TOK, 256>>>(o1, ln2_g, ln2_b, (uint32_t*)h2);

    // 7) FFN1: relu(h2 @ w1^T + b1) -> fp16 permuted (coalesced epilogue)
    gemm_f16<1><<<dim3(32, 32, 1), blk, SM_P4>>>(h2, w1r, (float*)ff, b1, nullptr,
        nullptr, nullptr, nullptr, nullptr,
        M_TOK, D_FF, D_MODEL, D_MODEL, D_MODEL, D_FF, 1.f, 1);

    // 8) FFN2: ff @ w2^T + b2 + o1 -> final out (fp32)
    gemm_f16<0><<<dim3(8, 32, 1), blk, SM_P4>>>(ff, w2r, out, b2, o1,
        nullptr, nullptr, nullptr, nullptr,
        M_TOK, D_MODEL, D_FF, D_FF, D_FF, D_MODEL, 1.f, 0);
}

// round 17
// speedup vs baseline: 2.2102x; 1.0306x over previous
#include <cuda_runtime.h>
#include <cuda_fp16.h>
#include <cstdint>

#define D_MODEL 1024
#define N_HEADS 16
#define D_HEAD  64
#define D_FF    4096
#define BATCH   4
#define SEQ     1024
#define M_TOK   (BATCH*SEQ)   // 4096

// ---------------- scratch (allocation-free: device globals) ----------------
__device__ __half g_h   [M_TOK*D_MODEL];
__device__ __half g_q   [M_TOK*D_MODEL];
__device__ __half g_k   [M_TOK*D_MODEL];
__device__ __half g_v   [M_TOK*D_MODEL];
__device__ __half g_vT  [M_TOK*D_MODEL];
__device__ __half g_h2  [M_TOK*D_MODEL];
__device__ __half g_ff  [M_TOK*D_FF];
__device__ __half g_wqkv[3*D_MODEL*D_MODEL];
__device__ __half g_w1r [D_FF*D_MODEL];
__device__ __half g_w2r [D_MODEL*D_FF];
__device__ float  g_o1  [M_TOK*D_MODEL];
__device__ float  g_rst [64*1024*2];     // per-(z,row): (m, 1/l)

// ---------------- helpers ----------------
__device__ __forceinline__ uint32_t pack_h2(float a, float b) {
    __half2 h = __floats2half2_rn(a, b);
    return reinterpret_cast<uint32_t&>(h);
}

__device__ __forceinline__ uint32_t smem_u32(const void* p) {
    uint32_t a;
    asm("{ .reg .u64 t; cvta.to.shared.u64 t, %1; cvt.u32.u64 %0, t; }" : "=r"(a) : "l"(p));
    return a;
}

__device__ __forceinline__ void cp_async16(uint32_t saddr, const void* gptr) {
    asm volatile("cp.async.cg.shared.global [%0], [%1], 16;" :: "r"(saddr), "l"(gptr) : "memory");
}
__device__ __forceinline__ void cp_commit() {
    asm volatile("cp.async.commit_group;" ::: "memory");
}
__device__ __forceinline__ void cp_wait0() {
    asm volatile("cp.async.wait_group 0;" ::: "memory");
}
__device__ __forceinline__ void cp_wait1() {
    asm volatile("cp.async.wait_group 1;" ::: "memory");
}

__device__ __forceinline__ void mma_f16(float* c, uint32_t a0, uint32_t a1, uint32_t a2, uint32_t a3,
                                        uint32_t b0, uint32_t b1) {
    asm volatile(
        "mma.sync.aligned.m16n8k16.row.col.f32.f16.f16.f32 "
        "{%0,%1,%2,%3}, {%4,%5,%6,%7}, {%8,%9}, {%0,%1,%2,%3};\n"
        : "+f"(c[0]), "+f"(c[1]), "+f"(c[2]), "+f"(c[3])
        : "r"(a0), "r"(a1), "r"(a2), "r"(a3), "r"(b0), "r"(b1));
}

// physical half position of logical half k inside its 32-half block:
// hu = (k&31)>>1; pos_h2 = 4*(hu&3) + (hu>>2); pos = 2*pos_h2 + (k&1)
__device__ __forceinline__ int permh(int k) {
    int k5 = k & 31, hu = k5 >> 1;
    return (k & ~31) + 2 * (4 * (hu & 3) + (hu >> 2)) + (k5 & 1);
}

// ---------------- merged weight round+permute: 5 tensors in one launch ----------
__global__ void round_all(const float4* __restrict__ wq, const float4* __restrict__ wk,
                          const float4* __restrict__ wv, const float4* __restrict__ w1,
                          const float4* __restrict__ w2,
                          uint32_t* __restrict__ dqkv, uint32_t* __restrict__ dw1,
                          uint32_t* __restrict__ dw2) {
    int i = blockIdx.x * blockDim.x + threadIdx.x;
    const float4* src; uint32_t* dst; int idx;
    if (i < 131072)       { src = wq; dst = dqkv;           idx = i; }
    else if (i < 262144)  { src = wk; dst = dqkv + 524288;  idx = i - 131072; }
    else if (i < 393216)  { src = wv; dst = dqkv + 1048576; idx = i - 262144; }
    else if (i < 917504)  { src = w1; dst = dw1;            idx = i - 393216; }
    else                  { src = w2; dst = dw2;            idx = i - 917504; }
    float4 va = src[2 * idx], vb = src[2 * idx + 1];
    uint32_t* p = dst + (size_t)(idx >> 2) * 16 + (idx & 3);
    p[0]  = pack_h2(va.x, va.y);
    p[4]  = pack_h2(va.z, va.w);
    p[8]  = pack_h2(vb.x, vb.y);
    p[12] = pack_h2(vb.z, vb.w);
}

// ---------------- LayerNorm; fp16 + PERMUTED output ----------------------------
__global__ void ln_kernel(const float* __restrict__ x, const float* __restrict__ g,
                          const float* __restrict__ b, uint32_t* __restrict__ outh2) {
    int row = blockIdx.x;
    int t = threadIdx.x;  // 256 threads, 4 floats each
    const float4* xr = (const float4*)(x + (size_t)row * D_MODEL);
    float4 v = xr[t];
    __shared__ float red[8];

    float s = v.x + v.y + v.z + v.w;
    #pragma unroll
    for (int o = 16; o; o >>= 1) s += __shfl_xor_sync(0xffffffffu, s, o);
    if ((t & 31) == 0) red[t >> 5] = s;
    __syncthreads();
    float tot = red[0]+red[1]+red[2]+red[3]+red[4]+red[5]+red[6]+red[7];
    float mean = tot * (1.0f / D_MODEL);

    float dx = v.x - mean, dy = v.y - mean, dz = v.z - mean, dw = v.w - mean;
    float ss = dx*dx + dy*dy + dz*dz + dw*dw;
    #pragma unroll
    for (int o = 16; o; o >>= 1) ss += __shfl_xor_sync(0xffffffffu, ss, o);
    __syncthreads();
    if ((t & 31) == 0) red[t >> 5] = ss;
    __syncthreads();
    float vtot = red[0]+red[1]+red[2]+red[3]+red[4]+red[5]+red[6]+red[7];
    float inv = 1.0f / (sqrtf(vtot * (1.0f / (D_MODEL - 1))) + 1e-12f);

    float4 g4 = ((const float4*)g)[t];
    float4 b4 = ((const float4*)b)[t];
    float o0 = g4.x * dx * inv + b4.x;
    float o1v = g4.y * dy * inv + b4.y;
    float o2 = g4.z * dz * inv + b4.z;
    float o3 = g4.w * dw * inv + b4.w;

    int s5 = (t >> 1) & 3, blk = t >> 3, odd = t & 1;
    uint32_t* p = outh2 + (size_t)row * 512 + blk * 16 + 8 * odd + s5;
    p[0] = pack_h2(o0, o1v);
    p[4] = pack_h2(o2, o3);
}

// ---------------- V transpose: v (half, permuted) -> vT (half, permuted) -------
__global__ void transpose_v(const __half* __restrict__ v, __half* __restrict__ vT) {
    __shared__ __half tile[32][33];
    int bh = blockIdx.z;             // b*H + h
    int b = bh / N_HEADS, h = bh % N_HEADS;
    int s0 = blockIdx.x * 32;
    int d0 = blockIdx.y * 32;
    int tx = threadIdx.x, ty = threadIdx.y;  // 32 x 8
    const __half* src = v + ((size_t)b * SEQ) * D_MODEL;
    int pc = permh(h * D_HEAD + d0 + tx);
    #pragma unroll
    for (int i = 0; i < 32; i += 8)
        tile[ty + i][tx] = src[(size_t)(s0 + ty + i) * D_MODEL + pc];
    __syncthreads();
    __half* dst = vT + ((size_t)bh * D_HEAD) * SEQ;
    int ps = permh(s0 + tx);
    #pragma unroll
    for (int i = 0; i < 32; i += 8)
        dst[(size_t)(d0 + ty + i) * SEQ + ps] = tile[tx][ty + i];
}

// ---------------- fp16 mma.sync GEMM: BK=64 halves, 128B rotation-swizzled rows ----
// C = scale*(A[M,K] @ B[N,K]^T) (+bias)(+res)(relu).
// Row layout identical to attn_ctx: 32-word rows, unit slot = (u + 4*(r&1)) & 7.
// 3-stage cp.async ring (stage = 8192 words: A rows [0,4096), B rows [4096,8192)).
// PERM_OUT: C is __half (permuted layout), coalesced uint4 stores.
// QKV select when Ck != null. Warp grid 4x2, warp tile 32x64, CTA tile 128x128.
template<int PERM_OUT>
__global__ void __launch_bounds__(256, 2)
gemm_f16(const __half* __restrict__ A, const __half* __restrict__ B,
         float* __restrict__ C, const float* __restrict__ bias, const float* __restrict__ res,
         __half* __restrict__ Ck, __half* __restrict__ Cv,
         const float* __restrict__ biask, const float* __restrict__ biasv,
         int M, int N, int K, int lda, int ldb, int ldc,
         float scale, int relu)
{
    extern __shared__ __align__(16) uint32_t sm[];

    const int tid = threadIdx.x, lane = tid & 31, warp = tid >> 5;
    const int wm = (warp & 3) * 32, wn = (warp >> 2) * 64;
    const int m0 = blockIdx.y * 128, n0 = blockIdx.x * 128;

    const int ft = lane & 3, frl = lane >> 2;

    auto swaddr = [](int r, int u) {
        return r * 32 + 4 * ((u + ((r & 1) << 2)) & 7);
    };

    float acc[2][8][4];
    #pragma unroll
    for (int i = 0; i < 2; i++)
        #pragma unroll
        for (int j = 0; j < 8; j++)
            #pragma unroll
            for (int c = 0; c < 4; c++) acc[i][j][c] = 0.f;

    const int nk = K / 64;

    auto compute_at = [&](const uint32_t* base) {
        #pragma unroll
        for (int kb = 0; kb < 2; kb++) {
            uint4 af[2][2];
            #pragma unroll
            for (int mt = 0; mt < 2; mt++)
                #pragma unroll
                for (int h = 0; h < 2; h++)
                    af[mt][h] = *(const uint4*)&base[swaddr(wm + mt * 16 + h * 8 + frl, 4 * kb + ft)];
            #pragma unroll
            for (int nt = 0; nt < 8; nt++) {
                uint4 bf = *(const uint4*)&base[4096 + swaddr(wn + nt * 8 + frl, 4 * kb + ft)];
                #pragma unroll
                for (int mt = 0; mt < 2; mt++) {
                    mma_f16(acc[mt][nt], af[mt][0].x, af[mt][1].x, af[mt][0].y, af[mt][1].y,
                            bf.x, bf.y);
                    mma_f16(acc[mt][nt], af[mt][0].z, af[mt][1].z, af[mt][0].w, af[mt][1].w,
                            bf.z, bf.w);
                }
            }
        }
    };

    {
        const uint32_t smem_base = smem_u32(sm);
        uint32_t sw8[8];
        const __half* gp8[8];
        #pragma unroll
        for (int j = 0; j < 8; j++) {
            int id = tid + 256 * j;
            if (id < 1024) {            // A: 128 rows x 8 units
                int r = id >> 3, u = id & 7;
                sw8[j] = (uint32_t)(4 * swaddr(r, u));
                gp8[j] = A + (size_t)(m0 + r) * lda + 8 * u;
            } else {                    // B: 128 rows x 8 units
                int idb = id - 1024;
                int r = idb >> 3, u = idb & 7;
                sw8[j] = (uint32_t)(4 * (4096 + swaddr(r, u)));
                gp8[j] = B + (size_t)(n0 + r) * ldb + 8 * u;
            }
        }
        auto issue = [&](int tile, int stg) {
            const int k0 = tile * 64;
            const uint32_t sb = smem_base + (uint32_t)stg * 32768u;
            #pragma unroll
            for (int j = 0; j < 8; j++) cp_async16(sb + sw8[j], gp8[j] + k0);
            cp_commit();
        };
        issue(0, 0); issue(1, 1);
        int st = 0;
        for (int t = 0; t < nk; ++t) {
            cp_wait1();
            __syncthreads();
            compute_at(sm + st * 8192);
            if (t + 2 < nk) {
                int s2 = st + 2; if (s2 >= 3) s2 -= 3;
                issue(t + 2, s2);
            } else {
                cp_commit();
            }
            if (++st == 3) st = 0;
        }
        __syncthreads();
    }

    // ---- epilogue (QKV 3-way select) ----
    void* Cp = (void*)C; const float* bp = bias; int noff = 0;
    if (Ck) {
        if (n0 >= 2048)      { Cp = (void*)Cv; bp = biasv; noff = 2048; }
        else if (n0 >= 1024) { Cp = (void*)Ck; bp = biask; noff = 1024; }
    }
    if (PERM_OUT) {
        uint32_t* Ch2 = (uint32_t*)Cp;
        const int a = lane & 3;
        const int clb = n0 + wn - noff;            // multiple of 32
        #pragma unroll
        for (int mt = 0; mt < 2; ++mt) {
            #pragma unroll
            for (int h = 0; h < 2; ++h) {
                int rr = m0 + wm + mt * 16 + h * 8 + (lane >> 2);
                #pragma unroll
                for (int g = 0; g < 2; ++g) {
                    uint32_t w[4];
                    #pragma unroll
                    for (int j = 0; j < 4; ++j) {
                        int nt = 4 * g + j;
                        int cl = clb + nt * 8 + a * 2;
                        float v0 = acc[mt][nt][h * 2 + 0] * scale;
                        float v1 = acc[mt][nt][h * 2 + 1] * scale;
                        if (bp) { float2 bb = *(const float2*)(bp + cl); v0 += bb.x; v1 += bb.y; }
                        if (relu) { v0 = fmaxf(v0, 0.f); v1 = fmaxf(v1, 0.f); }
                        w[j] = pack_h2(v0, v1);
                    }
                    int p0 = ((clb >> 5) + g) * 16 + 4 * a;
                    uint4 u4 = make_uint4(w[0], w[1], w[2], w[3]);
                    *(uint4*)&Ch2[(size_t)rr * (ldc >> 1) + p0] = u4;
                }
            }
        }
    } else {
        #pragma unroll
        for (int mt = 0; mt < 2; ++mt) {
            #pragma unroll
            for (int nt = 0; nt < 8; ++nt) {
                int rbase = m0 + wm + mt * 16 + (lane >> 2);
                int cbase = n0 + wn + nt * 8 + (lane & 3) * 2;
                #pragma unroll
                for (int h = 0; h < 2; ++h) {
                    int rr = rbase + h * 8;
                    int cl = cbase;
                    float v0 = acc[mt][nt][h * 2 + 0] * scale;
                    float v1 = acc[mt][nt][h * 2 + 1] * scale;
                    if (bp)  { float2 bb = *(const float2*)(bp + cl); v0 += bb.x; v1 += bb.y; }
                    if (res) { float2 r2 = *(const float2*)(res + (size_t)rr * ldc + cl); v0 += r2.x; v1 += r2.y; }
                    if (relu) { v0 = fmaxf(v0, 0.f); v1 = fmaxf(v1, 0.f); }
                    *(float2*)((float*)Cp + (size_t)rr * ldc + cl) = make_float2(v0, v1);
                }
            }
        }
    }
}

// ---------------- persistent-q online softmax stats ------------------------------
// Per CTA: (q-block m0, z). q tile resident in smem; loops 8 column tiles of k
// (double-buffered). Per tile: S = q@kt^T, per-row tile max + sumexp, combined
// ONLINE into (m, l). Emits rst[z*1024 + row] = (m, 1/l).
// smem words: q[0,4096) k[4096,12288) smf[12288,12800) mS[12800,12928) lS[12928,13056)
__global__ void __launch_bounds__(256, 2)
scores_stats(const __half* __restrict__ q, const __half* __restrict__ k,
             float2* __restrict__ rst)
{
    extern __shared__ __align__(16) uint32_t sm[];
    constexpr int QW = 0, KW = 4096;
    float* smf = (float*)(sm + 12288);
    float* mS  = (float*)(sm + 12800);
    float* lS  = (float*)(sm + 12928);

    const int tid = threadIdx.x, lane = tid & 31, warp = tid >> 5;
    const int wm = (warp & 3) * 32, wn = (warp >> 2) * 64;
    const int ft = lane & 3, frl = lane >> 2;
    const int g = warp >> 2, rl = lane >> 2;
    const int zz = blockIdx.y;           // h*4 + b
    const int b = zz & 3, hh = zz >> 2;
    const int m0 = blockIdx.x * 128;

    const __half* qbase = q + ((size_t)b * SEQ + m0) * D_MODEL + hh * 64;
    const __half* kbase = k + (size_t)b * SEQ * D_MODEL + hh * 64;

    const uint32_t smb = smem_u32(sm);
    auto swaddr = [](int r, int u) {
        return r * 32 + 4 * ((u + ((r & 1) << 2)) & 7);
    };

    auto load_q = [&]() {
        #pragma unroll
        for (int j = 0; j < 4; j++) {
            int gg = tid + 256 * j;
            int r = gg >> 3, u = gg & 7;
            cp_async16(smb + 4 * (QW + swaddr(r, u)), qbase + (size_t)r * D_MODEL + 8 * u);
        }
    };
    auto load_k = [&](int jt, int buf) {
        #pragma unroll
        for (int j = 0; j < 4; j++) {
            int gg = tid + 256 * j;
            int r = gg >> 3, u = gg & 7;
            cp_async16(smb + 4 * (KW + buf * 4096 + swaddr(r, u)),
                       kbase + (size_t)(jt * 128 + r) * D_MODEL + 8 * u);
        }
    };

    load_q(); load_k(0, 0); cp_commit();

    if (tid < 128) { mS[tid] = -1e30f; lS[tid] = 0.f; }

    for (int jt = 0; jt < 8; ++jt) {
        if (jt + 1 < 8) { load_k(jt + 1, (jt + 1) & 1); cp_commit(); cp_wait1(); }
        else            cp_wait0();
        __syncthreads();

        const int kwo = KW + (jt & 1) * 4096;
        float acc_s[2][8][4];
        #pragma unroll
        for (int i = 0; i < 2; i++)
            #pragma unroll
            for (int j = 0; j < 8; j++)
                #pragma unroll
                for (int c = 0; c < 4; c++) acc_s[i][j][c] = 0.f;

        #pragma unroll
        for (int kb = 0; kb < 2; kb++) {
            uint4 af[2][2];
            #pragma unroll
            for (int mt = 0; mt < 2; mt++)
                #pragma unroll
                for (int h = 0; h < 2; h++)
                    af[mt][h] = *(const uint4*)&sm[QW + swaddr(wm + mt * 16 + h * 8 + frl, 4 * kb + ft)];
            #pragma unroll
            for (int nt = 0; nt < 8; nt++) {
                uint4 bf = *(const uint4*)&sm[kwo + swaddr(wn + nt * 8 + frl, 4 * kb + ft)];
                #pragma unroll
                for (int mt = 0; mt < 2; mt++) {
                    mma_f16(acc_s[mt][nt], af[mt][0].x, af[mt][1].x, af[mt][0].y, af[mt][1].y,
                            bf.x, bf.y);
                    mma_f16(acc_s[mt][nt], af[mt][0].z, af[mt][1].z, af[mt][0].w, af[mt][1].w,
                            bf.z, bf.w);
                }
            }
        }

        // per-row tile max
        float lmax[2][2];
        #pragma unroll
        for (int mt = 0; mt < 2; mt++)
            #pragma unroll
            for (int h = 0; h < 2; h++) {
                float v = -1e30f;
                #pragma unroll
                for (int nt = 0; nt < 8; nt++) {
                    v = fmaxf(v, acc_s[mt][nt][2 * h]);
                    v = fmaxf(v, acc_s[mt][nt][2 * h + 1]);
                }
                lmax[mt][h] = v * 0.125f;
            }
        #pragma unroll
        for (int o = 1; o < 4; o <<= 1)
            #pragma unroll
            for (int mt = 0; mt < 2; mt++)
                #pragma unroll
                for (int h = 0; h < 2; h++)
                    lmax[mt][h] = fmaxf(lmax[mt][h], __shfl_xor_sync(0xffffffffu, lmax[mt][h], o));
        if ((lane & 3) == 0)
            #pragma unroll
            for (int mt = 0; mt < 2; mt++)
                #pragma unroll
                for (int h = 0; h < 2; h++)
                    smf[g * 128 + wm + mt * 16 + h * 8 + rl] = lmax[mt][h];
        __syncthreads();

        // per-row sumexp against tile max
        float rmax[2][2], lsum[2][2];
        #pragma unroll
        for (int mt = 0; mt < 2; mt++)
            #pragma unroll
            for (int h = 0; h < 2; h++) {
                int row = wm + mt * 16 + h * 8 + rl;
                rmax[mt][h] = fmaxf(smf[row], smf[128 + row]);
                lsum[mt][h] = 0.f;
            }
        #pragma unroll
        for (int mt = 0; mt < 2; ++mt)
            #pragma unroll
            for (int nt = 0; nt < 8; ++nt)
                #pragma unroll
                for (int h = 0; h < 2; ++h) {
                    lsum[mt][h] += __expf(acc_s[mt][nt][2 * h]     * 0.125f - rmax[mt][h]);
                    lsum[mt][h] += __expf(acc_s[mt][nt][2 * h + 1] * 0.125f - rmax[mt][h]);
                }
        #pragma unroll
        for (int o = 1; o < 4; o <<= 1)
            #pragma unroll
            for (int mt = 0; mt < 2; mt++)
                #pragma unroll
                for (int h = 0; h < 2; h++)
                    lsum[mt][h] += __shfl_xor_sync(0xffffffffu, lsum[mt][h], o);
        if ((lane & 3) == 0)
            #pragma unroll
            for (int mt = 0; mt < 2; mt++)
                #pragma unroll
                for (int h = 0; h < 2; h++)
                    smf[256 + g * 128 + wm + mt * 16 + h * 8 + rl] = lsum[mt][h];
        __syncthreads();

        // online combine into running (m, l)
        if (tid < 128) {
            float m_t = fmaxf(smf[tid], smf[128 + tid]);
            float l_t = smf[256 + tid] + smf[384 + tid];
            float m_old = mS[tid];
            float m_new = fmaxf(m_old, m_t);
            lS[tid] = lS[tid] * __expf(m_old - m_new) + l_t * __expf(m_t - m_new);
            mS[tid] = m_new;
        }
        __syncthreads();
    }

    if (tid < 128)
        rst[(size_t)zz * 1024 + m0 + tid] = make_float2(mS[tid], 1.0f / lS[tid]);
}

// ---------------- fused attention ctx (fp16 MMAs) ----------------------------------
// Per CTA: z, 128-row q block; 16 column tiles of 64 k-positions.
// S = q @ kt^T; p = __expf(s/8 - m)*invl; P -> gmem fp32 and smem fp16;
// ctx += P @ vt^T; epilogue o1 = ctx + x.
// smem words: q[0,4096) kt[4096,6144) vt[6144,8192) P[8192,12288) = 48KB
__global__ void __launch_bounds__(256, 2)
attn_ctx(const __half* __restrict__ q, const __half* __restrict__ k,
         const __half* __restrict__ vT, const float2* __restrict__ rst,
         float* __restrict__ attn, const float* __restrict__ x,
         float* __restrict__ o1)
{
    extern __shared__ __align__(16) uint32_t sm[];
    constexpr int QW = 0, KW = 4096, VW = 6144, PWo = 8192;
    constexpr int NJ = 16;

    const int tid = threadIdx.x, lane = tid & 31, warp = tid >> 5;
    const int wm = (warp & 3) * 32, wn = (warp >> 2) * 32;
    const int ft = lane & 3, frl = lane >> 2;
    const int zz = blockIdx.y;           // h*4 + b
    const int b = zz & 3, hh = zz >> 2;
    const int m0 = blockIdx.x * 128;

    const __half* qbase = q + ((size_t)b * SEQ + m0) * D_MODEL + hh * 64;
    const __half* kbase = k + (size_t)b * SEQ * D_MODEL + hh * 64;
    const __half* vbase = vT + (size_t)(b * N_HEADS + hh) * 64 * SEQ;
    float* pbase = attn + (size_t)zz * SEQ * SEQ + (size_t)m0 * SEQ;
    const float* xbase = x + ((size_t)b * SEQ + m0) * D_MODEL + hh * 64;
    float* obase = o1 + ((size_t)b * SEQ + m0) * D_MODEL + hh * 64;

    const uint32_t smb = smem_u32(sm);

    auto swaddr = [](int r, int u) {
        return r * 32 + 4 * ((u + ((r & 1) << 2)) & 7);
    };

    auto load_q = [&]() {
        #pragma unroll
        for (int j = 0; j < 4; j++) {
            int g = tid + 256 * j;
            int r = g >> 3, u = g & 7;
            cp_async16(smb + 4 * (QW + swaddr(r, u)), qbase + (size_t)r * D_MODEL + 8 * u);
        }
    };
    auto load_k = [&](int jt) {
        #pragma unroll
        for (int j = 0; j < 2; j++) {
            int g = tid + 256 * j;
            int r = g >> 3, u = g & 7;
            cp_async16(smb + 4 * (KW + swaddr(r, u)),
                       kbase + (size_t)(jt * 64 + r) * D_MODEL + 8 * u);
        }
    };
    auto load_v = [&](int jt) {
        #pragma unroll
        for (int j = 0; j < 2; j++) {
            int g = tid + 256 * j;
            int r = g >> 3, u = g & 7;
            cp_async16(smb + 4 * (VW + swaddr(r, u)),
                       vbase + (size_t)r * SEQ + jt * 64 + 8 * u);
        }
    };

    load_q(); load_k(0); cp_commit();     // group: {q, kt0}
    load_v(0); cp_commit();               // group: {vt0}

    float2 st[2][2];
    #pragma unroll
    for (int mt = 0; mt < 2; mt++)
        #pragma unroll
        for (int h = 0; h < 2; h++)
            st[mt][h] = rst[(size_t)zz * 1024 + m0 + wm + mt * 16 + h * 8 + frl];

    float acc_c[2][4][4];
    #pragma unroll
    for (int i = 0; i < 2; i++)
        #pragma unroll
        for (int j = 0; j < 4; j++)
            #pragma unroll
            for (int c = 0; c < 4; c++) acc_c[i][j][c] = 0.f;

    for (int jt = 0; jt < NJ; ++jt) {
        float acc_s[2][4][4];
        #pragma unroll
        for (int i = 0; i < 2; i++)
            #pragma unroll
            for (int j = 0; j < 4; j++)
                #pragma unroll
                for (int c = 0; c < 4; c++) acc_s[i][j][c] = 0.f;

        cp_wait1();          // q + kt ready
        __syncthreads();

        // S = q @ kt^T
        #pragma unroll
        for (int kb = 0; kb < 2; kb++) {
            uint4 af[2][2];
            #pragma unroll
            for (int mt = 0; mt < 2; mt++)
                #pragma unroll
                for (int h = 0; h < 2; h++)
                    af[mt][h] = *(const uint4*)&sm[QW + swaddr(wm + mt * 16 + h * 8 + frl, 4 * kb + ft)];
            #pragma unroll
            for (int nt = 0; nt < 4; nt++) {
                uint4 bf = *(const uint4*)&sm[KW + swaddr(wn + nt * 8 + frl, 4 * kb + ft)];
                #pragma unroll
                for (int mt = 0; mt < 2; mt++) {
                    mma_f16(acc_s[mt][nt], af[mt][0].x, af[mt][1].x, af[mt][0].y, af[mt][1].y,
                            bf.x, bf.y);
                    mma_f16(acc_s[mt][nt], af[mt][0].z, af[mt][1].z, af[mt][0].w, af[mt][1].w,
                            bf.z, bf.w);
                }
            }
        }

        // transform S -> P and stage P (fp16) into smem
        #pragma unroll
        for (int mt = 0; mt < 2; mt++) {
            #pragma unroll
            for (int h = 0; h < 2; h++) {
                int r = wm + mt * 16 + h * 8 + frl;
                int rot = (r & 1) << 2;
                float mrow = st[mt][h].x, invl = st[mt][h].y;
                #pragma unroll
                for (int nt = 0; nt < 4; nt++) {
                    float p0 = __expf(acc_s[mt][nt][h * 2 + 0] * 0.125f - mrow) * invl;
                    float p1 = __expf(acc_s[mt][nt][h * 2 + 1] * 0.125f - mrow) * invl;
                    acc_s[mt][nt][h * 2 + 0] = p0;
                    acc_s[mt][nt][h * 2 + 1] = p1;
                    int c = wn + nt * 8 + (lane & 3) * 2;
                    int blk = c >> 5, hu5 = (c & 31) >> 1;
                    int ul = 4 * blk + (hu5 & 3), sub = hu5 >> 2;
                    sm[PWo + r * 32 + 4 * ((ul + rot) & 7) + sub] = pack_h2(p0, p1);
                }
            }
        }

        cp_wait0();          // vt ready
        __syncthreads();     // P visible; kt consumed
        if (jt + 1 < NJ) load_k(jt + 1);
        cp_commit();

        // ctx += P @ vt^T
        #pragma unroll
        for (int kb = 0; kb < 2; kb++) {
            uint4 af[2][2];
            #pragma unroll
            for (int mt = 0; mt < 2; mt++)
                #pragma unroll
                for (int h = 0; h < 2; h++)
                    af[mt][h] = *(const uint4*)&sm[PWo + swaddr(wm + mt * 16 + h * 8 + frl, 4 * kb + ft)];
            #pragma unroll
            for (int nt = 0; nt < 4; nt++) {
                uint4 bf = *(const uint4*)&sm[VW + swaddr(wn + nt * 8 + frl, 4 * kb + ft)];
                #pragma unroll
                for (int mt = 0; mt < 2; mt++) {
                    mma_f16(acc_c[mt][nt], af[mt][0].x, af[mt][1].x, af[mt][0].y, af[mt][1].y,
                            bf.x, bf.y);
                    mma_f16(acc_c[mt][nt], af[mt][0].z, af[mt][1].z, af[mt][0].w, af[mt][1].w,
                            bf.z, bf.w);
                }
            }
        }

        // write final P (fp32) to gmem
        #pragma unroll
        for (int mt = 0; mt < 2; mt++)
            #pragma unroll
            for (int h = 0; h < 2; h++) {
                int r = wm + mt * 16 + h * 8 + frl;
                float* prow = pbase + (size_t)r * SEQ + jt * 64;
                #pragma unroll
                for (int nt = 0; nt < 4; nt++)
                    *(float2*)(prow + wn + nt * 8 + (lane & 3) * 2) =
                        make_float2(acc_s[mt][nt][h * 2], acc_s[mt][nt][h * 2 + 1]);
            }

        __syncthreads();     // vt and P consumed
        if (jt + 1 < NJ) load_v(jt + 1);
        cp_commit();
    }

    // epilogue: o1 = ctx + x
    #pragma unroll
    for (int mt = 0; mt < 2; mt++)
        #pragma unroll
        for (int h = 0; h < 2; h++) {
            int r = wm + mt * 16 + h * 8 + frl;
            #pragma unroll
            for (int nt = 0; nt < 4; nt++) {
                int c = wn + nt * 8 + (lane & 3) * 2;
                float2 xr = *(const float2*)(xbase + (size_t)r * D_MODEL + c);
                *(float2*)(obase + (size_t)r * D_MODEL + c) =
                    make_float2(acc_c[mt][nt][h * 2] + xr.x, acc_c[mt][nt][h * 2 + 1] + xr.y);
            }
        }
}

// ---------------- launch ----------------
extern "C" void kernel_launch(void* const* d_in, const int* in_sizes, int n_in,
                              void* d_out, int out_size) {
    const float* x     = (const float*)d_in[0];
    const float* ln1_g = (const float*)d_in[1];
    const float* ln1_b = (const float*)d_in[2];
    const float* wq    = (const float*)d_in[3];
    const float* bq    = (const float*)d_in[4];
    const float* wk    = (const float*)d_in[5];
    const float* bk    = (const float*)d_in[6];
    const float* wv    = (const float*)d_in[7];
    const float* bv    = (const float*)d_in[8];
    const float* ln2_g = (const float*)d_in[9];
    const float* ln2_b = (const float*)d_in[10];
    const float* w1    = (const float*)d_in[11];
    const float* b1    = (const float*)d_in[12];
    const float* w2    = (const float*)d_in[13];
    const float* b2    = (const float*)d_in[14];

    float* out  = (float*)d_out;
    float* attn = out + (size_t)BATCH * SEQ * D_MODEL;

    __half *h, *q, *k, *v, *vT, *h2, *ff, *wqkv, *w1r, *w2r;
    float *o1, *rst;
    cudaGetSymbolAddress((void**)&h,    g_h);
    cudaGetSymbolAddress((void**)&q,    g_q);
    cudaGetSymbolAddress((void**)&k,    g_k);
    cudaGetSymbolAddress((void**)&v,    g_v);
    cudaGetSymbolAddress((void**)&vT,   g_vT);
    cudaGetSymbolAddress((void**)&h2,   g_h2);
    cudaGetSymbolAddress((void**)&ff,   g_ff);
    cudaGetSymbolAddress((void**)&wqkv, g_wqkv);
    cudaGetSymbolAddress((void**)&w1r,  g_w1r);
    cudaGetSymbolAddress((void**)&w2r,  g_w2r);
    cudaGetSymbolAddress((void**)&o1,   g_o1);
    cudaGetSymbolAddress((void**)&rst,  g_rst);

    dim3 blk(256);
    const int SM_P3 = 3 * 8192 * 4;               // 98304 bytes (BK=64, 3 stages)
    const int SM_SS = 13056 * 4;                  // 52224 bytes
    const int SM_CTX = 12288 * 4;                 // 49152 bytes

    cudaFuncSetAttribute(gemm_f16<1>, cudaFuncAttributeMaxDynamicSharedMemorySize, SM_P3);
    cudaFuncSetAttribute(gemm_f16<0>, cudaFuncAttributeMaxDynamicSharedMemorySize, SM_P3);
    cudaFuncSetAttribute(scores_stats, cudaFuncAttributeMaxDynamicSharedMemorySize, SM_SS);
    cudaFuncSetAttribute(attn_ctx, cudaFuncAttributeMaxDynamicSharedMemorySize, SM_CTX);

    // 0) all weights -> fp16 permuted scratch (one launch)
    round_all<<<5632, 256>>>((const float4*)wq, (const float4*)wk, (const float4*)wv,
                             (const float4*)w1, (const float4*)w2,
                             (uint32_t*)wqkv, (uint32_t*)w1r, (uint32_t*)w2r);

    // 1) LN1 (fp16 permuted output)
    ln_kernel<<<M_TOK, 256>>>(x, ln1_g, ln1_b, (uint32_t*)h);

    // 2) fused QKV: q/k/v fp16 permuted (coalesced uint4 epilogue)
    gemm_f16<1><<<dim3(24, 32, 1), blk, SM_P3>>>(h, wqkv, (float*)q, bq, nullptr, k, v, bk, bv,
        M_TOK, 3 * D_MODEL, D_MODEL, D_MODEL, D_MODEL, D_MODEL, 1.f, 0);

    // 3) V transpose (fp16 permuted in/out)
    transpose_v<<<dim3(32, 2, BATCH * N_HEADS), dim3(32, 8)>>>(v, vT);

    // 4) persistent-q online softmax stats -> rst (m, 1/l)
    scores_stats<<<dim3(8, 64), blk, SM_SS>>>(q, k, (float2*)rst);

    // 5) fused ctx: recompute S, write P (fp32), ctx + x -> o1
    attn_ctx<<<dim3(8, 64), blk, SM_CTX>>>(q, k, vT, (const float2*)rst, attn, x, o1);

    // 6) LN2 (fp16 permuted output)
    ln_kernel<<<M_TOK, 256>>>(o1, ln2_g, ln2_b, (uint32_t*)h2);

    // 7) FFN1: relu(h2 @ w1^T + b1) -> fp16 permuted (coalesced epilogue)
    gemm_f16<1><<<dim3(32, 32, 1), blk, SM_P3>>>(h2, w1r, (float*)ff, b1, nullptr,
        nullptr, nullptr, nullptr, nullptr,
        M_TOK, D_FF, D_MODEL, D_MODEL, D_MODEL, D_FF, 1.f, 1);

    // 8) FFN2: ff @ w2^T + b2 + o1 -> final out (fp32)
    gemm_f16<0><<<dim3(8, 32, 1), blk, SM_P3>>>(ff, w2r, out, b2, o1,
        nullptr, nullptr, nullptr, nullptr,
        M_TOK, D_MODEL, D_FF, D_FF, D_FF, D_MODEL, 1.f, 0);
}